// round 12
// baseline (speedup 1.0000x reference)
#include <cuda_runtime.h>
#include <cstdint>

#define BZ 64
#define LZ 1024
#define DZ 64
#define C7 7
#define HZ 8
#define EZ 8
#define MZ 64
#define M2 128
#define DFFD 256
#define NROW (BZ*LZ)
#define NHE  (BZ*DZ)

__device__ float g_x[BZ*LZ*C7];
__device__ float g_seas0[BZ*LZ*C7];
__device__ float g_trend0[BZ*LZ*C7];
__device__ float g_mean7[BZ*C7];
__device__ float g_trendbase[BZ*LZ];
__device__ float g_seasinit[BZ*LZ*C7];
__device__ float g_h[NROW*DZ];
__device__ float g_y[NROW*DZ];
__device__ float g_a[NROW*DZ];
__device__ float g_a2[NROW*DZ];
__device__ float g_Hf[2*NHE*M2];
__device__ float g_Xf[NHE*M2];
__device__ float g_Xk[NHE*M2];
__device__ float g_sel[NHE*M2];
__device__ float g_sel2[NHE*M2];
__device__ float g_xd[NROW*DZ];
__device__ float g_tacc[NROW*DZ];
__device__ float g_cm[BZ*DZ];
__device__ float g_cm2[BZ*DZ];
__device__ float g_ln[NROW*DZ];
__device__ float g_F[M2*LZ];
__device__ float g_Fi[LZ*M2];
__device__ float g_pe[LZ*DZ];

// ------------------------------------------------------------------ tables
__global__ void build_tables_kernel() {
    int idx = blockIdx.x * blockDim.x + threadIdx.x;
    if (idx < LZ * M2) {
        int t = idx >> 7;
        int m2 = idx & 127;
        int m = m2 >> 1;
        int r = (m * t) & (LZ - 1);
        float a = (float)r * (6.28318530717958647692f / (float)LZ);
        float s, c;
        sincosf(a, &s, &c);
        float v = (m2 & 1) ? -s : c;
        g_F[(size_t)m2 * LZ + t] = v;
        float cm = (m == 0) ? 1.f : 2.f;
        g_Fi[(size_t)t * M2 + m2] = v * (cm / (float)LZ);
    }
    if (idx < LZ * DZ) {
        int o = idx & 63;
        int t = idx >> 6;
        int i2 = o & ~1;
        float div = expf(-(float)i2 * 0.14391156831212793f);
        float arg = (float)t * div;
        g_pe[idx] = (o & 1) ? cosf(arg) : sinf(arg);
    }
}

// ------------------------------------------------------------------ input prep
__global__ void transpose_in_kernel(const float* __restrict__ xe) {
    int idx = blockIdx.x * blockDim.x + threadIdx.x;
    if (idx >= BZ * C7 * LZ) return;
    int t = idx & 1023;
    int c = (idx >> 10) % C7;
    int b = idx / (C7 * LZ);
    g_x[((size_t)(b * LZ + t)) * C7 + c] = xe[idx];
}

__global__ void colmean7_kernel(const float* __restrict__ xe) {
    __shared__ float r[256];
    int bc = blockIdx.x;
    float s = 0.f;
    for (int t = threadIdx.x; t < LZ; t += 256) s += xe[(size_t)bc * LZ + t];
    r[threadIdx.x] = s;
    __syncthreads();
    for (int o = 128; o > 0; o >>= 1) {
        if (threadIdx.x < o) r[threadIdx.x] += r[threadIdx.x + o];
        __syncthreads();
    }
    if (threadIdx.x == 0) g_mean7[bc] = r[0] * (1.f / LZ);
}

// ------------------------------------------------------------------ decomp7
__global__ void decomp7_kernel(const float* __restrict__ A,
                               const float* __restrict__ w4, const float* __restrict__ b4,
                               float* __restrict__ seas, float* __restrict__ trend) {
    __shared__ float ps[LZ];
    __shared__ float wsum[32];
    __shared__ float sx0, sxN;
    int c = blockIdx.x % C7, b = blockIdx.x / C7;
    int t = threadIdx.x, lane = t & 31, wid = t >> 5;
    size_t idx = ((size_t)(b * LZ + t)) * C7 + c;
    float x = A[idx];
    float s = x;
#pragma unroll
    for (int off = 1; off < 32; off <<= 1) {
        float v = __shfl_up_sync(0xffffffffu, s, off);
        if (lane >= off) s += v;
    }
    if (lane == 31) wsum[wid] = s;
    if (t == 0) sx0 = x;
    if (t == LZ - 1) sxN = x;
    __syncthreads();
    if (wid == 0) {
        float v = wsum[lane];
#pragma unroll
        for (int off = 1; off < 32; off <<= 1) {
            float u = __shfl_up_sync(0xffffffffu, v, off);
            if (lane >= off) v += u;
        }
        wsum[lane] = v;
    }
    __syncthreads();
    if (wid > 0) s += wsum[wid - 1];
    ps[t] = s;
    __syncthreads();
    float x0 = sx0, xN = sxN;
    const int ks[4] = {10, 50, 100, 500};
    float ma[4];
#pragma unroll
    for (int kk = 0; kk < 4; kk++) {
        int k = ks[kk], f = (k - 1) >> 1, e = k >> 1;
        int lo = t - f, hi = t + e;
        int cl = lo < 0 ? 0 : lo, ch = hi > LZ - 1 ? LZ - 1 : hi;
        float sw = ps[ch] - (cl > 0 ? ps[cl - 1] : 0.f)
                 + (float)(cl - lo) * x0 + (float)(hi - ch) * xN;
        ma[kk] = sw / (float)k;
    }
    float z[4], mx = -1e30f;
#pragma unroll
    for (int kk = 0; kk < 4; kk++) { z[kk] = x * w4[kk] + b4[kk]; mx = fmaxf(mx, z[kk]); }
    float se = 0.f, mean = 0.f;
#pragma unroll
    for (int kk = 0; kk < 4; kk++) { float e2 = expf(z[kk] - mx); se += e2; mean += ma[kk] * e2; }
    mean /= se;
    seas[idx] = x - mean;
    trend[idx] = mean;
}

__device__ __forceinline__ float4 f4add(float4 a, float4 b) {
    return make_float4(a.x + b.x, a.y + b.y, a.z + b.z, a.w + b.w);
}

// ------------------------------------------------------------------ decomp64
__global__ __launch_bounds__(256) void decomp64_kernel(
    const float* __restrict__ A, const float* __restrict__ Bb,
    const float* __restrict__ w4, const float* __restrict__ b4,
    float* __restrict__ seas, float* __restrict__ trend, int accum) {
    __shared__ float4 ps[LZ];
    __shared__ float4 wsum[8];
    __shared__ float4 sedge[2];
    int c4 = blockIdx.x & 15, b = blockIdx.x >> 4;
    int tid = threadIdx.x, lane = tid & 31, wid = tid >> 5;
    int t4 = tid * 4;
    size_t base = ((size_t)(b * LZ + t4)) * DZ + c4 * 4;

    float4 x[4], p[4];
#pragma unroll
    for (int j = 0; j < 4; j++) {
        x[j] = *reinterpret_cast<const float4*>(A + base + (size_t)j * DZ);
        if (Bb) x[j] = f4add(x[j], *reinterpret_cast<const float4*>(Bb + base + (size_t)j * DZ));
    }
    p[0] = x[0];
#pragma unroll
    for (int j = 1; j < 4; j++) p[j] = f4add(p[j - 1], x[j]);

    float4 s = p[3];
#pragma unroll
    for (int off = 1; off < 32; off <<= 1) {
        float4 v;
        v.x = __shfl_up_sync(0xffffffffu, s.x, off);
        v.y = __shfl_up_sync(0xffffffffu, s.y, off);
        v.z = __shfl_up_sync(0xffffffffu, s.z, off);
        v.w = __shfl_up_sync(0xffffffffu, s.w, off);
        if (lane >= off) s = f4add(s, v);
    }
    if (lane == 31) wsum[wid] = s;
    if (tid == 0) sedge[0] = x[0];
    if (tid == 255) sedge[1] = x[3];
    __syncthreads();
    if (wid == 0 && lane < 8) {
        float4 v = wsum[lane];
#pragma unroll
        for (int off = 1; off < 8; off <<= 1) {
            float4 u;
            u.x = __shfl_up_sync(0xffu, v.x, off);
            u.y = __shfl_up_sync(0xffu, v.y, off);
            u.z = __shfl_up_sync(0xffu, v.z, off);
            u.w = __shfl_up_sync(0xffu, v.w, off);
            if (lane >= off) v = f4add(v, u);
        }
        wsum[lane] = v;
    }
    __syncthreads();
    float4 ex = make_float4(0.f, 0.f, 0.f, 0.f);
    if (wid > 0) ex = wsum[wid - 1];
    {
        float4 d;
        d.x = s.x - p[3].x; d.y = s.y - p[3].y; d.z = s.z - p[3].z; d.w = s.w - p[3].w;
        ex = f4add(ex, d);
    }
#pragma unroll
    for (int j = 0; j < 4; j++) ps[t4 + j] = f4add(ex, p[j]);
    __syncthreads();

    float4 x0 = sedge[0], xN = sedge[1];
    const int ks[4] = {10, 50, 100, 500};
#pragma unroll
    for (int j = 0; j < 4; j++) {
        int t = t4 + j;
        float ma[4][4];
#pragma unroll
        for (int kk = 0; kk < 4; kk++) {
            int k = ks[kk], f = (k - 1) >> 1, e = k >> 1;
            int lo = t - f, hi = t + e;
            int cl = lo < 0 ? 0 : lo, ch = hi > LZ - 1 ? LZ - 1 : hi;
            float4 pc = ps[ch];
            float4 pl = make_float4(0.f, 0.f, 0.f, 0.f);
            if (cl > 0) pl = ps[cl - 1];
            float fl = (float)(cl - lo), fr = (float)(hi - ch);
            float inv = 1.f / (float)k;
            ma[kk][0] = (pc.x - pl.x + fl * x0.x + fr * xN.x) * inv;
            ma[kk][1] = (pc.y - pl.y + fl * x0.y + fr * xN.y) * inv;
            ma[kk][2] = (pc.z - pl.z + fl * x0.z + fr * xN.z) * inv;
            ma[kk][3] = (pc.w - pl.w + fl * x0.w + fr * xN.w) * inv;
        }
        float xa[4] = {x[j].x, x[j].y, x[j].z, x[j].w};
        float so[4], tr[4];
#pragma unroll
        for (int cc = 0; cc < 4; cc++) {
            float z[4], mx = -1e30f;
#pragma unroll
            for (int kk = 0; kk < 4; kk++) { z[kk] = xa[cc] * w4[kk] + b4[kk]; mx = fmaxf(mx, z[kk]); }
            float se = 0.f, mean = 0.f;
#pragma unroll
            for (int kk = 0; kk < 4; kk++) { float e2 = expf(z[kk] - mx); se += e2; mean += ma[kk][cc] * e2; }
            mean /= se;
            so[cc] = xa[cc] - mean;
            tr[cc] = mean;
        }
        *reinterpret_cast<float4*>(seas + base + (size_t)j * DZ) =
            make_float4(so[0], so[1], so[2], so[3]);
        if (trend) {
            float4 tv = make_float4(tr[0], tr[1], tr[2], tr[3]);
            if (accum) {
                float4 old = *reinterpret_cast<float4*>(trend + base + (size_t)j * DZ);
                tv = f4add(tv, old);
            }
            *reinterpret_cast<float4*>(trend + base + (size_t)j * DZ) = tv;
        }
    }
}

// ------------------------------------------------------------------ trend/seasonal init
__global__ void trendbase_kernel(const float* __restrict__ dpw, const float* __restrict__ dpb) {
    int idx = blockIdx.x * blockDim.x + threadIdx.x;
    if (idx >= BZ * LZ) return;
    int t = idx & 1023, b = idx >> 10;
    float s = dpb[0];
#pragma unroll
    for (int c = 0; c < C7; c++) {
        float v = (t < 512) ? g_trend0[((size_t)(b * LZ + 512 + t)) * C7 + c]
                            : g_mean7[b * C7 + c];
        s += v * dpw[c];
    }
    g_trendbase[idx] = s;
}

__global__ void seasinit_kernel() {
    int idx = blockIdx.x * blockDim.x + threadIdx.x;
    if (idx >= BZ * LZ * C7) return;
    int c = idx % C7;
    int t = (idx / C7) & 1023;
    int b = idx / (C7 * LZ);
    g_seasinit[idx] = (t < 512) ? g_seas0[((size_t)(b * LZ + 512 + t)) * C7 + c] : 0.f;
}

// ------------------------------------------------------------------ embedding
__global__ void embed_kernel(const float* __restrict__ in, const float* __restrict__ w,
                             float* __restrict__ out) {
    int idx = blockIdx.x * blockDim.x + threadIdx.x;
    if (idx >= BZ * LZ * DZ) return;
    int o = idx & 63;
    int t = (idx >> 6) & 1023;
    int b = idx >> 16;
    float s = 0.f;
#pragma unroll
    for (int j = 0; j < 3; j++) {
        int ts = (t + j - 1 + LZ) & (LZ - 1);
        const float* ip = in + ((size_t)(b * LZ + ts)) * C7;
#pragma unroll
        for (int c = 0; c < C7; c++) s += ip[c] * w[(o * C7 + c) * 3 + j];
    }
    out[idx] = s + g_pe[(t << 6) + o];
}

// ------------------------------------------------------------------ tf32 helpers
__device__ __forceinline__ uint32_t to_tf32(float x) {
    uint32_t r;
    asm("cvt.rna.tf32.f32 %0, %1;" : "=r"(r) : "f"(x));
    return r;
}
__device__ __forceinline__ void cpa16(uint32_t s, const float* g) {
    asm volatile("cp.async.ca.shared.global [%0], [%1], 16;" :: "r"(s), "l"(g));
}
__device__ __forceinline__ void cpa_commit() {
    asm volatile("cp.async.commit_group;");
}
__device__ __forceinline__ void cpa_wait1() {
    asm volatile("cp.async.wait_group 1;");
}
__device__ __forceinline__ void mma_tf32(float* acc, const uint32_t* a, const uint32_t* bf) {
    asm volatile(
        "mma.sync.aligned.m16n8k8.row.col.f32.tf32.tf32.f32 "
        "{%0,%1,%2,%3}, {%4,%5,%6,%7}, {%8,%9}, {%0,%1,%2,%3};"
        : "+f"(acc[0]), "+f"(acc[1]), "+f"(acc[2]), "+f"(acc[3])
        : "r"(a[0]), "r"(a[1]), "r"(a[2]), "r"(a[3]), "r"(bf[0]), "r"(bf[1]));
}

// ------------------------------------------------------------------ tf32 GEMM
#define GT_ASTRIDE (128*36)
#define GT_BSTRIDE (64*36)
#define GT_SMEM ((2*GT_ASTRIDE + 2*GT_BSTRIDE) * 4)

template <int ACT>
__global__ __launch_bounds__(128) void gemm_tc(const float* __restrict__ A,
                                               const float* __restrict__ W,
                                               const float* __restrict__ bias,
                                               float* __restrict__ C,
                                               int N, int K, int O) {
    extern __shared__ float dsm[];
    float* As = dsm;
    float* Bs = dsm + 2 * GT_ASTRIDE;
    const int rb = blockIdx.x * 128;
    const int cb = blockIdx.y * 64;
    const int tid = threadIdx.x;
    const int lane = tid & 31;
    const int w = tid >> 5;
    const int wm = w & 1, wn = w >> 1;
    const int m0 = wm * 64, n0 = wn * 32;
    const int g = lane >> 2, tg = lane & 3;
    const int lrow = tid >> 3;
    const int lcol = (tid & 7) * 4;

    uint32_t sA = (uint32_t)__cvta_generic_to_shared(As);
    uint32_t sB = (uint32_t)__cvta_generic_to_shared(Bs);

    float acc[4][4][4];
#pragma unroll
    for (int mi = 0; mi < 4; mi++)
#pragma unroll
        for (int ni = 0; ni < 4; ni++)
#pragma unroll
            for (int r = 0; r < 4; r++) acc[mi][ni][r] = 0.f;

#pragma unroll
    for (int r = 0; r < 8; r++) {
        int row = lrow + r * 16;
        cpa16(sA + (uint32_t)((row * 36 + lcol) * 4), A + (size_t)(rb + row) * K + lcol);
    }
#pragma unroll
    for (int r = 0; r < 4; r++) {
        int row = lrow + r * 16;
        cpa16(sB + (uint32_t)((row * 36 + lcol) * 4), W + (size_t)(cb + row) * K + lcol);
    }
    cpa_commit();

    int st = 0;
    for (int k0 = 0; k0 < K; k0 += 32, st ^= 1) {
        if (k0 + 32 < K) {
            int nx = st ^ 1;
#pragma unroll
            for (int r = 0; r < 8; r++) {
                int row = lrow + r * 16;
                cpa16(sA + (uint32_t)((nx * GT_ASTRIDE + row * 36 + lcol) * 4),
                      A + (size_t)(rb + row) * K + k0 + 32 + lcol);
            }
#pragma unroll
            for (int r = 0; r < 4; r++) {
                int row = lrow + r * 16;
                cpa16(sB + (uint32_t)((nx * GT_BSTRIDE + row * 36 + lcol) * 4),
                      W + (size_t)(cb + row) * K + k0 + 32 + lcol);
            }
        }
        cpa_commit();
        cpa_wait1();
        __syncthreads();
        const float* Ast = As + st * GT_ASTRIDE;
        const float* Bst = Bs + st * GT_BSTRIDE;
#pragma unroll
        for (int kk = 0; kk < 32; kk += 8) {
            uint32_t a[4][4], bfr[4][2];
#pragma unroll
            for (int mi = 0; mi < 4; mi++) {
                int r = m0 + mi * 16 + g;
                a[mi][0] = to_tf32(Ast[r * 36 + kk + tg]);
                a[mi][1] = to_tf32(Ast[(r + 8) * 36 + kk + tg]);
                a[mi][2] = to_tf32(Ast[r * 36 + kk + tg + 4]);
                a[mi][3] = to_tf32(Ast[(r + 8) * 36 + kk + tg + 4]);
            }
#pragma unroll
            for (int ni = 0; ni < 4; ni++) {
                int c = n0 + ni * 8 + g;
                bfr[ni][0] = to_tf32(Bst[c * 36 + kk + tg]);
                bfr[ni][1] = to_tf32(Bst[c * 36 + kk + tg + 4]);
            }
#pragma unroll
            for (int mi = 0; mi < 4; mi++)
#pragma unroll
                for (int ni = 0; ni < 4; ni++)
                    mma_tf32(acc[mi][ni], a[mi], bfr[ni]);
        }
        __syncthreads();
    }
#pragma unroll
    for (int mi = 0; mi < 4; mi++) {
        int row0 = rb + m0 + mi * 16 + g;
#pragma unroll
        for (int ni = 0; ni < 4; ni++) {
            int col = cb + n0 + ni * 8 + 2 * tg;
#pragma unroll
            for (int half = 0; half < 2; half++) {
                int row = row0 + half * 8;
                float v0 = acc[mi][ni][half * 2 + 0];
                float v1 = acc[mi][ni][half * 2 + 1];
                if (bias) { v0 += bias[col]; v1 += bias[col + 1]; }
                if (ACT == 1) {
                    v0 = 0.5f * v0 * (1.f + erff(v0 * 0.70710678118654752f));
                    v1 = 0.5f * v1 * (1.f + erff(v1 * 0.70710678118654752f));
                }
                C[(size_t)row * O + col] = v0;
                C[(size_t)row * O + col + 1] = v1;
            }
        }
    }
}

// ------------------------------------------------------------------ fused FFN
#define FFN_AS  (128*68)
#define FFN_WS  (64*68)
#define FFN_PS  (128*68)
#define FFN_SMEM ((FFN_AS + 2*FFN_WS + FFN_PS) * 4)

__global__ __launch_bounds__(128) void gemm_ffn(const float* __restrict__ A,
                                                const float* __restrict__ W1,
                                                const float* __restrict__ W2,
                                                float* __restrict__ C) {
    extern __shared__ float sm[];
    float* As  = sm;
    float* Ws1 = sm + FFN_AS;
    float* Ws2 = sm + FFN_AS + FFN_WS;
    float* Ps  = sm + FFN_AS + 2 * FFN_WS;
    const int rb = blockIdx.x * 128;
    const int tid = threadIdx.x;
    const int lane = tid & 31;
    const int w = tid >> 5;
    const int wm = w & 1, wn = w >> 1;
    const int m0 = wm * 64, n0 = wn * 32;
    const int g = lane >> 2, tg = lane & 3;

    for (int i = tid; i < 128 * 16; i += 128) {
        int row = i >> 4;
        int c4 = (i & 15) * 4;
        *reinterpret_cast<float4*>(&As[row * 68 + c4]) =
            *reinterpret_cast<const float4*>(A + (size_t)(rb + row) * 64 + c4);
    }

    float acc[4][4][4];
#pragma unroll
    for (int mi = 0; mi < 4; mi++)
#pragma unroll
        for (int ni = 0; ni < 4; ni++)
#pragma unroll
            for (int r = 0; r < 4; r++) acc[mi][ni][r] = 0.f;

    for (int ch = 0; ch < 4; ch++) {
        __syncthreads();
        for (int i = tid; i < 64 * 16; i += 128) {
            int row = i >> 4;
            int c4 = (i & 15) * 4;
            *reinterpret_cast<float4*>(&Ws1[row * 68 + c4]) =
                *reinterpret_cast<const float4*>(W1 + (size_t)(ch * 64 + row) * 64 + c4);
            *reinterpret_cast<float4*>(&Ws2[row * 68 + c4]) =
                *reinterpret_cast<const float4*>(W2 + (size_t)row * 256 + ch * 64 + c4);
        }
        __syncthreads();
        float p1[4][4][4];
#pragma unroll
        for (int mi = 0; mi < 4; mi++)
#pragma unroll
            for (int ni = 0; ni < 4; ni++)
#pragma unroll
                for (int r = 0; r < 4; r++) p1[mi][ni][r] = 0.f;
#pragma unroll
        for (int kk = 0; kk < 64; kk += 8) {
            uint32_t a[4][4], bfr[4][2];
#pragma unroll
            for (int mi = 0; mi < 4; mi++) {
                int r = m0 + mi * 16 + g;
                a[mi][0] = to_tf32(As[r * 68 + kk + tg]);
                a[mi][1] = to_tf32(As[(r + 8) * 68 + kk + tg]);
                a[mi][2] = to_tf32(As[r * 68 + kk + tg + 4]);
                a[mi][3] = to_tf32(As[(r + 8) * 68 + kk + tg + 4]);
            }
#pragma unroll
            for (int ni = 0; ni < 4; ni++) {
                int c = n0 + ni * 8 + g;
                bfr[ni][0] = to_tf32(Ws1[c * 68 + kk + tg]);
                bfr[ni][1] = to_tf32(Ws1[c * 68 + kk + tg + 4]);
            }
#pragma unroll
            for (int mi = 0; mi < 4; mi++)
#pragma unroll
                for (int ni = 0; ni < 4; ni++)
                    mma_tf32(p1[mi][ni], a[mi], bfr[ni]);
        }
#pragma unroll
        for (int mi = 0; mi < 4; mi++) {
            int row0 = m0 + mi * 16 + g;
#pragma unroll
            for (int ni = 0; ni < 4; ni++) {
                int col = n0 + ni * 8 + 2 * tg;
#pragma unroll
                for (int half = 0; half < 2; half++) {
                    int row = row0 + half * 8;
                    float v0 = p1[mi][ni][half * 2 + 0];
                    float v1 = p1[mi][ni][half * 2 + 1];
                    v0 = 0.5f * v0 * (1.f + erff(v0 * 0.70710678118654752f));
                    v1 = 0.5f * v1 * (1.f + erff(v1 * 0.70710678118654752f));
                    Ps[row * 68 + col] = v0;
                    Ps[row * 68 + col + 1] = v1;
                }
            }
        }
        __syncthreads();
#pragma unroll
        for (int kk = 0; kk < 64; kk += 8) {
            uint32_t a[4][4], bfr[4][2];
#pragma unroll
            for (int mi = 0; mi < 4; mi++) {
                int r = m0 + mi * 16 + g;
                a[mi][0] = to_tf32(Ps[r * 68 + kk + tg]);
                a[mi][1] = to_tf32(Ps[(r + 8) * 68 + kk + tg]);
                a[mi][2] = to_tf32(Ps[r * 68 + kk + tg + 4]);
                a[mi][3] = to_tf32(Ps[(r + 8) * 68 + kk + tg + 4]);
            }
#pragma unroll
            for (int ni = 0; ni < 4; ni++) {
                int c = n0 + ni * 8 + g;
                bfr[ni][0] = to_tf32(Ws2[c * 68 + kk + tg]);
                bfr[ni][1] = to_tf32(Ws2[c * 68 + kk + tg + 4]);
            }
#pragma unroll
            for (int mi = 0; mi < 4; mi++)
#pragma unroll
                for (int ni = 0; ni < 4; ni++)
                    mma_tf32(acc[mi][ni], a[mi], bfr[ni]);
        }
    }
#pragma unroll
    for (int mi = 0; mi < 4; mi++) {
        int row0 = rb + m0 + mi * 16 + g;
#pragma unroll
        for (int ni = 0; ni < 4; ni++) {
            int col = n0 + ni * 8 + 2 * tg;
#pragma unroll
            for (int half = 0; half < 2; half++) {
                int row = row0 + half * 8;
                C[(size_t)row * 64 + col] = acc[mi][ni][half * 2 + 0];
                C[(size_t)row * 64 + col + 1] = acc[mi][ni][half * 2 + 1];
            }
        }
    }
}

// ------------------------------------------------------------------ fused iDFT + output projection
// Per block (tb, b): Y[he][tl] = sum_m2 sel[b,he,m2]*Fi[tb*64+tl, m2]
// then a[(b, l=he*16+tb, d)] = sum_c Y[he][c] * Wo[d][c] + bo[d]
#define IFO_SS 132
#define IFO_YS 68
#define IFO_SMEM ((64*IFO_SS + 64*IFO_SS + 64*68) * 4)

__global__ __launch_bounds__(128) void ifft_out_kernel(const float* __restrict__ sel,
                                                       const float* __restrict__ Fi,
                                                       const float* __restrict__ Wo,
                                                       const float* __restrict__ bo,
                                                       float* __restrict__ out) {
    extern __shared__ float sm[];
    float* Ss = sm;                        // [64][132] sel rows (he x m2)
    float* Fs = sm + 64 * IFO_SS;          // [64][132] Fi rows (tl x m2); later Y [64][68]
    float* Ws = sm + 2 * 64 * IFO_SS;      // [64][68]  Wo rows (d x c)
    const int tb = blockIdx.x;
    const int b = blockIdx.y;
    const int tid = threadIdx.x;
    const int lane = tid & 31;
    const int w = tid >> 5;
    const int wm = w & 1, wn = w >> 1;
    const int m0 = wm * 32, n0 = wn * 32;
    const int g = lane >> 2, tg = lane & 3;

    // loads
    for (int i = tid; i < 64 * 32; i += 128) {
        int row = i >> 5;
        int c4 = (i & 31) * 4;
        *reinterpret_cast<float4*>(&Ss[row * IFO_SS + c4]) =
            *reinterpret_cast<const float4*>(sel + ((size_t)(b * 64 + row)) * M2 + c4);
        *reinterpret_cast<float4*>(&Fs[row * IFO_SS + c4]) =
            *reinterpret_cast<const float4*>(Fi + ((size_t)(tb * 64 + row)) * M2 + c4);
    }
    for (int i = tid; i < 64 * 16; i += 128) {
        int row = i >> 4;
        int c4 = (i & 15) * 4;
        *reinterpret_cast<float4*>(&Ws[row * 68 + c4]) =
            *reinterpret_cast<const float4*>(Wo + (size_t)row * 64 + c4);
    }
    __syncthreads();

    // gemm1: Y[he][tl], M=64 he, N=64 tl, K=128 m2
    float acc1[2][4][4];
#pragma unroll
    for (int mi = 0; mi < 2; mi++)
#pragma unroll
        for (int ni = 0; ni < 4; ni++)
#pragma unroll
            for (int r = 0; r < 4; r++) acc1[mi][ni][r] = 0.f;
#pragma unroll
    for (int kk = 0; kk < 128; kk += 8) {
        uint32_t a[2][4], bfr[4][2];
#pragma unroll
        for (int mi = 0; mi < 2; mi++) {
            int r = m0 + mi * 16 + g;
            a[mi][0] = to_tf32(Ss[r * IFO_SS + kk + tg]);
            a[mi][1] = to_tf32(Ss[(r + 8) * IFO_SS + kk + tg]);
            a[mi][2] = to_tf32(Ss[r * IFO_SS + kk + tg + 4]);
            a[mi][3] = to_tf32(Ss[(r + 8) * IFO_SS + kk + tg + 4]);
        }
#pragma unroll
        for (int ni = 0; ni < 4; ni++) {
            int c = n0 + ni * 8 + g;
            bfr[ni][0] = to_tf32(Fs[c * IFO_SS + kk + tg]);
            bfr[ni][1] = to_tf32(Fs[c * IFO_SS + kk + tg + 4]);
        }
#pragma unroll
        for (int mi = 0; mi < 2; mi++)
#pragma unroll
            for (int ni = 0; ni < 4; ni++)
                mma_tf32(acc1[mi][ni], a[mi], bfr[ni]);
    }
    __syncthreads();   // everyone done reading Fs
    // stage Y into Fs region (stride 68)
#pragma unroll
    for (int mi = 0; mi < 2; mi++) {
        int row0 = m0 + mi * 16 + g;
#pragma unroll
        for (int ni = 0; ni < 4; ni++) {
            int col = n0 + ni * 8 + 2 * tg;
#pragma unroll
            for (int half = 0; half < 2; half++) {
                int row = row0 + half * 8;
                Fs[row * IFO_YS + col] = acc1[mi][ni][half * 2 + 0];
                Fs[row * IFO_YS + col + 1] = acc1[mi][ni][half * 2 + 1];
            }
        }
    }
    __syncthreads();

    // gemm2: out[he][d] = Y[he][:] @ Wo[d][:]^T, M=64 he, N=64 d, K=64 c
    float acc2[2][4][4];
#pragma unroll
    for (int mi = 0; mi < 2; mi++)
#pragma unroll
        for (int ni = 0; ni < 4; ni++)
#pragma unroll
            for (int r = 0; r < 4; r++) acc2[mi][ni][r] = 0.f;
#pragma unroll
    for (int kk = 0; kk < 64; kk += 8) {
        uint32_t a[2][4], bfr[4][2];
#pragma unroll
        for (int mi = 0; mi < 2; mi++) {
            int r = m0 + mi * 16 + g;
            a[mi][0] = to_tf32(Fs[r * IFO_YS + kk + tg]);
            a[mi][1] = to_tf32(Fs[(r + 8) * IFO_YS + kk + tg]);
            a[mi][2] = to_tf32(Fs[r * IFO_YS + kk + tg + 4]);
            a[mi][3] = to_tf32(Fs[(r + 8) * IFO_YS + kk + tg + 4]);
        }
#pragma unroll
        for (int ni = 0; ni < 4; ni++) {
            int c = n0 + ni * 8 + g;
            bfr[ni][0] = to_tf32(Ws[c * 68 + kk + tg]);
            bfr[ni][1] = to_tf32(Ws[c * 68 + kk + tg + 4]);
        }
#pragma unroll
        for (int mi = 0; mi < 2; mi++)
#pragma unroll
            for (int ni = 0; ni < 4; ni++)
                mma_tf32(acc2[mi][ni], a[mi], bfr[ni]);
    }
#pragma unroll
    for (int mi = 0; mi < 2; mi++) {
        int he0 = m0 + mi * 16 + g;
#pragma unroll
        for (int ni = 0; ni < 4; ni++) {
            int col = n0 + ni * 8 + 2 * tg;
#pragma unroll
            for (int half = 0; half < 2; half++) {
                int he = he0 + half * 8;
                int l = he * 16 + tb;
                float v0 = acc2[mi][ni][half * 2 + 0] + bo[col];
                float v1 = acc2[mi][ni][half * 2 + 1] + bo[col + 1];
                out[((size_t)b * LZ + l) * 64 + col] = v0;
                out[((size_t)b * LZ + l) * 64 + col + 1] = v1;
            }
        }
    }
}

// ------------------------------------------------------------------ DFT GEMM with fused transpose
__device__ __forceinline__ void dft_body(const float* __restrict__ Aq,
                                         const float* __restrict__ F,
                                         float* __restrict__ X,
                                         int b, int cb, int zz) {
    __shared__ float As[64][33];
    __shared__ float Bs[64][36];
    const int tbase = zz * 256;
    const int tid = threadIdx.x;
    const int lane = tid & 31;
    const int w = tid >> 5;
    const int wm = w & 1, wn = w >> 1;
    const int m0 = wm * 32, n0 = wn * 32;
    const int g = lane >> 2, tg = lane & 3;
    const int lrow = tid >> 3;
    const int lcol = (tid & 7) * 4;

    float acc[2][4][4];
#pragma unroll
    for (int mi = 0; mi < 2; mi++)
#pragma unroll
        for (int ni = 0; ni < 4; ni++)
#pragma unroll
            for (int r = 0; r < 4; r++) acc[mi][ni][r] = 0.f;

    for (int t0 = tbase; t0 < tbase + 256; t0 += 32) {
#pragma unroll
        for (int i = 0; i < 4; i++) {
            int f4 = i * 128 + tid;
            int tl = f4 >> 4;
            int he = (f4 & 15) * 4;
            float4 v = *reinterpret_cast<const float4*>(
                Aq + ((size_t)(b * LZ + t0 + tl)) * DZ + he);
            As[he + 0][tl] = v.x;
            As[he + 1][tl] = v.y;
            As[he + 2][tl] = v.z;
            As[he + 3][tl] = v.w;
        }
#pragma unroll
        for (int r = 0; r < 4; r++) {
            int row = lrow + r * 16;
            *reinterpret_cast<float4*>(&Bs[row][lcol]) =
                *reinterpret_cast<const float4*>(F + (size_t)(cb + row) * LZ + t0 + lcol);
        }
        __syncthreads();
#pragma unroll
        for (int kk = 0; kk < 32; kk += 8) {
            uint32_t a[2][4], bfr[4][2];
#pragma unroll
            for (int mi = 0; mi < 2; mi++) {
                int r = m0 + mi * 16 + g;
                a[mi][0] = to_tf32(As[r][kk + tg]);
                a[mi][1] = to_tf32(As[r + 8][kk + tg]);
                a[mi][2] = to_tf32(As[r][kk + tg + 4]);
                a[mi][3] = to_tf32(As[r + 8][kk + tg + 4]);
            }
#pragma unroll
            for (int ni = 0; ni < 4; ni++) {
                int c = n0 + ni * 8 + g;
                bfr[ni][0] = to_tf32(Bs[c][kk + tg]);
                bfr[ni][1] = to_tf32(Bs[c][kk + tg + 4]);
            }
#pragma unroll
            for (int mi = 0; mi < 2; mi++)
#pragma unroll
                for (int ni = 0; ni < 4; ni++)
                    mma_tf32(acc[mi][ni], a[mi], bfr[ni]);
        }
        __syncthreads();
    }
#pragma unroll
    for (int mi = 0; mi < 2; mi++) {
        int r0 = m0 + mi * 16 + g;
#pragma unroll
        for (int ni = 0; ni < 4; ni++) {
            int col = cb + n0 + ni * 8 + 2 * tg;
#pragma unroll
            for (int half = 0; half < 2; half++) {
                int row = r0 + half * 8;
                atomicAdd(&X[(size_t)(b * 64 + row) * M2 + col], acc[mi][ni][half * 2 + 0]);
                atomicAdd(&X[(size_t)(b * 64 + row) * M2 + col + 1], acc[mi][ni][half * 2 + 1]);
            }
        }
    }
}

__global__ __launch_bounds__(128) void gemm_dft(const float* __restrict__ Aq,
                                                const float* __restrict__ F,
                                                float* __restrict__ X) {
    dft_body(Aq, F, X, blockIdx.x, blockIdx.y * 64, blockIdx.z);
}

__global__ __launch_bounds__(128) void gemm_dft2(const float* __restrict__ Aq1,
                                                 float* __restrict__ X1,
                                                 const float* __restrict__ Aq2,
                                                 float* __restrict__ X2,
                                                 const float* __restrict__ F) {
    int z = blockIdx.z;
    if (z < 4) dft_body(Aq1, F, X1, blockIdx.x, blockIdx.y * 64, z);
    else       dft_body(Aq2, F, X2, blockIdx.x, blockIdx.y * 64, z - 4);
}

// ------------------------------------------------------------------ mode-space projection (cross path)
__global__ __launch_bounds__(256) void modeproj_kernel(const float* __restrict__ Hf,
                                                       const float* __restrict__ Wq,
                                                       const float* __restrict__ bq,
                                                       const float* __restrict__ cm,
                                                       float* __restrict__ Qf) {
    __shared__ float Hs[64][68];
    __shared__ float Ws[64][68];
    int b = blockIdx.x;
    int mh = blockIdx.y;
    int tid = threadIdx.x;
    for (int i = tid; i < 64 * 16; i += 256) {
        int d = i >> 4;
        int c4 = (i & 15) * 4;
        *reinterpret_cast<float4*>(&Hs[d][c4]) =
            *reinterpret_cast<const float4*>(Hf + ((size_t)(b * 64 + d)) * M2 + mh * 64 + c4);
    }
    for (int i = tid; i < 64 * 16; i += 256) {
        int he = i >> 4;
        int c4 = (i & 15) * 4;
        *reinterpret_cast<float4*>(&Ws[he][c4]) =
            *reinterpret_cast<const float4*>(Wq + he * 64 + c4);
    }
    __syncthreads();
    if (cm && mh == 0 && tid < 64) Hs[tid][0] -= cm[b * 64 + tid] * 1024.f;
    __syncthreads();
    int he = tid >> 2;
    int mg = tid & 3;
#pragma unroll
    for (int j = 0; j < 16; j++) {
        int ml = mg + 4 * j;
        float s = 0.f;
#pragma unroll
        for (int d = 0; d < 64; d++) s += Ws[he][d] * Hs[d][ml];
        int m2 = mh * 64 + ml;
        if (m2 == 0) s += bq[he] * 1024.f;
        Qf[((size_t)(b * 64 + he)) * M2 + m2] = s;
    }
}

// ------------------------------------------------------------------ fused modeproj + mode_mix (self-attn)
#define MPM_SMEM ((2*64*68 + 64*66) * 4)
__global__ __launch_bounds__(256) void modeproj_mix_kernel(const float* __restrict__ Hf,
                                                           const float* __restrict__ Wq,
                                                           const float* __restrict__ bq,
                                                           const float* __restrict__ wr,
                                                           const float* __restrict__ wi,
                                                           float* __restrict__ sel,
                                                           float scale) {
    extern __shared__ float sm[];
    float* Hs = sm;
    float* Ws = sm + 64 * 68;
    float* Qs = sm + 2 * 64 * 68;
    int b = blockIdx.x;
    int mh = blockIdx.y;
    int tid = threadIdx.x;
    for (int i = tid; i < 64 * 16; i += 256) {
        int d = i >> 4;
        int c4 = (i & 15) * 4;
        *reinterpret_cast<float4*>(&Hs[d * 68 + c4]) =
            *reinterpret_cast<const float4*>(Hf + ((size_t)(b * 64 + d)) * M2 + mh * 64 + c4);
    }
    for (int i = tid; i < 64 * 16; i += 256) {
        int he = i >> 4;
        int c4 = (i & 15) * 4;
        *reinterpret_cast<float4*>(&Ws[he * 68 + c4]) =
            *reinterpret_cast<const float4*>(Wq + he * 64 + c4);
    }
    __syncthreads();
    {
        int he = tid >> 2;
        int mg = tid & 3;
#pragma unroll
        for (int j = 0; j < 16; j++) {
            int ml = mg + 4 * j;
            float s = 0.f;
#pragma unroll
            for (int d = 0; d < 64; d++) s += Ws[he * 68 + d] * Hs[d * 68 + ml];
            if (mh == 0 && ml == 0) s += bq[he] * 1024.f;
            Qs[he * 66 + ml] = s;
        }
    }
    __syncthreads();
    {
        int lm = tid & 31;
        int hob = tid >> 5;
        int m = mh * 32 + lm;
#pragma unroll
        for (int j = 0; j < 8; j++) {
            int ho = hob * 8 + j;
            int h = ho >> 3, o = ho & 7;
            float ar = 0.f, ai = 0.f;
#pragma unroll
            for (int e = 0; e < 8; e++) {
                float xr = Qs[(h * 8 + e) * 66 + 2 * lm];
                float xi = Qs[(h * 8 + e) * 66 + 2 * lm + 1];
                int wix = ((h * 8 + e) * 8 + o) * MZ + m;
                float wrv = wr[wix], wiv = wi[wix];
                ar += xr * wrv - xi * wiv;
                ai += xr * wiv + xi * wrv;
            }
            size_t ro = ((size_t)(b * 64 + h * 8 + o)) * M2 + 2 * m;
            sel[ro] = ar * scale;
            sel[ro + 1] = ai * scale;
        }
    }
}

// ------------------------------------------------------------------ fused cross attention
__global__ __launch_bounds__(256) void qkattn_kernel(const float* __restrict__ Qf,
                                                     const float* __restrict__ Kf,
                                                     const float* __restrict__ wr,
                                                     const float* __restrict__ wi,
                                                     float* __restrict__ sel,
                                                     float scale) {
    __shared__ float Qs[8][128];
    __shared__ float Ks[8][128];
    __shared__ float qks[64][130];
    __shared__ float Vs[8][128];
    int bh = blockIdx.x;
    int h = bh & 7, b = bh >> 3;
    int tid = threadIdx.x;
    size_t tbase = (size_t)(b * 64 + h * 8) * M2;
#pragma unroll
    for (int i = 0; i < 4; i++) {
        int f = i * 256 + tid;
        int e = f >> 7, c = f & 127;
        Qs[e][c] = Qf[tbase + e * M2 + c];
        Ks[e][c] = Kf[tbase + e * M2 + c];
    }
    __syncthreads();
    {
        int x = tid >> 2;
        int ys = tid & 3;
#pragma unroll
        for (int j = 0; j < 16; j++) {
            int y = ys * 16 + j;
            float ar = 0.f, ai = 0.f;
#pragma unroll
            for (int e = 0; e < 8; e++) {
                float qr = Qs[e][2 * x], qi = Qs[e][2 * x + 1];
                float kr = Ks[e][2 * y], ki = Ks[e][2 * y + 1];
                ar += qr * kr - qi * ki;
                ai += qr * ki + qi * kr;
            }
            float a2 = 2.f * ar, b2 = 2.f * ai;
            float tr, ti;
            if (fabsf(a2) > 30.f) {
                tr = copysignf(1.f, ar);
                ti = 0.f;
            } else {
                float sn, cs;
                sincosf(b2, &sn, &cs);
                float ex = expf(a2);
                float exi = 1.f / ex;
                float den = 0.5f * (ex + exi) + cs;
                tr = 0.5f * (ex - exi) / den;
                ti = sn / den;
            }
            qks[x][2 * y] = tr;
            qks[x][2 * y + 1] = ti;
        }
    }
    __syncthreads();
    {
        int flat0 = tid * 2;
#pragma unroll
        for (int u = 0; u < 2; u++) {
            int flat = flat0 + u;
            int e = flat >> 6, x = flat & 63;
            float ar = 0.f, ai = 0.f;
#pragma unroll 16
            for (int y = 0; y < 64; y++) {
                float qr = qks[x][2 * y], qi = qks[x][2 * y + 1];
                float kr = Ks[e][2 * y], ki = Ks[e][2 * y + 1];
                ar += qr * kr - qi * ki;
                ai += qr * ki + qi * kr;
            }
            Vs[e][2 * x] = ar;
            Vs[e][2 * x + 1] = ai;
        }
    }
    __syncthreads();
    {
        int m = tid & 63;
        int og = tid >> 6;
#pragma unroll
        for (int j = 0; j < 2; j++) {
            int o = og * 2 + j;
            float ar = 0.f, ai = 0.f;
#pragma unroll
            for (int e = 0; e < 8; e++) {
                float xr = Vs[e][2 * m], xi = Vs[e][2 * m + 1];
                int wix = ((h * 8 + e) * 8 + o) * MZ + m;
                float wrv = wr[wix], wiv = wi[wix];
                ar += xr * wrv - xi * wiv;
                ai += xr * wiv + xi * wrv;
            }
            size_t ro = ((size_t)(b * 64 + h * 8 + o)) * M2 + 2 * m;
            sel[ro] = ar * scale;
            sel[ro + 1] = ai * scale;
        }
    }
}

// ------------------------------------------------------------------ layernorm family
__global__ void ln_row_kernel(const float* __restrict__ X, const float* __restrict__ g,
                              const float* __restrict__ be, float* __restrict__ out) {
    __shared__ float red[256];
    int tid = threadIdx.x;
    int sub = tid >> 6;
    int d = tid & 63;
    int row = blockIdx.x * 4 + sub;
    float v = X[(size_t)row * DZ + d];
    red[tid] = v;
    __syncthreads();
    for (int s = 32; s > 0; s >>= 1) {
        if (d < s) red[tid] += red[tid + s];
        __syncthreads();
    }
    float mu = red[sub * 64] * (1.f / 64.f);
    __syncthreads();
    float dv = v - mu;
    red[tid] = dv * dv;
    __syncthreads();
    for (int s = 32; s > 0; s >>= 1) {
        if (d < s) red[tid] += red[tid + s];
        __syncthreads();
    }
    float var = red[sub * 64] * (1.f / 64.f);
    out[(size_t)row * DZ + d] = dv * rsqrtf(var + 1e-5f) * g[d] + be[d];
}

__global__ void colmean_kernel(const float* __restrict__ X, float* __restrict__ cm) {
    __shared__ float r[256];
    int b = blockIdx.x / DZ, d = blockIdx.x % DZ;
    float s = 0.f;
    for (int t = threadIdx.x; t < LZ; t += 256) s += X[((size_t)(b * LZ + t)) * DZ + d];
    r[threadIdx.x] = s;
    __syncthreads();
    for (int o = 128; o > 0; o >>= 1) {
        if (threadIdx.x < o) r[threadIdx.x] += r[threadIdx.x + o];
        __syncthreads();
    }
    if (threadIdx.x == 0) cm[b * DZ + d] = r[0] * (1.f / LZ);
}

// ------------------------------------------------------------------ final epilogue
__global__ void final_kernel(const float* __restrict__ xln, const float* __restrict__ cm,
                             const float* __restrict__ tacc,
                             const float* __restrict__ tbase, const float* __restrict__ tw,
                             const float* __restrict__ pw, const float* __restrict__ pb,
                             float* __restrict__ out) {
    int idx = blockIdx.x * blockDim.x + threadIdx.x;
    if (idx >= BZ * 512) return;
    int t = idx & 511, b = idx >> 9;
    int tt = t + 512;
    float cv = 0.f;
#pragma unroll
    for (int j = 0; j < 3; j++) {
        int ts = (tt + j - 1) & (LZ - 1);
        const float* row = tacc + ((size_t)(b * LZ + ts)) * DZ;
#pragma unroll 4
        for (int d4 = 0; d4 < 16; d4++) {
            float4 rv = *reinterpret_cast<const float4*>(row + d4 * 4);
            cv += rv.x * tw[(d4 * 4 + 0) * 3 + j] + rv.y * tw[(d4 * 4 + 1) * 3 + j]
                + rv.z * tw[(d4 * 4 + 2) * 3 + j] + rv.w * tw[(d4 * 4 + 3) * 3 + j];
        }
    }
    float p = pb[0];
    const float* xr = xln + ((size_t)(b * LZ + tt)) * DZ;
    const float* cmr = cm + b * DZ;
#pragma unroll 4
    for (int d4 = 0; d4 < 16; d4++) {
        float4 xv = *reinterpret_cast<const float4*>(xr + d4 * 4);
        float4 cvv = *reinterpret_cast<const float4*>(cmr + d4 * 4);
        float4 pv = *reinterpret_cast<const float4*>(pw + d4 * 4);
        p += (xv.x - cvv.x) * pv.x + (xv.y - cvv.y) * pv.y
           + (xv.z - cvv.z) * pv.z + (xv.w - cvv.w) * pv.w;
    }
    out[idx] = p + cv + tbase[b * LZ + tt];
}

static float* symaddr_f(const void* sym) {
    void* p = nullptr;
    cudaGetSymbolAddress(&p, sym);
    return (float*)p;
}

extern "C" void kernel_launch(void* const* d_in, const int* in_sizes, int n_in,
                              void* d_out, int out_size) {
    const float* x_enc       = (const float*)d_in[0];
    const float* dp_w        = (const float*)d_in[1];
    const float* dp_b        = (const float*)d_in[2];
    const float* emb_enc_w   = (const float*)d_in[3];
    const float* emb_dec_w   = (const float*)d_in[4];
    const float* decomp_w    = (const float*)d_in[5];
    const float* decomp_b    = (const float*)d_in[6];
    const float* enc_attn_w  = (const float*)d_in[7];
    const float* enc_attn_b  = (const float*)d_in[8];
    const float* enc_four_wr = (const float*)d_in[9];
    const float* enc_four_wi = (const float*)d_in[10];
    const float* enc_c1      = (const float*)d_in[11];
    const float* enc_c2      = (const float*)d_in[12];
    const float* enc_ln_g    = (const float*)d_in[13];
    const float* enc_ln_b    = (const float*)d_in[14];
    const float* dec_self_w  = (const float*)d_in[15];
    const float* dec_self_b  = (const float*)d_in[16];
    const float* dec_four_wr = (const float*)d_in[17];
    const float* dec_four_wi = (const float*)d_in[18];
    const float* dec_cross_w = (const float*)d_in[19];
    const float* dec_cross_b = (const float*)d_in[20];
    const float* dec_cross_wr= (const float*)d_in[21];
    const float* dec_cross_wi= (const float*)d_in[22];
    const float* dec_c1      = (const float*)d_in[23];
    const float* dec_c2      = (const float*)d_in[24];
    const float* dec_trend_w = (const float*)d_in[25];
    const float* dec_ln_g    = (const float*)d_in[26];
    const float* dec_ln_b    = (const float*)d_in[27];
    const float* dec_proj_w  = (const float*)d_in[28];
    const float* dec_proj_b  = (const float*)d_in[29];
    float* out = (float*)d_out;

    float* px        = symaddr_f(g_x);
    float* pseas0    = symaddr_f(g_seas0);
    float* ptrend0   = symaddr_f(g_trend0);
    float* pseasinit = symaddr_f(g_seasinit);
    float* ph        = symaddr_f(g_h);
    float* pa        = symaddr_f(g_a);
    float* pa2       = symaddr_f(g_a2);
    float* pHf       = symaddr_f(g_Hf);
    float* pHf2      = pHf + (size_t)NHE * M2;
    float* pXf       = symaddr_f(g_Xf);
    float* pXk       = symaddr_f(g_Xk);
    float* psel      = symaddr_f(g_sel);
    float* psel2     = symaddr_f(g_sel2);
    float* pxd       = symaddr_f(g_xd);
    float* ptacc     = symaddr_f(g_tacc);
    float* pcm       = symaddr_f(g_cm);
    float* pcm2      = symaddr_f(g_cm2);
    float* pln       = symaddr_f(g_ln);
    float* pF        = symaddr_f(g_F);
    float* pFi       = symaddr_f(g_Fi);
    float* ptbase    = symaddr_f(g_trendbase);
    float* py        = symaddr_f(g_y);

    cudaFuncSetAttribute(gemm_tc<0>, cudaFuncAttributeMaxDynamicSharedMemorySize, GT_SMEM);
    cudaFuncSetAttribute(gemm_ffn, cudaFuncAttributeMaxDynamicSharedMemorySize, FFN_SMEM);
    cudaFuncSetAttribute(modeproj_mix_kernel, cudaFuncAttributeMaxDynamicSharedMemorySize, MPM_SMEM);
    cudaFuncSetAttribute(ifft_out_kernel, cudaFuncAttributeMaxDynamicSharedMemorySize, IFO_SMEM);

    static cudaStream_t s2 = nullptr;
    static cudaEvent_t evFork = nullptr, evJoin = nullptr;
    if (!s2) {
        cudaStreamCreateWithFlags(&s2, cudaStreamNonBlocking);
        cudaEventCreateWithFlags(&evFork, cudaEventDisableTiming);
        cudaEventCreateWithFlags(&evJoin, cudaEventDisableTiming);
    }

    dim3 dftg(BZ, 2, 4);
    dim3 dftg2(BZ, 2, 8);
    dim3 mpg(BZ, 2);
    dim3 ifog(16, BZ);

    // ---- shared prep (stream 0) ----
    build_tables_kernel<<<512, 256>>>();
    transpose_in_kernel<<<1792, 256>>>(x_enc);
    colmean7_kernel<<<BZ * C7, 256>>>(x_enc);
    decomp7_kernel<<<BZ * C7, LZ>>>(px, decomp_w + 0, decomp_b + 0, pseas0, ptrend0);
    trendbase_kernel<<<256, 256>>>(dp_w, dp_b);
    seasinit_kernel<<<1792, 256>>>();
    cudaEventRecord(evFork, 0);

    // ---- decoder prefix (stream s2) ----
    cudaStreamWaitEvent(s2, evFork, 0);
    embed_kernel<<<16384, 256, 0, s2>>>(pseasinit, emb_dec_w, pxd);
    cudaMemsetAsync(pHf2, 0, (size_t)NHE * M2 * sizeof(float), s2);
    gemm_dft<<<dftg, 128, 0, s2>>>(pxd, pF, pHf2);
    modeproj_mix_kernel<<<mpg, 256, MPM_SMEM, s2>>>(pHf2, dec_self_w + 0, dec_self_b + 0,
                                                    dec_four_wr, dec_four_wi, psel2, 1.0f);
    ifft_out_kernel<<<ifog, 128, IFO_SMEM, s2>>>(psel2, pFi, dec_self_w + 3 * 4096,
                                                 dec_self_b + 3 * 64, pa2);
    decomp64_kernel<<<1024, 256, 0, s2>>>(pxd, pa2, decomp_w + 5 * 4, decomp_b + 5 * 4,
                                          pxd, ptacc, 0);
    cudaEventRecord(evJoin, s2);

    // ---- encoder (stream 0) ----
    embed_kernel<<<16384, 256>>>(px, emb_enc_w, ph);
    for (int l = 0; l < 2; l++) {
        const float* wq = enc_attn_w + (size_t)(l * 4 + 0) * 4096;
        const float* bq = enc_attn_b + (size_t)(l * 4 + 0) * 64;
        const float* wo = enc_attn_w + (size_t)(l * 4 + 3) * 4096;
        const float* bo = enc_attn_b + (size_t)(l * 4 + 3) * 64;
        cudaMemsetAsync(pHf, 0, (size_t)NHE * M2 * sizeof(float));
        gemm_dft<<<dftg, 128>>>(ph, pF, pHf);
        modeproj_mix_kernel<<<mpg, 256, MPM_SMEM>>>(pHf, wq, bq,
                                                    enc_four_wr + (size_t)l * 32768,
                                                    enc_four_wi + (size_t)l * 32768, psel, 1.0f);
        ifft_out_kernel<<<ifog, 128, IFO_SMEM>>>(psel, pFi, wo, bo, pa);
        decomp64_kernel<<<1024, 256>>>(ph, pa, decomp_w + (1 + 2 * l) * 4,
                                       decomp_b + (1 + 2 * l) * 4, ph, nullptr, 0);
        gemm_ffn<<<512, 128, FFN_SMEM>>>(ph, enc_c1 + (size_t)l * 16384,
                                         enc_c2 + (size_t)l * 16384, py);
        decomp64_kernel<<<1024, 256>>>(ph, py, decomp_w + (2 + 2 * l) * 4,
                                       decomp_b + (2 + 2 * l) * 4, ph, nullptr, 0);
    }
    ln_row_kernel<<<16384, 256>>>(ph, enc_ln_g, enc_ln_b, ph);
    colmean_kernel<<<BZ * DZ, 256>>>(ph, pcm2);

    // ---- join, then cross attention ----
    cudaStreamWaitEvent(0, evJoin, 0);
    cudaMemsetAsync(pHf, 0, (size_t)2 * NHE * M2 * sizeof(float));
    gemm_dft2<<<dftg2, 128>>>(pxd, pHf, ph, pHf2, pF);
    modeproj_kernel<<<mpg, 256>>>(pHf, dec_cross_w + 0, dec_cross_b + 0, nullptr, pXf);
    modeproj_kernel<<<mpg, 256>>>(pHf2, dec_cross_w + 1 * 4096, dec_cross_b + 1 * 64, pcm2, pXk);
    qkattn_kernel<<<512, 256>>>(pXf, pXk, dec_cross_wr, dec_cross_wi, psel, 1.0f / 4096.0f);
    ifft_out_kernel<<<ifog, 128, IFO_SMEM>>>(psel, pFi, dec_cross_w + 3 * 4096,
                                             dec_cross_b + 3 * 64, pa);
    decomp64_kernel<<<1024, 256>>>(pxd, pa, decomp_w + 6 * 4, decomp_b + 6 * 4, pxd, ptacc, 1);

    gemm_ffn<<<512, 128, FFN_SMEM>>>(pxd, dec_c1, dec_c2, py);
    decomp64_kernel<<<1024, 256>>>(pxd, py, decomp_w + 7 * 4, decomp_b + 7 * 4, pxd, ptacc, 1);

    ln_row_kernel<<<16384, 256>>>(pxd, dec_ln_g, dec_ln_b, pln);
    colmean_kernel<<<BZ * DZ, 256>>>(pln, pcm);
    final_kernel<<<128, 256>>>(pln, pcm, ptacc, ptbase, dec_trend_w, dec_proj_w, dec_proj_b, out);
}

// round 13
// speedup vs baseline: 1.0343x; 1.0343x over previous
#include <cuda_runtime.h>
#include <cstdint>

#define BZ 64
#define LZ 1024
#define DZ 64
#define C7 7
#define HZ 8
#define EZ 8
#define MZ 64
#define M2 128
#define DFFD 256
#define NROW (BZ*LZ)
#define NHE  (BZ*DZ)

__device__ float g_x[BZ*LZ*C7];
__device__ float g_seas0[BZ*LZ*C7];
__device__ float g_trend0[BZ*LZ*C7];
__device__ float g_mean7[BZ*C7];
__device__ float g_trendbase[BZ*LZ];
__device__ float g_seasinit[BZ*LZ*C7];
__device__ float g_h[NROW*DZ];
__device__ float g_y[NROW*DZ];
__device__ float g_a[NROW*DZ];
__device__ float g_y2[NROW*DZ];
__device__ float g_a2[NROW*DZ];
__device__ float g_Hf[2*NHE*M2];
__device__ float g_Xf[NHE*M2];
__device__ float g_Xk[NHE*M2];
__device__ float g_sel[NHE*M2];
__device__ float g_sel2[NHE*M2];
__device__ float g_xd[NROW*DZ];
__device__ float g_tacc[NROW*DZ];
__device__ float g_cm[BZ*DZ];
__device__ float g_cm2[BZ*DZ];
__device__ float g_ln[NROW*DZ];
__device__ float g_F[M2*LZ];
__device__ float g_Fi[LZ*M2];
__device__ float g_pe[LZ*DZ];

// ------------------------------------------------------------------ tables
__global__ void build_tables_kernel() {
    int idx = blockIdx.x * blockDim.x + threadIdx.x;
    if (idx < LZ * M2) {
        int t = idx >> 7;
        int m2 = idx & 127;
        int m = m2 >> 1;
        int r = (m * t) & (LZ - 1);
        float a = (float)r * (6.28318530717958647692f / (float)LZ);
        float s, c;
        sincosf(a, &s, &c);
        float v = (m2 & 1) ? -s : c;
        g_F[(size_t)m2 * LZ + t] = v;
        float cm = (m == 0) ? 1.f : 2.f;
        g_Fi[(size_t)t * M2 + m2] = v * (cm / (float)LZ);
    }
    if (idx < LZ * DZ) {
        int o = idx & 63;
        int t = idx >> 6;
        int i2 = o & ~1;
        float div = expf(-(float)i2 * 0.14391156831212793f);
        float arg = (float)t * div;
        g_pe[idx] = (o & 1) ? cosf(arg) : sinf(arg);
    }
}

// ------------------------------------------------------------------ input prep
__global__ void transpose_in_kernel(const float* __restrict__ xe) {
    int idx = blockIdx.x * blockDim.x + threadIdx.x;
    if (idx >= BZ * C7 * LZ) return;
    int t = idx & 1023;
    int c = (idx >> 10) % C7;
    int b = idx / (C7 * LZ);
    g_x[((size_t)(b * LZ + t)) * C7 + c] = xe[idx];
}

__global__ void colmean7_kernel(const float* __restrict__ xe) {
    __shared__ float r[256];
    int bc = blockIdx.x;
    float s = 0.f;
    for (int t = threadIdx.x; t < LZ; t += 256) s += xe[(size_t)bc * LZ + t];
    r[threadIdx.x] = s;
    __syncthreads();
    for (int o = 128; o > 0; o >>= 1) {
        if (threadIdx.x < o) r[threadIdx.x] += r[threadIdx.x + o];
        __syncthreads();
    }
    if (threadIdx.x == 0) g_mean7[bc] = r[0] * (1.f / LZ);
}

// ------------------------------------------------------------------ decomp7
__global__ void decomp7_kernel(const float* __restrict__ A,
                               const float* __restrict__ w4, const float* __restrict__ b4,
                               float* __restrict__ seas, float* __restrict__ trend) {
    __shared__ float ps[LZ];
    __shared__ float wsum[32];
    __shared__ float sx0, sxN;
    int c = blockIdx.x % C7, b = blockIdx.x / C7;
    int t = threadIdx.x, lane = t & 31, wid = t >> 5;
    size_t idx = ((size_t)(b * LZ + t)) * C7 + c;
    float x = A[idx];
    float s = x;
#pragma unroll
    for (int off = 1; off < 32; off <<= 1) {
        float v = __shfl_up_sync(0xffffffffu, s, off);
        if (lane >= off) s += v;
    }
    if (lane == 31) wsum[wid] = s;
    if (t == 0) sx0 = x;
    if (t == LZ - 1) sxN = x;
    __syncthreads();
    if (wid == 0) {
        float v = wsum[lane];
#pragma unroll
        for (int off = 1; off < 32; off <<= 1) {
            float u = __shfl_up_sync(0xffffffffu, v, off);
            if (lane >= off) v += u;
        }
        wsum[lane] = v;
    }
    __syncthreads();
    if (wid > 0) s += wsum[wid - 1];
    ps[t] = s;
    __syncthreads();
    float x0 = sx0, xN = sxN;
    const int ks[4] = {10, 50, 100, 500};
    float ma[4];
#pragma unroll
    for (int kk = 0; kk < 4; kk++) {
        int k = ks[kk], f = (k - 1) >> 1, e = k >> 1;
        int lo = t - f, hi = t + e;
        int cl = lo < 0 ? 0 : lo, ch = hi > LZ - 1 ? LZ - 1 : hi;
        float sw = ps[ch] - (cl > 0 ? ps[cl - 1] : 0.f)
                 + (float)(cl - lo) * x0 + (float)(hi - ch) * xN;
        ma[kk] = sw / (float)k;
    }
    float z[4], mx = -1e30f;
#pragma unroll
    for (int kk = 0; kk < 4; kk++) { z[kk] = x * w4[kk] + b4[kk]; mx = fmaxf(mx, z[kk]); }
    float se = 0.f, mean = 0.f;
#pragma unroll
    for (int kk = 0; kk < 4; kk++) { float e2 = expf(z[kk] - mx); se += e2; mean += ma[kk] * e2; }
    mean /= se;
    seas[idx] = x - mean;
    trend[idx] = mean;
}

__device__ __forceinline__ float4 f4add(float4 a, float4 b) {
    return make_float4(a.x + b.x, a.y + b.y, a.z + b.z, a.w + b.w);
}

// ------------------------------------------------------------------ decomp64
__global__ __launch_bounds__(256) void decomp64_kernel(
    const float* __restrict__ A, const float* __restrict__ Bb,
    const float* __restrict__ w4, const float* __restrict__ b4,
    float* __restrict__ seas, float* __restrict__ trend, int accum) {
    __shared__ float4 ps[LZ];
    __shared__ float4 wsum[8];
    __shared__ float4 sedge[2];
    int c4 = blockIdx.x & 15, b = blockIdx.x >> 4;
    int tid = threadIdx.x, lane = tid & 31, wid = tid >> 5;
    int t4 = tid * 4;
    size_t base = ((size_t)(b * LZ + t4)) * DZ + c4 * 4;

    float4 x[4], p[4];
#pragma unroll
    for (int j = 0; j < 4; j++) {
        x[j] = *reinterpret_cast<const float4*>(A + base + (size_t)j * DZ);
        if (Bb) x[j] = f4add(x[j], *reinterpret_cast<const float4*>(Bb + base + (size_t)j * DZ));
    }
    p[0] = x[0];
#pragma unroll
    for (int j = 1; j < 4; j++) p[j] = f4add(p[j - 1], x[j]);

    float4 s = p[3];
#pragma unroll
    for (int off = 1; off < 32; off <<= 1) {
        float4 v;
        v.x = __shfl_up_sync(0xffffffffu, s.x, off);
        v.y = __shfl_up_sync(0xffffffffu, s.y, off);
        v.z = __shfl_up_sync(0xffffffffu, s.z, off);
        v.w = __shfl_up_sync(0xffffffffu, s.w, off);
        if (lane >= off) s = f4add(s, v);
    }
    if (lane == 31) wsum[wid] = s;
    if (tid == 0) sedge[0] = x[0];
    if (tid == 255) sedge[1] = x[3];
    __syncthreads();
    if (wid == 0 && lane < 8) {
        float4 v = wsum[lane];
#pragma unroll
        for (int off = 1; off < 8; off <<= 1) {
            float4 u;
            u.x = __shfl_up_sync(0xffu, v.x, off);
            u.y = __shfl_up_sync(0xffu, v.y, off);
            u.z = __shfl_up_sync(0xffu, v.z, off);
            u.w = __shfl_up_sync(0xffu, v.w, off);
            if (lane >= off) v = f4add(v, u);
        }
        wsum[lane] = v;
    }
    __syncthreads();
    float4 ex = make_float4(0.f, 0.f, 0.f, 0.f);
    if (wid > 0) ex = wsum[wid - 1];
    {
        float4 d;
        d.x = s.x - p[3].x; d.y = s.y - p[3].y; d.z = s.z - p[3].z; d.w = s.w - p[3].w;
        ex = f4add(ex, d);
    }
#pragma unroll
    for (int j = 0; j < 4; j++) ps[t4 + j] = f4add(ex, p[j]);
    __syncthreads();

    float4 x0 = sedge[0], xN = sedge[1];
    const int ks[4] = {10, 50, 100, 500};
#pragma unroll
    for (int j = 0; j < 4; j++) {
        int t = t4 + j;
        float ma[4][4];
#pragma unroll
        for (int kk = 0; kk < 4; kk++) {
            int k = ks[kk], f = (k - 1) >> 1, e = k >> 1;
            int lo = t - f, hi = t + e;
            int cl = lo < 0 ? 0 : lo, ch = hi > LZ - 1 ? LZ - 1 : hi;
            float4 pc = ps[ch];
            float4 pl = make_float4(0.f, 0.f, 0.f, 0.f);
            if (cl > 0) pl = ps[cl - 1];
            float fl = (float)(cl - lo), fr = (float)(hi - ch);
            float inv = 1.f / (float)k;
            ma[kk][0] = (pc.x - pl.x + fl * x0.x + fr * xN.x) * inv;
            ma[kk][1] = (pc.y - pl.y + fl * x0.y + fr * xN.y) * inv;
            ma[kk][2] = (pc.z - pl.z + fl * x0.z + fr * xN.z) * inv;
            ma[kk][3] = (pc.w - pl.w + fl * x0.w + fr * xN.w) * inv;
        }
        float xa[4] = {x[j].x, x[j].y, x[j].z, x[j].w};
        float so[4], tr[4];
#pragma unroll
        for (int cc = 0; cc < 4; cc++) {
            float z[4], mx = -1e30f;
#pragma unroll
            for (int kk = 0; kk < 4; kk++) { z[kk] = xa[cc] * w4[kk] + b4[kk]; mx = fmaxf(mx, z[kk]); }
            float se = 0.f, mean = 0.f;
#pragma unroll
            for (int kk = 0; kk < 4; kk++) { float e2 = expf(z[kk] - mx); se += e2; mean += ma[kk][cc] * e2; }
            mean /= se;
            so[cc] = xa[cc] - mean;
            tr[cc] = mean;
        }
        *reinterpret_cast<float4*>(seas + base + (size_t)j * DZ) =
            make_float4(so[0], so[1], so[2], so[3]);
        if (trend) {
            float4 tv = make_float4(tr[0], tr[1], tr[2], tr[3]);
            if (accum) {
                float4 old = *reinterpret_cast<float4*>(trend + base + (size_t)j * DZ);
                tv = f4add(tv, old);
            }
            *reinterpret_cast<float4*>(trend + base + (size_t)j * DZ) = tv;
        }
    }
}

// ------------------------------------------------------------------ trend/seasonal init
__global__ void trendbase_kernel(const float* __restrict__ dpw, const float* __restrict__ dpb) {
    int idx = blockIdx.x * blockDim.x + threadIdx.x;
    if (idx >= BZ * LZ) return;
    int t = idx & 1023, b = idx >> 10;
    float s = dpb[0];
#pragma unroll
    for (int c = 0; c < C7; c++) {
        float v = (t < 512) ? g_trend0[((size_t)(b * LZ + 512 + t)) * C7 + c]
                            : g_mean7[b * C7 + c];
        s += v * dpw[c];
    }
    g_trendbase[idx] = s;
}

__global__ void seasinit_kernel() {
    int idx = blockIdx.x * blockDim.x + threadIdx.x;
    if (idx >= BZ * LZ * C7) return;
    int c = idx % C7;
    int t = (idx / C7) & 1023;
    int b = idx / (C7 * LZ);
    g_seasinit[idx] = (t < 512) ? g_seas0[((size_t)(b * LZ + 512 + t)) * C7 + c] : 0.f;
}

// ------------------------------------------------------------------ embedding
__global__ void embed_kernel(const float* __restrict__ in, const float* __restrict__ w,
                             float* __restrict__ out) {
    int idx = blockIdx.x * blockDim.x + threadIdx.x;
    if (idx >= BZ * LZ * DZ) return;
    int o = idx & 63;
    int t = (idx >> 6) & 1023;
    int b = idx >> 16;
    float s = 0.f;
#pragma unroll
    for (int j = 0; j < 3; j++) {
        int ts = (t + j - 1 + LZ) & (LZ - 1);
        const float* ip = in + ((size_t)(b * LZ + ts)) * C7;
#pragma unroll
        for (int c = 0; c < C7; c++) s += ip[c] * w[(o * C7 + c) * 3 + j];
    }
    out[idx] = s + g_pe[(t << 6) + o];
}

// ------------------------------------------------------------------ tf32 helpers
__device__ __forceinline__ uint32_t to_tf32(float x) {
    uint32_t r;
    asm("cvt.rna.tf32.f32 %0, %1;" : "=r"(r) : "f"(x));
    return r;
}
__device__ __forceinline__ void cpa16(uint32_t s, const float* g) {
    asm volatile("cp.async.ca.shared.global [%0], [%1], 16;" :: "r"(s), "l"(g));
}
__device__ __forceinline__ void cpa_commit() {
    asm volatile("cp.async.commit_group;");
}
__device__ __forceinline__ void cpa_wait1() {
    asm volatile("cp.async.wait_group 1;");
}
__device__ __forceinline__ void mma_tf32(float* acc, const uint32_t* a, const uint32_t* bf) {
    asm volatile(
        "mma.sync.aligned.m16n8k8.row.col.f32.tf32.tf32.f32 "
        "{%0,%1,%2,%3}, {%4,%5,%6,%7}, {%8,%9}, {%0,%1,%2,%3};"
        : "+f"(acc[0]), "+f"(acc[1]), "+f"(acc[2]), "+f"(acc[3])
        : "r"(a[0]), "r"(a[1]), "r"(a[2]), "r"(a[3]), "r"(bf[0]), "r"(bf[1]));
}

// ------------------------------------------------------------------ tf32 GEMM
#define GT_ASTRIDE (128*36)
#define GT_BSTRIDE (64*36)
#define GT_SMEM ((2*GT_ASTRIDE + 2*GT_BSTRIDE) * 4)

template <int ACT>
__global__ __launch_bounds__(128) void gemm_tc(const float* __restrict__ A,
                                               const float* __restrict__ W,
                                               const float* __restrict__ bias,
                                               float* __restrict__ C,
                                               int N, int K, int O) {
    extern __shared__ float dsm[];
    float* As = dsm;
    float* Bs = dsm + 2 * GT_ASTRIDE;
    const int rb = blockIdx.x * 128;
    const int cb = blockIdx.y * 64;
    const int tid = threadIdx.x;
    const int lane = tid & 31;
    const int w = tid >> 5;
    const int wm = w & 1, wn = w >> 1;
    const int m0 = wm * 64, n0 = wn * 32;
    const int g = lane >> 2, tg = lane & 3;
    const int lrow = tid >> 3;
    const int lcol = (tid & 7) * 4;

    uint32_t sA = (uint32_t)__cvta_generic_to_shared(As);
    uint32_t sB = (uint32_t)__cvta_generic_to_shared(Bs);

    float acc[4][4][4];
#pragma unroll
    for (int mi = 0; mi < 4; mi++)
#pragma unroll
        for (int ni = 0; ni < 4; ni++)
#pragma unroll
            for (int r = 0; r < 4; r++) acc[mi][ni][r] = 0.f;

#pragma unroll
    for (int r = 0; r < 8; r++) {
        int row = lrow + r * 16;
        cpa16(sA + (uint32_t)((row * 36 + lcol) * 4), A + (size_t)(rb + row) * K + lcol);
    }
#pragma unroll
    for (int r = 0; r < 4; r++) {
        int row = lrow + r * 16;
        cpa16(sB + (uint32_t)((row * 36 + lcol) * 4), W + (size_t)(cb + row) * K + lcol);
    }
    cpa_commit();

    int st = 0;
    for (int k0 = 0; k0 < K; k0 += 32, st ^= 1) {
        if (k0 + 32 < K) {
            int nx = st ^ 1;
#pragma unroll
            for (int r = 0; r < 8; r++) {
                int row = lrow + r * 16;
                cpa16(sA + (uint32_t)((nx * GT_ASTRIDE + row * 36 + lcol) * 4),
                      A + (size_t)(rb + row) * K + k0 + 32 + lcol);
            }
#pragma unroll
            for (int r = 0; r < 4; r++) {
                int row = lrow + r * 16;
                cpa16(sB + (uint32_t)((nx * GT_BSTRIDE + row * 36 + lcol) * 4),
                      W + (size_t)(cb + row) * K + k0 + 32 + lcol);
            }
        }
        cpa_commit();
        cpa_wait1();
        __syncthreads();
        const float* Ast = As + st * GT_ASTRIDE;
        const float* Bst = Bs + st * GT_BSTRIDE;
#pragma unroll
        for (int kk = 0; kk < 32; kk += 8) {
            uint32_t a[4][4], bfr[4][2];
#pragma unroll
            for (int mi = 0; mi < 4; mi++) {
                int r = m0 + mi * 16 + g;
                a[mi][0] = to_tf32(Ast[r * 36 + kk + tg]);
                a[mi][1] = to_tf32(Ast[(r + 8) * 36 + kk + tg]);
                a[mi][2] = to_tf32(Ast[r * 36 + kk + tg + 4]);
                a[mi][3] = to_tf32(Ast[(r + 8) * 36 + kk + tg + 4]);
            }
#pragma unroll
            for (int ni = 0; ni < 4; ni++) {
                int c = n0 + ni * 8 + g;
                bfr[ni][0] = to_tf32(Bst[c * 36 + kk + tg]);
                bfr[ni][1] = to_tf32(Bst[c * 36 + kk + tg + 4]);
            }
#pragma unroll
            for (int mi = 0; mi < 4; mi++)
#pragma unroll
                for (int ni = 0; ni < 4; ni++)
                    mma_tf32(acc[mi][ni], a[mi], bfr[ni]);
        }
        __syncthreads();
    }
#pragma unroll
    for (int mi = 0; mi < 4; mi++) {
        int row0 = rb + m0 + mi * 16 + g;
#pragma unroll
        for (int ni = 0; ni < 4; ni++) {
            int col = cb + n0 + ni * 8 + 2 * tg;
#pragma unroll
            for (int half = 0; half < 2; half++) {
                int row = row0 + half * 8;
                float v0 = acc[mi][ni][half * 2 + 0];
                float v1 = acc[mi][ni][half * 2 + 1];
                if (bias) { v0 += bias[col]; v1 += bias[col + 1]; }
                if (ACT == 1) {
                    v0 = 0.5f * v0 * (1.f + erff(v0 * 0.70710678118654752f));
                    v1 = 0.5f * v1 * (1.f + erff(v1 * 0.70710678118654752f));
                }
                C[(size_t)row * O + col] = v0;
                C[(size_t)row * O + col + 1] = v1;
            }
        }
    }
}

// ------------------------------------------------------------------ fused FFN
#define FFN_AS  (128*68)
#define FFN_WS  (64*68)
#define FFN_PS  (128*68)
#define FFN_SMEM ((FFN_AS + 2*FFN_WS + FFN_PS) * 4)

__global__ __launch_bounds__(128) void gemm_ffn(const float* __restrict__ A,
                                                const float* __restrict__ W1,
                                                const float* __restrict__ W2,
                                                float* __restrict__ C) {
    extern __shared__ float sm[];
    float* As  = sm;
    float* Ws1 = sm + FFN_AS;
    float* Ws2 = sm + FFN_AS + FFN_WS;
    float* Ps  = sm + FFN_AS + 2 * FFN_WS;
    const int rb = blockIdx.x * 128;
    const int tid = threadIdx.x;
    const int lane = tid & 31;
    const int w = tid >> 5;
    const int wm = w & 1, wn = w >> 1;
    const int m0 = wm * 64, n0 = wn * 32;
    const int g = lane >> 2, tg = lane & 3;

    for (int i = tid; i < 128 * 16; i += 128) {
        int row = i >> 4;
        int c4 = (i & 15) * 4;
        *reinterpret_cast<float4*>(&As[row * 68 + c4]) =
            *reinterpret_cast<const float4*>(A + (size_t)(rb + row) * 64 + c4);
    }

    float acc[4][4][4];
#pragma unroll
    for (int mi = 0; mi < 4; mi++)
#pragma unroll
        for (int ni = 0; ni < 4; ni++)
#pragma unroll
            for (int r = 0; r < 4; r++) acc[mi][ni][r] = 0.f;

    for (int ch = 0; ch < 4; ch++) {
        __syncthreads();
        for (int i = tid; i < 64 * 16; i += 128) {
            int row = i >> 4;
            int c4 = (i & 15) * 4;
            *reinterpret_cast<float4*>(&Ws1[row * 68 + c4]) =
                *reinterpret_cast<const float4*>(W1 + (size_t)(ch * 64 + row) * 64 + c4);
            *reinterpret_cast<float4*>(&Ws2[row * 68 + c4]) =
                *reinterpret_cast<const float4*>(W2 + (size_t)row * 256 + ch * 64 + c4);
        }
        __syncthreads();
        float p1[4][4][4];
#pragma unroll
        for (int mi = 0; mi < 4; mi++)
#pragma unroll
            for (int ni = 0; ni < 4; ni++)
#pragma unroll
                for (int r = 0; r < 4; r++) p1[mi][ni][r] = 0.f;
#pragma unroll
        for (int kk = 0; kk < 64; kk += 8) {
            uint32_t a[4][4], bfr[4][2];
#pragma unroll
            for (int mi = 0; mi < 4; mi++) {
                int r = m0 + mi * 16 + g;
                a[mi][0] = to_tf32(As[r * 68 + kk + tg]);
                a[mi][1] = to_tf32(As[(r + 8) * 68 + kk + tg]);
                a[mi][2] = to_tf32(As[r * 68 + kk + tg + 4]);
                a[mi][3] = to_tf32(As[(r + 8) * 68 + kk + tg + 4]);
            }
#pragma unroll
            for (int ni = 0; ni < 4; ni++) {
                int c = n0 + ni * 8 + g;
                bfr[ni][0] = to_tf32(Ws1[c * 68 + kk + tg]);
                bfr[ni][1] = to_tf32(Ws1[c * 68 + kk + tg + 4]);
            }
#pragma unroll
            for (int mi = 0; mi < 4; mi++)
#pragma unroll
                for (int ni = 0; ni < 4; ni++)
                    mma_tf32(p1[mi][ni], a[mi], bfr[ni]);
        }
#pragma unroll
        for (int mi = 0; mi < 4; mi++) {
            int row0 = m0 + mi * 16 + g;
#pragma unroll
            for (int ni = 0; ni < 4; ni++) {
                int col = n0 + ni * 8 + 2 * tg;
#pragma unroll
                for (int half = 0; half < 2; half++) {
                    int row = row0 + half * 8;
                    float v0 = p1[mi][ni][half * 2 + 0];
                    float v1 = p1[mi][ni][half * 2 + 1];
                    v0 = 0.5f * v0 * (1.f + erff(v0 * 0.70710678118654752f));
                    v1 = 0.5f * v1 * (1.f + erff(v1 * 0.70710678118654752f));
                    Ps[row * 68 + col] = v0;
                    Ps[row * 68 + col + 1] = v1;
                }
            }
        }
        __syncthreads();
#pragma unroll
        for (int kk = 0; kk < 64; kk += 8) {
            uint32_t a[4][4], bfr[4][2];
#pragma unroll
            for (int mi = 0; mi < 4; mi++) {
                int r = m0 + mi * 16 + g;
                a[mi][0] = to_tf32(Ps[r * 68 + kk + tg]);
                a[mi][1] = to_tf32(Ps[(r + 8) * 68 + kk + tg]);
                a[mi][2] = to_tf32(Ps[r * 68 + kk + tg + 4]);
                a[mi][3] = to_tf32(Ps[(r + 8) * 68 + kk + tg + 4]);
            }
#pragma unroll
            for (int ni = 0; ni < 4; ni++) {
                int c = n0 + ni * 8 + g;
                bfr[ni][0] = to_tf32(Ws2[c * 68 + kk + tg]);
                bfr[ni][1] = to_tf32(Ws2[c * 68 + kk + tg + 4]);
            }
#pragma unroll
            for (int mi = 0; mi < 4; mi++)
#pragma unroll
                for (int ni = 0; ni < 4; ni++)
                    mma_tf32(acc[mi][ni], a[mi], bfr[ni]);
        }
    }
#pragma unroll
    for (int mi = 0; mi < 4; mi++) {
        int row0 = rb + m0 + mi * 16 + g;
#pragma unroll
        for (int ni = 0; ni < 4; ni++) {
            int col = n0 + ni * 8 + 2 * tg;
#pragma unroll
            for (int half = 0; half < 2; half++) {
                int row = row0 + half * 8;
                C[(size_t)row * 64 + col] = acc[mi][ni][half * 2 + 0];
                C[(size_t)row * 64 + col + 1] = acc[mi][ni][half * 2 + 1];
            }
        }
    }
}

// ------------------------------------------------------------------ DFT GEMM with fused transpose
__device__ __forceinline__ void dft_body(const float* __restrict__ Aq,
                                         const float* __restrict__ F,
                                         float* __restrict__ X,
                                         int b, int cb, int zz) {
    __shared__ float As[64][33];
    __shared__ float Bs[64][36];
    const int tbase = zz * 256;
    const int tid = threadIdx.x;
    const int lane = tid & 31;
    const int w = tid >> 5;
    const int wm = w & 1, wn = w >> 1;
    const int m0 = wm * 32, n0 = wn * 32;
    const int g = lane >> 2, tg = lane & 3;
    const int lrow = tid >> 3;
    const int lcol = (tid & 7) * 4;

    float acc[2][4][4];
#pragma unroll
    for (int mi = 0; mi < 2; mi++)
#pragma unroll
        for (int ni = 0; ni < 4; ni++)
#pragma unroll
            for (int r = 0; r < 4; r++) acc[mi][ni][r] = 0.f;

    for (int t0 = tbase; t0 < tbase + 256; t0 += 32) {
#pragma unroll
        for (int i = 0; i < 4; i++) {
            int f4 = i * 128 + tid;
            int tl = f4 >> 4;
            int he = (f4 & 15) * 4;
            float4 v = *reinterpret_cast<const float4*>(
                Aq + ((size_t)(b * LZ + t0 + tl)) * DZ + he);
            As[he + 0][tl] = v.x;
            As[he + 1][tl] = v.y;
            As[he + 2][tl] = v.z;
            As[he + 3][tl] = v.w;
        }
#pragma unroll
        for (int r = 0; r < 4; r++) {
            int row = lrow + r * 16;
            *reinterpret_cast<float4*>(&Bs[row][lcol]) =
                *reinterpret_cast<const float4*>(F + (size_t)(cb + row) * LZ + t0 + lcol);
        }
        __syncthreads();
#pragma unroll
        for (int kk = 0; kk < 32; kk += 8) {
            uint32_t a[2][4], bfr[4][2];
#pragma unroll
            for (int mi = 0; mi < 2; mi++) {
                int r = m0 + mi * 16 + g;
                a[mi][0] = to_tf32(As[r][kk + tg]);
                a[mi][1] = to_tf32(As[r + 8][kk + tg]);
                a[mi][2] = to_tf32(As[r][kk + tg + 4]);
                a[mi][3] = to_tf32(As[r + 8][kk + tg + 4]);
            }
#pragma unroll
            for (int ni = 0; ni < 4; ni++) {
                int c = n0 + ni * 8 + g;
                bfr[ni][0] = to_tf32(Bs[c][kk + tg]);
                bfr[ni][1] = to_tf32(Bs[c][kk + tg + 4]);
            }
#pragma unroll
            for (int mi = 0; mi < 2; mi++)
#pragma unroll
                for (int ni = 0; ni < 4; ni++)
                    mma_tf32(acc[mi][ni], a[mi], bfr[ni]);
        }
        __syncthreads();
    }
#pragma unroll
    for (int mi = 0; mi < 2; mi++) {
        int r0 = m0 + mi * 16 + g;
#pragma unroll
        for (int ni = 0; ni < 4; ni++) {
            int col = cb + n0 + ni * 8 + 2 * tg;
#pragma unroll
            for (int half = 0; half < 2; half++) {
                int row = r0 + half * 8;
                atomicAdd(&X[(size_t)(b * 64 + row) * M2 + col], acc[mi][ni][half * 2 + 0]);
                atomicAdd(&X[(size_t)(b * 64 + row) * M2 + col + 1], acc[mi][ni][half * 2 + 1]);
            }
        }
    }
}

__global__ __launch_bounds__(128) void gemm_dft(const float* __restrict__ Aq,
                                                const float* __restrict__ F,
                                                float* __restrict__ X) {
    dft_body(Aq, F, X, blockIdx.x, blockIdx.y * 64, blockIdx.z);
}

__global__ __launch_bounds__(128) void gemm_dft2(const float* __restrict__ Aq1,
                                                 float* __restrict__ X1,
                                                 const float* __restrict__ Aq2,
                                                 float* __restrict__ X2,
                                                 const float* __restrict__ F) {
    int z = blockIdx.z;
    if (z < 4) dft_body(Aq1, F, X1, blockIdx.x, blockIdx.y * 64, z);
    else       dft_body(Aq2, F, X2, blockIdx.x, blockIdx.y * 64, z - 4);
}

// ------------------------------------------------------------------ mode-space projection (cross path)
__global__ __launch_bounds__(256) void modeproj_kernel(const float* __restrict__ Hf,
                                                       const float* __restrict__ Wq,
                                                       const float* __restrict__ bq,
                                                       const float* __restrict__ cm,
                                                       float* __restrict__ Qf) {
    __shared__ float Hs[64][68];
    __shared__ float Ws[64][68];
    int b = blockIdx.x;
    int mh = blockIdx.y;
    int tid = threadIdx.x;
    for (int i = tid; i < 64 * 16; i += 256) {
        int d = i >> 4;
        int c4 = (i & 15) * 4;
        *reinterpret_cast<float4*>(&Hs[d][c4]) =
            *reinterpret_cast<const float4*>(Hf + ((size_t)(b * 64 + d)) * M2 + mh * 64 + c4);
    }
    for (int i = tid; i < 64 * 16; i += 256) {
        int he = i >> 4;
        int c4 = (i & 15) * 4;
        *reinterpret_cast<float4*>(&Ws[he][c4]) =
            *reinterpret_cast<const float4*>(Wq + he * 64 + c4);
    }
    __syncthreads();
    if (cm && mh == 0 && tid < 64) Hs[tid][0] -= cm[b * 64 + tid] * 1024.f;
    __syncthreads();
    int he = tid >> 2;
    int mg = tid & 3;
#pragma unroll
    for (int j = 0; j < 16; j++) {
        int ml = mg + 4 * j;
        float s = 0.f;
#pragma unroll
        for (int d = 0; d < 64; d++) s += Ws[he][d] * Hs[d][ml];
        int m2 = mh * 64 + ml;
        if (m2 == 0) s += bq[he] * 1024.f;
        Qf[((size_t)(b * 64 + he)) * M2 + m2] = s;
    }
}

// ------------------------------------------------------------------ fused modeproj + mode_mix (self-attn)
#define MPM_SMEM ((2*64*68 + 64*66) * 4)
__global__ __launch_bounds__(256) void modeproj_mix_kernel(const float* __restrict__ Hf,
                                                           const float* __restrict__ Wq,
                                                           const float* __restrict__ bq,
                                                           const float* __restrict__ wr,
                                                           const float* __restrict__ wi,
                                                           float* __restrict__ sel,
                                                           float scale) {
    extern __shared__ float sm[];
    float* Hs = sm;
    float* Ws = sm + 64 * 68;
    float* Qs = sm + 2 * 64 * 68;
    int b = blockIdx.x;
    int mh = blockIdx.y;
    int tid = threadIdx.x;
    for (int i = tid; i < 64 * 16; i += 256) {
        int d = i >> 4;
        int c4 = (i & 15) * 4;
        *reinterpret_cast<float4*>(&Hs[d * 68 + c4]) =
            *reinterpret_cast<const float4*>(Hf + ((size_t)(b * 64 + d)) * M2 + mh * 64 + c4);
    }
    for (int i = tid; i < 64 * 16; i += 256) {
        int he = i >> 4;
        int c4 = (i & 15) * 4;
        *reinterpret_cast<float4*>(&Ws[he * 68 + c4]) =
            *reinterpret_cast<const float4*>(Wq + he * 64 + c4);
    }
    __syncthreads();
    {
        int he = tid >> 2;
        int mg = tid & 3;
#pragma unroll
        for (int j = 0; j < 16; j++) {
            int ml = mg + 4 * j;
            float s = 0.f;
#pragma unroll
            for (int d = 0; d < 64; d++) s += Ws[he * 68 + d] * Hs[d * 68 + ml];
            if (mh == 0 && ml == 0) s += bq[he] * 1024.f;
            Qs[he * 66 + ml] = s;
        }
    }
    __syncthreads();
    {
        int lm = tid & 31;
        int hob = tid >> 5;
        int m = mh * 32 + lm;
#pragma unroll
        for (int j = 0; j < 8; j++) {
            int ho = hob * 8 + j;
            int h = ho >> 3, o = ho & 7;
            float ar = 0.f, ai = 0.f;
#pragma unroll
            for (int e = 0; e < 8; e++) {
                float xr = Qs[(h * 8 + e) * 66 + 2 * lm];
                float xi = Qs[(h * 8 + e) * 66 + 2 * lm + 1];
                int wix = ((h * 8 + e) * 8 + o) * MZ + m;
                float wrv = wr[wix], wiv = wi[wix];
                ar += xr * wrv - xi * wiv;
                ai += xr * wiv + xi * wrv;
            }
            size_t ro = ((size_t)(b * 64 + h * 8 + o)) * M2 + 2 * m;
            sel[ro] = ar * scale;
            sel[ro + 1] = ai * scale;
        }
    }
}

// ------------------------------------------------------------------ fused cross attention
__global__ __launch_bounds__(256) void qkattn_kernel(const float* __restrict__ Qf,
                                                     const float* __restrict__ Kf,
                                                     const float* __restrict__ wr,
                                                     const float* __restrict__ wi,
                                                     float* __restrict__ sel,
                                                     float scale) {
    __shared__ float Qs[8][128];
    __shared__ float Ks[8][128];
    __shared__ float qks[64][130];
    __shared__ float Vs[8][128];
    int bh = blockIdx.x;
    int h = bh & 7, b = bh >> 3;
    int tid = threadIdx.x;
    size_t tbase = (size_t)(b * 64 + h * 8) * M2;
#pragma unroll
    for (int i = 0; i < 4; i++) {
        int f = i * 256 + tid;
        int e = f >> 7, c = f & 127;
        Qs[e][c] = Qf[tbase + e * M2 + c];
        Ks[e][c] = Kf[tbase + e * M2 + c];
    }
    __syncthreads();
    {
        int x = tid >> 2;
        int ys = tid & 3;
#pragma unroll
        for (int j = 0; j < 16; j++) {
            int y = ys * 16 + j;
            float ar = 0.f, ai = 0.f;
#pragma unroll
            for (int e = 0; e < 8; e++) {
                float qr = Qs[e][2 * x], qi = Qs[e][2 * x + 1];
                float kr = Ks[e][2 * y], ki = Ks[e][2 * y + 1];
                ar += qr * kr - qi * ki;
                ai += qr * ki + qi * kr;
            }
            float a2 = 2.f * ar, b2 = 2.f * ai;
            float tr, ti;
            if (fabsf(a2) > 30.f) {
                tr = copysignf(1.f, ar);
                ti = 0.f;
            } else {
                float sn, cs;
                sincosf(b2, &sn, &cs);
                float ex = expf(a2);
                float exi = 1.f / ex;
                float den = 0.5f * (ex + exi) + cs;
                tr = 0.5f * (ex - exi) / den;
                ti = sn / den;
            }
            qks[x][2 * y] = tr;
            qks[x][2 * y + 1] = ti;
        }
    }
    __syncthreads();
    {
        int flat0 = tid * 2;
#pragma unroll
        for (int u = 0; u < 2; u++) {
            int flat = flat0 + u;
            int e = flat >> 6, x = flat & 63;
            float ar = 0.f, ai = 0.f;
#pragma unroll 16
            for (int y = 0; y < 64; y++) {
                float qr = qks[x][2 * y], qi = qks[x][2 * y + 1];
                float kr = Ks[e][2 * y], ki = Ks[e][2 * y + 1];
                ar += qr * kr - qi * ki;
                ai += qr * ki + qi * kr;
            }
            Vs[e][2 * x] = ar;
            Vs[e][2 * x + 1] = ai;
        }
    }
    __syncthreads();
    {
        int m = tid & 63;
        int og = tid >> 6;
#pragma unroll
        for (int j = 0; j < 2; j++) {
            int o = og * 2 + j;
            float ar = 0.f, ai = 0.f;
#pragma unroll
            for (int e = 0; e < 8; e++) {
                float xr = Vs[e][2 * m], xi = Vs[e][2 * m + 1];
                int wix = ((h * 8 + e) * 8 + o) * MZ + m;
                float wrv = wr[wix], wiv = wi[wix];
                ar += xr * wrv - xi * wiv;
                ai += xr * wiv + xi * wrv;
            }
            size_t ro = ((size_t)(b * 64 + h * 8 + o)) * M2 + 2 * m;
            sel[ro] = ar * scale;
            sel[ro + 1] = ai * scale;
        }
    }
}

// ------------------------------------------------------------------ layernorm family
__global__ void ln_row_kernel(const float* __restrict__ X, const float* __restrict__ g,
                              const float* __restrict__ be, float* __restrict__ out) {
    __shared__ float red[256];
    int tid = threadIdx.x;
    int sub = tid >> 6;
    int d = tid & 63;
    int row = blockIdx.x * 4 + sub;
    float v = X[(size_t)row * DZ + d];
    red[tid] = v;
    __syncthreads();
    for (int s = 32; s > 0; s >>= 1) {
        if (d < s) red[tid] += red[tid + s];
        __syncthreads();
    }
    float mu = red[sub * 64] * (1.f / 64.f);
    __syncthreads();
    float dv = v - mu;
    red[tid] = dv * dv;
    __syncthreads();
    for (int s = 32; s > 0; s >>= 1) {
        if (d < s) red[tid] += red[tid + s];
        __syncthreads();
    }
    float var = red[sub * 64] * (1.f / 64.f);
    out[(size_t)row * DZ + d] = dv * rsqrtf(var + 1e-5f) * g[d] + be[d];
}

__global__ void colmean_kernel(const float* __restrict__ X, float* __restrict__ cm) {
    __shared__ float r[256];
    int b = blockIdx.x / DZ, d = blockIdx.x % DZ;
    float s = 0.f;
    for (int t = threadIdx.x; t < LZ; t += 256) s += X[((size_t)(b * LZ + t)) * DZ + d];
    r[threadIdx.x] = s;
    __syncthreads();
    for (int o = 128; o > 0; o >>= 1) {
        if (threadIdx.x < o) r[threadIdx.x] += r[threadIdx.x + o];
        __syncthreads();
    }
    if (threadIdx.x == 0) cm[b * DZ + d] = r[0] * (1.f / LZ);
}

// ------------------------------------------------------------------ final epilogue
__global__ void final_kernel(const float* __restrict__ xln, const float* __restrict__ cm,
                             const float* __restrict__ tacc,
                             const float* __restrict__ tbase, const float* __restrict__ tw,
                             const float* __restrict__ pw, const float* __restrict__ pb,
                             float* __restrict__ out) {
    int idx = blockIdx.x * blockDim.x + threadIdx.x;
    if (idx >= BZ * 512) return;
    int t = idx & 511, b = idx >> 9;
    int tt = t + 512;
    float cv = 0.f;
#pragma unroll
    for (int j = 0; j < 3; j++) {
        int ts = (tt + j - 1) & (LZ - 1);
        const float* row = tacc + ((size_t)(b * LZ + ts)) * DZ;
#pragma unroll 4
        for (int d4 = 0; d4 < 16; d4++) {
            float4 rv = *reinterpret_cast<const float4*>(row + d4 * 4);
            cv += rv.x * tw[(d4 * 4 + 0) * 3 + j] + rv.y * tw[(d4 * 4 + 1) * 3 + j]
                + rv.z * tw[(d4 * 4 + 2) * 3 + j] + rv.w * tw[(d4 * 4 + 3) * 3 + j];
        }
    }
    float p = pb[0];
    const float* xr = xln + ((size_t)(b * LZ + tt)) * DZ;
    const float* cmr = cm + b * DZ;
#pragma unroll 4
    for (int d4 = 0; d4 < 16; d4++) {
        float4 xv = *reinterpret_cast<const float4*>(xr + d4 * 4);
        float4 cvv = *reinterpret_cast<const float4*>(cmr + d4 * 4);
        float4 pv = *reinterpret_cast<const float4*>(pw + d4 * 4);
        p += (xv.x - cvv.x) * pv.x + (xv.y - cvv.y) * pv.y
           + (xv.z - cvv.z) * pv.z + (xv.w - cvv.w) * pv.w;
    }
    out[idx] = p + cv + tbase[b * LZ + tt];
}

static float* symaddr_f(const void* sym) {
    void* p = nullptr;
    cudaGetSymbolAddress(&p, sym);
    return (float*)p;
}

extern "C" void kernel_launch(void* const* d_in, const int* in_sizes, int n_in,
                              void* d_out, int out_size) {
    const float* x_enc       = (const float*)d_in[0];
    const float* dp_w        = (const float*)d_in[1];
    const float* dp_b        = (const float*)d_in[2];
    const float* emb_enc_w   = (const float*)d_in[3];
    const float* emb_dec_w   = (const float*)d_in[4];
    const float* decomp_w    = (const float*)d_in[5];
    const float* decomp_b    = (const float*)d_in[6];
    const float* enc_attn_w  = (const float*)d_in[7];
    const float* enc_attn_b  = (const float*)d_in[8];
    const float* enc_four_wr = (const float*)d_in[9];
    const float* enc_four_wi = (const float*)d_in[10];
    const float* enc_c1      = (const float*)d_in[11];
    const float* enc_c2      = (const float*)d_in[12];
    const float* enc_ln_g    = (const float*)d_in[13];
    const float* enc_ln_b    = (const float*)d_in[14];
    const float* dec_self_w  = (const float*)d_in[15];
    const float* dec_self_b  = (const float*)d_in[16];
    const float* dec_four_wr = (const float*)d_in[17];
    const float* dec_four_wi = (const float*)d_in[18];
    const float* dec_cross_w = (const float*)d_in[19];
    const float* dec_cross_b = (const float*)d_in[20];
    const float* dec_cross_wr= (const float*)d_in[21];
    const float* dec_cross_wi= (const float*)d_in[22];
    const float* dec_c1      = (const float*)d_in[23];
    const float* dec_c2      = (const float*)d_in[24];
    const float* dec_trend_w = (const float*)d_in[25];
    const float* dec_ln_g    = (const float*)d_in[26];
    const float* dec_ln_b    = (const float*)d_in[27];
    const float* dec_proj_w  = (const float*)d_in[28];
    const float* dec_proj_b  = (const float*)d_in[29];
    float* out = (float*)d_out;

    float* px        = symaddr_f(g_x);
    float* pseas0    = symaddr_f(g_seas0);
    float* ptrend0   = symaddr_f(g_trend0);
    float* pseasinit = symaddr_f(g_seasinit);
    float* ph        = symaddr_f(g_h);
    float* py        = symaddr_f(g_y);
    float* pa        = symaddr_f(g_a);
    float* py2       = symaddr_f(g_y2);
    float* pa2       = symaddr_f(g_a2);
    float* pHf       = symaddr_f(g_Hf);
    float* pHf2      = pHf + (size_t)NHE * M2;
    float* pXf       = symaddr_f(g_Xf);
    float* pXk       = symaddr_f(g_Xk);
    float* psel      = symaddr_f(g_sel);
    float* psel2     = symaddr_f(g_sel2);
    float* pxd       = symaddr_f(g_xd);
    float* ptacc     = symaddr_f(g_tacc);
    float* pcm       = symaddr_f(g_cm);
    float* pcm2      = symaddr_f(g_cm2);
    float* pln       = symaddr_f(g_ln);
    float* pF        = symaddr_f(g_F);
    float* pFi       = symaddr_f(g_Fi);
    float* ptbase    = symaddr_f(g_trendbase);

    cudaFuncSetAttribute(gemm_tc<0>, cudaFuncAttributeMaxDynamicSharedMemorySize, GT_SMEM);
    cudaFuncSetAttribute(gemm_ffn, cudaFuncAttributeMaxDynamicSharedMemorySize, FFN_SMEM);
    cudaFuncSetAttribute(modeproj_mix_kernel, cudaFuncAttributeMaxDynamicSharedMemorySize, MPM_SMEM);

    static cudaStream_t s2 = nullptr;
    static cudaEvent_t evFork = nullptr, evJoin = nullptr;
    if (!s2) {
        cudaStreamCreateWithFlags(&s2, cudaStreamNonBlocking);
        cudaEventCreateWithFlags(&evFork, cudaEventDisableTiming);
        cudaEventCreateWithFlags(&evJoin, cudaEventDisableTiming);
    }

    dim3 dftg(BZ, 2, 4);
    dim3 dftg2(BZ, 2, 8);
    dim3 mpg(BZ, 2);

    // ---- shared prep (stream 0) ----
    build_tables_kernel<<<512, 256>>>();
    transpose_in_kernel<<<1792, 256>>>(x_enc);
    colmean7_kernel<<<BZ * C7, 256>>>(x_enc);
    decomp7_kernel<<<BZ * C7, LZ>>>(px, decomp_w + 0, decomp_b + 0, pseas0, ptrend0);
    trendbase_kernel<<<256, 256>>>(dp_w, dp_b);
    seasinit_kernel<<<1792, 256>>>();
    cudaEventRecord(evFork, 0);

    // ---- decoder prefix (stream s2) ----
    cudaStreamWaitEvent(s2, evFork, 0);
    embed_kernel<<<16384, 256, 0, s2>>>(pseasinit, emb_dec_w, pxd);
    cudaMemsetAsync(pHf2, 0, (size_t)NHE * M2 * sizeof(float), s2);
    gemm_dft<<<dftg, 128, 0, s2>>>(pxd, pF, pHf2);
    modeproj_mix_kernel<<<mpg, 256, MPM_SMEM, s2>>>(pHf2, dec_self_w + 0, dec_self_b + 0,
                                                    dec_four_wr, dec_four_wi, psel2, 1.0f);
    gemm_tc<0><<<dim3(32, 16), 128, GT_SMEM, s2>>>(psel2, pFi, nullptr, py2, NHE, 128, 1024);
    gemm_tc<0><<<dim3(512, 1), 128, GT_SMEM, s2>>>(py2, dec_self_w + 3 * 4096,
                                                   dec_self_b + 3 * 64, pa2, NROW, 64, 64);
    decomp64_kernel<<<1024, 256, 0, s2>>>(pxd, pa2, decomp_w + 5 * 4, decomp_b + 5 * 4,
                                          pxd, ptacc, 0);
    cudaEventRecord(evJoin, s2);

    // ---- encoder (stream 0) ----
    embed_kernel<<<16384, 256>>>(px, emb_enc_w, ph);
    for (int l = 0; l < 2; l++) {
        const float* wq = enc_attn_w + (size_t)(l * 4 + 0) * 4096;
        const float* bq = enc_attn_b + (size_t)(l * 4 + 0) * 64;
        const float* wo = enc_attn_w + (size_t)(l * 4 + 3) * 4096;
        const float* bo = enc_attn_b + (size_t)(l * 4 + 3) * 64;
        cudaMemsetAsync(pHf, 0, (size_t)NHE * M2 * sizeof(float));
        gemm_dft<<<dftg, 128>>>(ph, pF, pHf);
        modeproj_mix_kernel<<<mpg, 256, MPM_SMEM>>>(pHf, wq, bq,
                                                    enc_four_wr + (size_t)l * 32768,
                                                    enc_four_wi + (size_t)l * 32768, psel, 1.0f);
        gemm_tc<0><<<dim3(32, 16), 128, GT_SMEM>>>(psel, pFi, nullptr, py, NHE, 128, 1024);
        gemm_tc<0><<<dim3(512, 1), 128, GT_SMEM>>>(py, wo, bo, pa, NROW, 64, 64);
        decomp64_kernel<<<1024, 256>>>(ph, pa, decomp_w + (1 + 2 * l) * 4,
                                       decomp_b + (1 + 2 * l) * 4, ph, nullptr, 0);
        gemm_ffn<<<512, 128, FFN_SMEM>>>(ph, enc_c1 + (size_t)l * 16384,
                                         enc_c2 + (size_t)l * 16384, py);
        decomp64_kernel<<<1024, 256>>>(ph, py, decomp_w + (2 + 2 * l) * 4,
                                       decomp_b + (2 + 2 * l) * 4, ph, nullptr, 0);
    }
    ln_row_kernel<<<16384, 256>>>(ph, enc_ln_g, enc_ln_b, ph);
    colmean_kernel<<<BZ * DZ, 256>>>(ph, pcm2);

    // ---- join, then cross attention ----
    cudaStreamWaitEvent(0, evJoin, 0);
    cudaMemsetAsync(pHf, 0, (size_t)2 * NHE * M2 * sizeof(float));
    gemm_dft2<<<dftg2, 128>>>(pxd, pHf, ph, pHf2, pF);
    modeproj_kernel<<<mpg, 256>>>(pHf, dec_cross_w + 0, dec_cross_b + 0, nullptr, pXf);
    modeproj_kernel<<<mpg, 256>>>(pHf2, dec_cross_w + 1 * 4096, dec_cross_b + 1 * 64, pcm2, pXk);
    qkattn_kernel<<<512, 256>>>(pXf, pXk, dec_cross_wr, dec_cross_wi, psel, 1.0f / 4096.0f);
    gemm_tc<0><<<dim3(32, 16), 128, GT_SMEM>>>(psel, pFi, nullptr, py, NHE, 128, 1024);
    gemm_tc<0><<<dim3(512, 1), 128, GT_SMEM>>>(py, dec_cross_w + 3 * 4096, dec_cross_b + 3 * 64, pa,
                                               NROW, 64, 64);
    decomp64_kernel<<<1024, 256>>>(pxd, pa, decomp_w + 6 * 4, decomp_b + 6 * 4, pxd, ptacc, 1);

    gemm_ffn<<<512, 128, FFN_SMEM>>>(pxd, dec_c1, dec_c2, py);
    decomp64_kernel<<<1024, 256>>>(pxd, py, decomp_w + 7 * 4, decomp_b + 7 * 4, pxd, ptacc, 1);

    ln_row_kernel<<<16384, 256>>>(pxd, dec_ln_g, dec_ln_b, pln);
    colmean_kernel<<<BZ * DZ, 256>>>(pln, pcm);
    final_kernel<<<128, 256>>>(pln, pcm, ptacc, ptbase, dec_trend_w, dec_proj_w, dec_proj_b, out);
}

// round 14
// speedup vs baseline: 1.0498x; 1.0149x over previous
#include <cuda_runtime.h>
#include <cstdint>

#define BZ 64
#define LZ 1024
#define DZ 64
#define C7 7
#define HZ 8
#define EZ 8
#define MZ 64
#define M2 128
#define DFFD 256
#define NROW (BZ*LZ)
#define NHE  (BZ*DZ)

__device__ float g_x[BZ*LZ*C7];
__device__ float g_seas0[BZ*LZ*C7];
__device__ float g_trend0[BZ*LZ*C7];
__device__ float g_mean7[BZ*C7];
__device__ float g_trendbase[BZ*LZ];
__device__ float g_seasinit[BZ*LZ*C7];
__device__ float g_h[NROW*DZ];
__device__ float g_y[NROW*DZ];
__device__ float g_a[NROW*DZ];
__device__ float g_y2[NROW*DZ];
__device__ float g_a2[NROW*DZ];
__device__ float g_Hf[2*NHE*M2];
__device__ float g_Hq[NHE*M2];
__device__ float g_Xf[NHE*M2];
__device__ float g_Xk[NHE*M2];
__device__ float g_sel[NHE*M2];
__device__ float g_sel2[NHE*M2];
__device__ float g_xd[NROW*DZ];
__device__ float g_tacc[NROW*DZ];
__device__ float g_cm[BZ*DZ];
__device__ float g_cm2[BZ*DZ];
__device__ float g_ln[NROW*DZ];
__device__ float g_F[M2*LZ];
__device__ float g_Fi[LZ*M2];
__device__ float g_pe[LZ*DZ];

// ------------------------------------------------------------------ tables
__global__ void build_tables_kernel() {
    int idx = blockIdx.x * blockDim.x + threadIdx.x;
    if (idx < LZ * M2) {
        int t = idx >> 7;
        int m2 = idx & 127;
        int m = m2 >> 1;
        int r = (m * t) & (LZ - 1);
        float a = (float)r * (6.28318530717958647692f / (float)LZ);
        float s, c;
        sincosf(a, &s, &c);
        float v = (m2 & 1) ? -s : c;
        g_F[(size_t)m2 * LZ + t] = v;
        float cm = (m == 0) ? 1.f : 2.f;
        g_Fi[(size_t)t * M2 + m2] = v * (cm / (float)LZ);
    }
    if (idx < LZ * DZ) {
        int o = idx & 63;
        int t = idx >> 6;
        int i2 = o & ~1;
        float div = expf(-(float)i2 * 0.14391156831212793f);
        float arg = (float)t * div;
        g_pe[idx] = (o & 1) ? cosf(arg) : sinf(arg);
    }
}

// ------------------------------------------------------------------ input prep
__global__ void transpose_in_kernel(const float* __restrict__ xe) {
    int idx = blockIdx.x * blockDim.x + threadIdx.x;
    if (idx >= BZ * C7 * LZ) return;
    int t = idx & 1023;
    int c = (idx >> 10) % C7;
    int b = idx / (C7 * LZ);
    g_x[((size_t)(b * LZ + t)) * C7 + c] = xe[idx];
}

__global__ void colmean7_kernel(const float* __restrict__ xe) {
    __shared__ float r[256];
    int bc = blockIdx.x;
    float s = 0.f;
    for (int t = threadIdx.x; t < LZ; t += 256) s += xe[(size_t)bc * LZ + t];
    r[threadIdx.x] = s;
    __syncthreads();
    for (int o = 128; o > 0; o >>= 1) {
        if (threadIdx.x < o) r[threadIdx.x] += r[threadIdx.x + o];
        __syncthreads();
    }
    if (threadIdx.x == 0) g_mean7[bc] = r[0] * (1.f / LZ);
}

// ------------------------------------------------------------------ decomp7
__global__ void decomp7_kernel(const float* __restrict__ A,
                               const float* __restrict__ w4, const float* __restrict__ b4,
                               float* __restrict__ seas, float* __restrict__ trend) {
    __shared__ float ps[LZ];
    __shared__ float wsum[32];
    __shared__ float sx0, sxN;
    int c = blockIdx.x % C7, b = blockIdx.x / C7;
    int t = threadIdx.x, lane = t & 31, wid = t >> 5;
    size_t idx = ((size_t)(b * LZ + t)) * C7 + c;
    float x = A[idx];
    float s = x;
#pragma unroll
    for (int off = 1; off < 32; off <<= 1) {
        float v = __shfl_up_sync(0xffffffffu, s, off);
        if (lane >= off) s += v;
    }
    if (lane == 31) wsum[wid] = s;
    if (t == 0) sx0 = x;
    if (t == LZ - 1) sxN = x;
    __syncthreads();
    if (wid == 0) {
        float v = wsum[lane];
#pragma unroll
        for (int off = 1; off < 32; off <<= 1) {
            float u = __shfl_up_sync(0xffffffffu, v, off);
            if (lane >= off) v += u;
        }
        wsum[lane] = v;
    }
    __syncthreads();
    if (wid > 0) s += wsum[wid - 1];
    ps[t] = s;
    __syncthreads();
    float x0 = sx0, xN = sxN;
    const int ks[4] = {10, 50, 100, 500};
    float ma[4];
#pragma unroll
    for (int kk = 0; kk < 4; kk++) {
        int k = ks[kk], f = (k - 1) >> 1, e = k >> 1;
        int lo = t - f, hi = t + e;
        int cl = lo < 0 ? 0 : lo, ch = hi > LZ - 1 ? LZ - 1 : hi;
        float sw = ps[ch] - (cl > 0 ? ps[cl - 1] : 0.f)
                 + (float)(cl - lo) * x0 + (float)(hi - ch) * xN;
        ma[kk] = sw / (float)k;
    }
    float z[4], mx = -1e30f;
#pragma unroll
    for (int kk = 0; kk < 4; kk++) { z[kk] = x * w4[kk] + b4[kk]; mx = fmaxf(mx, z[kk]); }
    float se = 0.f, mean = 0.f;
#pragma unroll
    for (int kk = 0; kk < 4; kk++) { float e2 = expf(z[kk] - mx); se += e2; mean += ma[kk] * e2; }
    mean /= se;
    seas[idx] = x - mean;
    trend[idx] = mean;
}

__device__ __forceinline__ float4 f4add(float4 a, float4 b) {
    return make_float4(a.x + b.x, a.y + b.y, a.z + b.z, a.w + b.w);
}

// ------------------------------------------------------------------ decomp64
__global__ __launch_bounds__(256) void decomp64_kernel(
    const float* __restrict__ A, const float* __restrict__ Bb,
    const float* __restrict__ w4, const float* __restrict__ b4,
    float* __restrict__ seas, float* __restrict__ trend, int accum) {
    __shared__ float4 ps[LZ];
    __shared__ float4 wsum[8];
    __shared__ float4 sedge[2];
    int c4 = blockIdx.x & 15, b = blockIdx.x >> 4;
    int tid = threadIdx.x, lane = tid & 31, wid = tid >> 5;
    int t4 = tid * 4;
    size_t base = ((size_t)(b * LZ + t4)) * DZ + c4 * 4;

    float4 x[4], p[4];
#pragma unroll
    for (int j = 0; j < 4; j++) {
        x[j] = *reinterpret_cast<const float4*>(A + base + (size_t)j * DZ);
        if (Bb) x[j] = f4add(x[j], *reinterpret_cast<const float4*>(Bb + base + (size_t)j * DZ));
    }
    p[0] = x[0];
#pragma unroll
    for (int j = 1; j < 4; j++) p[j] = f4add(p[j - 1], x[j]);

    float4 s = p[3];
#pragma unroll
    for (int off = 1; off < 32; off <<= 1) {
        float4 v;
        v.x = __shfl_up_sync(0xffffffffu, s.x, off);
        v.y = __shfl_up_sync(0xffffffffu, s.y, off);
        v.z = __shfl_up_sync(0xffffffffu, s.z, off);
        v.w = __shfl_up_sync(0xffffffffu, s.w, off);
        if (lane >= off) s = f4add(s, v);
    }
    if (lane == 31) wsum[wid] = s;
    if (tid == 0) sedge[0] = x[0];
    if (tid == 255) sedge[1] = x[3];
    __syncthreads();
    if (wid == 0 && lane < 8) {
        float4 v = wsum[lane];
#pragma unroll
        for (int off = 1; off < 8; off <<= 1) {
            float4 u;
            u.x = __shfl_up_sync(0xffu, v.x, off);
            u.y = __shfl_up_sync(0xffu, v.y, off);
            u.z = __shfl_up_sync(0xffu, v.z, off);
            u.w = __shfl_up_sync(0xffu, v.w, off);
            if (lane >= off) v = f4add(v, u);
        }
        wsum[lane] = v;
    }
    __syncthreads();
    float4 ex = make_float4(0.f, 0.f, 0.f, 0.f);
    if (wid > 0) ex = wsum[wid - 1];
    {
        float4 d;
        d.x = s.x - p[3].x; d.y = s.y - p[3].y; d.z = s.z - p[3].z; d.w = s.w - p[3].w;
        ex = f4add(ex, d);
    }
#pragma unroll
    for (int j = 0; j < 4; j++) ps[t4 + j] = f4add(ex, p[j]);
    __syncthreads();

    float4 x0 = sedge[0], xN = sedge[1];
    const int ks[4] = {10, 50, 100, 500};
#pragma unroll
    for (int j = 0; j < 4; j++) {
        int t = t4 + j;
        float ma[4][4];
#pragma unroll
        for (int kk = 0; kk < 4; kk++) {
            int k = ks[kk], f = (k - 1) >> 1, e = k >> 1;
            int lo = t - f, hi = t + e;
            int cl = lo < 0 ? 0 : lo, ch = hi > LZ - 1 ? LZ - 1 : hi;
            float4 pc = ps[ch];
            float4 pl = make_float4(0.f, 0.f, 0.f, 0.f);
            if (cl > 0) pl = ps[cl - 1];
            float fl = (float)(cl - lo), fr = (float)(hi - ch);
            float inv = 1.f / (float)k;
            ma[kk][0] = (pc.x - pl.x + fl * x0.x + fr * xN.x) * inv;
            ma[kk][1] = (pc.y - pl.y + fl * x0.y + fr * xN.y) * inv;
            ma[kk][2] = (pc.z - pl.z + fl * x0.z + fr * xN.z) * inv;
            ma[kk][3] = (pc.w - pl.w + fl * x0.w + fr * xN.w) * inv;
        }
        float xa[4] = {x[j].x, x[j].y, x[j].z, x[j].w};
        float so[4], tr[4];
#pragma unroll
        for (int cc = 0; cc < 4; cc++) {
            float z[4], mx = -1e30f;
#pragma unroll
            for (int kk = 0; kk < 4; kk++) { z[kk] = xa[cc] * w4[kk] + b4[kk]; mx = fmaxf(mx, z[kk]); }
            float se = 0.f, mean = 0.f;
#pragma unroll
            for (int kk = 0; kk < 4; kk++) { float e2 = expf(z[kk] - mx); se += e2; mean += ma[kk][cc] * e2; }
            mean /= se;
            so[cc] = xa[cc] - mean;
            tr[cc] = mean;
        }
        *reinterpret_cast<float4*>(seas + base + (size_t)j * DZ) =
            make_float4(so[0], so[1], so[2], so[3]);
        if (trend) {
            float4 tv = make_float4(tr[0], tr[1], tr[2], tr[3]);
            if (accum) {
                float4 old = *reinterpret_cast<float4*>(trend + base + (size_t)j * DZ);
                tv = f4add(tv, old);
            }
            *reinterpret_cast<float4*>(trend + base + (size_t)j * DZ) = tv;
        }
    }
}

// ------------------------------------------------------------------ trend/seasonal init
__global__ void trendbase_kernel(const float* __restrict__ dpw, const float* __restrict__ dpb) {
    int idx = blockIdx.x * blockDim.x + threadIdx.x;
    if (idx >= BZ * LZ) return;
    int t = idx & 1023, b = idx >> 10;
    float s = dpb[0];
#pragma unroll
    for (int c = 0; c < C7; c++) {
        float v = (t < 512) ? g_trend0[((size_t)(b * LZ + 512 + t)) * C7 + c]
                            : g_mean7[b * C7 + c];
        s += v * dpw[c];
    }
    g_trendbase[idx] = s;
}

__global__ void seasinit_kernel() {
    int idx = blockIdx.x * blockDim.x + threadIdx.x;
    if (idx >= BZ * LZ * C7) return;
    int c = idx % C7;
    int t = (idx / C7) & 1023;
    int b = idx / (C7 * LZ);
    g_seasinit[idx] = (t < 512) ? g_seas0[((size_t)(b * LZ + 512 + t)) * C7 + c] : 0.f;
}

// ------------------------------------------------------------------ embedding
__global__ void embed_kernel(const float* __restrict__ in, const float* __restrict__ w,
                             float* __restrict__ out) {
    int idx = blockIdx.x * blockDim.x + threadIdx.x;
    if (idx >= BZ * LZ * DZ) return;
    int o = idx & 63;
    int t = (idx >> 6) & 1023;
    int b = idx >> 16;
    float s = 0.f;
#pragma unroll
    for (int j = 0; j < 3; j++) {
        int ts = (t + j - 1 + LZ) & (LZ - 1);
        const float* ip = in + ((size_t)(b * LZ + ts)) * C7;
#pragma unroll
        for (int c = 0; c < C7; c++) s += ip[c] * w[(o * C7 + c) * 3 + j];
    }
    out[idx] = s + g_pe[(t << 6) + o];
}

// ------------------------------------------------------------------ tf32 helpers
__device__ __forceinline__ uint32_t to_tf32(float x) {
    uint32_t r;
    asm("cvt.rna.tf32.f32 %0, %1;" : "=r"(r) : "f"(x));
    return r;
}
__device__ __forceinline__ void cpa16(uint32_t s, const float* g) {
    asm volatile("cp.async.ca.shared.global [%0], [%1], 16;" :: "r"(s), "l"(g));
}
__device__ __forceinline__ void cpa_commit() {
    asm volatile("cp.async.commit_group;");
}
__device__ __forceinline__ void cpa_wait1() {
    asm volatile("cp.async.wait_group 1;");
}
__device__ __forceinline__ void mma_tf32(float* acc, const uint32_t* a, const uint32_t* bf) {
    asm volatile(
        "mma.sync.aligned.m16n8k8.row.col.f32.tf32.tf32.f32 "
        "{%0,%1,%2,%3}, {%4,%5,%6,%7}, {%8,%9}, {%0,%1,%2,%3};"
        : "+f"(acc[0]), "+f"(acc[1]), "+f"(acc[2]), "+f"(acc[3])
        : "r"(a[0]), "r"(a[1]), "r"(a[2]), "r"(a[3]), "r"(bf[0]), "r"(bf[1]));
}

// ------------------------------------------------------------------ tf32 GEMM
#define GT_ASTRIDE (128*36)
#define GT_BSTRIDE (64*36)
#define GT_SMEM ((2*GT_ASTRIDE + 2*GT_BSTRIDE) * 4)

template <int ACT>
__global__ __launch_bounds__(128) void gemm_tc(const float* __restrict__ A,
                                               const float* __restrict__ W,
                                               const float* __restrict__ bias,
                                               float* __restrict__ C,
                                               int N, int K, int O) {
    extern __shared__ float dsm[];
    float* As = dsm;
    float* Bs = dsm + 2 * GT_ASTRIDE;
    const int rb = blockIdx.x * 128;
    const int cb = blockIdx.y * 64;
    const int tid = threadIdx.x;
    const int lane = tid & 31;
    const int w = tid >> 5;
    const int wm = w & 1, wn = w >> 1;
    const int m0 = wm * 64, n0 = wn * 32;
    const int g = lane >> 2, tg = lane & 3;
    const int lrow = tid >> 3;
    const int lcol = (tid & 7) * 4;

    uint32_t sA = (uint32_t)__cvta_generic_to_shared(As);
    uint32_t sB = (uint32_t)__cvta_generic_to_shared(Bs);

    float acc[4][4][4];
#pragma unroll
    for (int mi = 0; mi < 4; mi++)
#pragma unroll
        for (int ni = 0; ni < 4; ni++)
#pragma unroll
            for (int r = 0; r < 4; r++) acc[mi][ni][r] = 0.f;

#pragma unroll
    for (int r = 0; r < 8; r++) {
        int row = lrow + r * 16;
        cpa16(sA + (uint32_t)((row * 36 + lcol) * 4), A + (size_t)(rb + row) * K + lcol);
    }
#pragma unroll
    for (int r = 0; r < 4; r++) {
        int row = lrow + r * 16;
        cpa16(sB + (uint32_t)((row * 36 + lcol) * 4), W + (size_t)(cb + row) * K + lcol);
    }
    cpa_commit();

    int st = 0;
    for (int k0 = 0; k0 < K; k0 += 32, st ^= 1) {
        if (k0 + 32 < K) {
            int nx = st ^ 1;
#pragma unroll
            for (int r = 0; r < 8; r++) {
                int row = lrow + r * 16;
                cpa16(sA + (uint32_t)((nx * GT_ASTRIDE + row * 36 + lcol) * 4),
                      A + (size_t)(rb + row) * K + k0 + 32 + lcol);
            }
#pragma unroll
            for (int r = 0; r < 4; r++) {
                int row = lrow + r * 16;
                cpa16(sB + (uint32_t)((nx * GT_BSTRIDE + row * 36 + lcol) * 4),
                      W + (size_t)(cb + row) * K + k0 + 32 + lcol);
            }
        }
        cpa_commit();
        cpa_wait1();
        __syncthreads();
        const float* Ast = As + st * GT_ASTRIDE;
        const float* Bst = Bs + st * GT_BSTRIDE;
#pragma unroll
        for (int kk = 0; kk < 32; kk += 8) {
            uint32_t a[4][4], bfr[4][2];
#pragma unroll
            for (int mi = 0; mi < 4; mi++) {
                int r = m0 + mi * 16 + g;
                a[mi][0] = to_tf32(Ast[r * 36 + kk + tg]);
                a[mi][1] = to_tf32(Ast[(r + 8) * 36 + kk + tg]);
                a[mi][2] = to_tf32(Ast[r * 36 + kk + tg + 4]);
                a[mi][3] = to_tf32(Ast[(r + 8) * 36 + kk + tg + 4]);
            }
#pragma unroll
            for (int ni = 0; ni < 4; ni++) {
                int c = n0 + ni * 8 + g;
                bfr[ni][0] = to_tf32(Bst[c * 36 + kk + tg]);
                bfr[ni][1] = to_tf32(Bst[c * 36 + kk + tg + 4]);
            }
#pragma unroll
            for (int mi = 0; mi < 4; mi++)
#pragma unroll
                for (int ni = 0; ni < 4; ni++)
                    mma_tf32(acc[mi][ni], a[mi], bfr[ni]);
        }
        __syncthreads();
    }
#pragma unroll
    for (int mi = 0; mi < 4; mi++) {
        int row0 = rb + m0 + mi * 16 + g;
#pragma unroll
        for (int ni = 0; ni < 4; ni++) {
            int col = cb + n0 + ni * 8 + 2 * tg;
#pragma unroll
            for (int half = 0; half < 2; half++) {
                int row = row0 + half * 8;
                float v0 = acc[mi][ni][half * 2 + 0];
                float v1 = acc[mi][ni][half * 2 + 1];
                if (bias) { v0 += bias[col]; v1 += bias[col + 1]; }
                if (ACT == 1) {
                    v0 = 0.5f * v0 * (1.f + erff(v0 * 0.70710678118654752f));
                    v1 = 0.5f * v1 * (1.f + erff(v1 * 0.70710678118654752f));
                }
                C[(size_t)row * O + col] = v0;
                C[(size_t)row * O + col + 1] = v1;
            }
        }
    }
}

// ------------------------------------------------------------------ fused FFN
#define FFN_AS  (128*68)
#define FFN_WS  (64*68)
#define FFN_PS  (128*68)
#define FFN_SMEM ((FFN_AS + 2*FFN_WS + FFN_PS) * 4)

__global__ __launch_bounds__(128) void gemm_ffn(const float* __restrict__ A,
                                                const float* __restrict__ W1,
                                                const float* __restrict__ W2,
                                                float* __restrict__ C) {
    extern __shared__ float sm[];
    float* As  = sm;
    float* Ws1 = sm + FFN_AS;
    float* Ws2 = sm + FFN_AS + FFN_WS;
    float* Ps  = sm + FFN_AS + 2 * FFN_WS;
    const int rb = blockIdx.x * 128;
    const int tid = threadIdx.x;
    const int lane = tid & 31;
    const int w = tid >> 5;
    const int wm = w & 1, wn = w >> 1;
    const int m0 = wm * 64, n0 = wn * 32;
    const int g = lane >> 2, tg = lane & 3;

    for (int i = tid; i < 128 * 16; i += 128) {
        int row = i >> 4;
        int c4 = (i & 15) * 4;
        *reinterpret_cast<float4*>(&As[row * 68 + c4]) =
            *reinterpret_cast<const float4*>(A + (size_t)(rb + row) * 64 + c4);
    }

    float acc[4][4][4];
#pragma unroll
    for (int mi = 0; mi < 4; mi++)
#pragma unroll
        for (int ni = 0; ni < 4; ni++)
#pragma unroll
            for (int r = 0; r < 4; r++) acc[mi][ni][r] = 0.f;

    for (int ch = 0; ch < 4; ch++) {
        __syncthreads();
        for (int i = tid; i < 64 * 16; i += 128) {
            int row = i >> 4;
            int c4 = (i & 15) * 4;
            *reinterpret_cast<float4*>(&Ws1[row * 68 + c4]) =
                *reinterpret_cast<const float4*>(W1 + (size_t)(ch * 64 + row) * 64 + c4);
            *reinterpret_cast<float4*>(&Ws2[row * 68 + c4]) =
                *reinterpret_cast<const float4*>(W2 + (size_t)row * 256 + ch * 64 + c4);
        }
        __syncthreads();
        float p1[4][4][4];
#pragma unroll
        for (int mi = 0; mi < 4; mi++)
#pragma unroll
            for (int ni = 0; ni < 4; ni++)
#pragma unroll
                for (int r = 0; r < 4; r++) p1[mi][ni][r] = 0.f;
#pragma unroll
        for (int kk = 0; kk < 64; kk += 8) {
            uint32_t a[4][4], bfr[4][2];
#pragma unroll
            for (int mi = 0; mi < 4; mi++) {
                int r = m0 + mi * 16 + g;
                a[mi][0] = to_tf32(As[r * 68 + kk + tg]);
                a[mi][1] = to_tf32(As[(r + 8) * 68 + kk + tg]);
                a[mi][2] = to_tf32(As[r * 68 + kk + tg + 4]);
                a[mi][3] = to_tf32(As[(r + 8) * 68 + kk + tg + 4]);
            }
#pragma unroll
            for (int ni = 0; ni < 4; ni++) {
                int c = n0 + ni * 8 + g;
                bfr[ni][0] = to_tf32(Ws1[c * 68 + kk + tg]);
                bfr[ni][1] = to_tf32(Ws1[c * 68 + kk + tg + 4]);
            }
#pragma unroll
            for (int mi = 0; mi < 4; mi++)
#pragma unroll
                for (int ni = 0; ni < 4; ni++)
                    mma_tf32(p1[mi][ni], a[mi], bfr[ni]);
        }
#pragma unroll
        for (int mi = 0; mi < 4; mi++) {
            int row0 = m0 + mi * 16 + g;
#pragma unroll
            for (int ni = 0; ni < 4; ni++) {
                int col = n0 + ni * 8 + 2 * tg;
#pragma unroll
                for (int half = 0; half < 2; half++) {
                    int row = row0 + half * 8;
                    float v0 = p1[mi][ni][half * 2 + 0];
                    float v1 = p1[mi][ni][half * 2 + 1];
                    v0 = 0.5f * v0 * (1.f + erff(v0 * 0.70710678118654752f));
                    v1 = 0.5f * v1 * (1.f + erff(v1 * 0.70710678118654752f));
                    Ps[row * 68 + col] = v0;
                    Ps[row * 68 + col + 1] = v1;
                }
            }
        }
        __syncthreads();
#pragma unroll
        for (int kk = 0; kk < 64; kk += 8) {
            uint32_t a[4][4], bfr[4][2];
#pragma unroll
            for (int mi = 0; mi < 4; mi++) {
                int r = m0 + mi * 16 + g;
                a[mi][0] = to_tf32(Ps[r * 68 + kk + tg]);
                a[mi][1] = to_tf32(Ps[(r + 8) * 68 + kk + tg]);
                a[mi][2] = to_tf32(Ps[r * 68 + kk + tg + 4]);
                a[mi][3] = to_tf32(Ps[(r + 8) * 68 + kk + tg + 4]);
            }
#pragma unroll
            for (int ni = 0; ni < 4; ni++) {
                int c = n0 + ni * 8 + g;
                bfr[ni][0] = to_tf32(Ws2[c * 68 + kk + tg]);
                bfr[ni][1] = to_tf32(Ws2[c * 68 + kk + tg + 4]);
            }
#pragma unroll
            for (int mi = 0; mi < 4; mi++)
#pragma unroll
                for (int ni = 0; ni < 4; ni++)
                    mma_tf32(acc[mi][ni], a[mi], bfr[ni]);
        }
    }
#pragma unroll
    for (int mi = 0; mi < 4; mi++) {
        int row0 = rb + m0 + mi * 16 + g;
#pragma unroll
        for (int ni = 0; ni < 4; ni++) {
            int col = n0 + ni * 8 + 2 * tg;
#pragma unroll
            for (int half = 0; half < 2; half++) {
                int row = row0 + half * 8;
                C[(size_t)row * 64 + col] = acc[mi][ni][half * 2 + 0];
                C[(size_t)row * 64 + col + 1] = acc[mi][ni][half * 2 + 1];
            }
        }
    }
}

// ------------------------------------------------------------------ DFT GEMM with fused transpose (reg-prefetch)
__device__ __forceinline__ void dft_body(const float* __restrict__ Aq,
                                         const float* __restrict__ F,
                                         float* __restrict__ X,
                                         int b, int cb, int zz) {
    __shared__ float As[64][33];
    __shared__ float Bs[64][36];
    const int tbase = zz * 256;
    const int tid = threadIdx.x;
    const int lane = tid & 31;
    const int w = tid >> 5;
    const int wm = w & 1, wn = w >> 1;
    const int m0 = wm * 32, n0 = wn * 32;
    const int g = lane >> 2, tg = lane & 3;
    const int lrow = tid >> 3;
    const int lcol = (tid & 7) * 4;

    float acc[2][4][4];
#pragma unroll
    for (int mi = 0; mi < 2; mi++)
#pragma unroll
        for (int ni = 0; ni < 4; ni++)
#pragma unroll
            for (int r = 0; r < 4; r++) acc[mi][ni][r] = 0.f;

    float4 va[4], vb[4];
#pragma unroll
    for (int i = 0; i < 4; i++) {
        int f4 = i * 128 + tid;
        int tl = f4 >> 4;
        int he = (f4 & 15) * 4;
        va[i] = *reinterpret_cast<const float4*>(Aq + ((size_t)(b * LZ + tbase + tl)) * DZ + he);
    }
#pragma unroll
    for (int r = 0; r < 4; r++) {
        int row = lrow + r * 16;
        vb[r] = *reinterpret_cast<const float4*>(F + (size_t)(cb + row) * LZ + tbase + lcol);
    }

    for (int it = 0; it < 8; it++) {
        int t0 = tbase + it * 32;
#pragma unroll
        for (int i = 0; i < 4; i++) {
            int f4 = i * 128 + tid;
            int tl = f4 >> 4;
            int he = (f4 & 15) * 4;
            As[he + 0][tl] = va[i].x;
            As[he + 1][tl] = va[i].y;
            As[he + 2][tl] = va[i].z;
            As[he + 3][tl] = va[i].w;
        }
#pragma unroll
        for (int r = 0; r < 4; r++) {
            int row = lrow + r * 16;
            *reinterpret_cast<float4*>(&Bs[row][lcol]) = vb[r];
        }
        __syncthreads();
        // prefetch next tile into registers while mma runs
        float4 na[4], nb[4];
        if (it < 7) {
#pragma unroll
            for (int i = 0; i < 4; i++) {
                int f4 = i * 128 + tid;
                int tl = f4 >> 4;
                int he = (f4 & 15) * 4;
                na[i] = *reinterpret_cast<const float4*>(
                    Aq + ((size_t)(b * LZ + t0 + 32 + tl)) * DZ + he);
            }
#pragma unroll
            for (int r = 0; r < 4; r++) {
                int row = lrow + r * 16;
                nb[r] = *reinterpret_cast<const float4*>(
                    F + (size_t)(cb + row) * LZ + t0 + 32 + lcol);
            }
        }
#pragma unroll
        for (int kk = 0; kk < 32; kk += 8) {
            uint32_t a[2][4], bfr[4][2];
#pragma unroll
            for (int mi = 0; mi < 2; mi++) {
                int r = m0 + mi * 16 + g;
                a[mi][0] = to_tf32(As[r][kk + tg]);
                a[mi][1] = to_tf32(As[r + 8][kk + tg]);
                a[mi][2] = to_tf32(As[r][kk + tg + 4]);
                a[mi][3] = to_tf32(As[r + 8][kk + tg + 4]);
            }
#pragma unroll
            for (int ni = 0; ni < 4; ni++) {
                int c = n0 + ni * 8 + g;
                bfr[ni][0] = to_tf32(Bs[c][kk + tg]);
                bfr[ni][1] = to_tf32(Bs[c][kk + tg + 4]);
            }
#pragma unroll
            for (int mi = 0; mi < 2; mi++)
#pragma unroll
                for (int ni = 0; ni < 4; ni++)
                    mma_tf32(acc[mi][ni], a[mi], bfr[ni]);
        }
        __syncthreads();
        if (it < 7) {
#pragma unroll
            for (int i = 0; i < 4; i++) va[i] = na[i];
#pragma unroll
            for (int r = 0; r < 4; r++) vb[r] = nb[r];
        }
    }
#pragma unroll
    for (int mi = 0; mi < 2; mi++) {
        int r0 = m0 + mi * 16 + g;
#pragma unroll
        for (int ni = 0; ni < 4; ni++) {
            int col = cb + n0 + ni * 8 + 2 * tg;
#pragma unroll
            for (int half = 0; half < 2; half++) {
                int row = r0 + half * 8;
                atomicAdd(&X[(size_t)(b * 64 + row) * M2 + col], acc[mi][ni][half * 2 + 0]);
                atomicAdd(&X[(size_t)(b * 64 + row) * M2 + col + 1], acc[mi][ni][half * 2 + 1]);
            }
        }
    }
}

__global__ __launch_bounds__(128) void gemm_dft(const float* __restrict__ Aq,
                                                const float* __restrict__ F,
                                                float* __restrict__ X) {
    dft_body(Aq, F, X, blockIdx.x, blockIdx.y * 64, blockIdx.z);
}

// ------------------------------------------------------------------ mode-space projection (cross path)
__global__ __launch_bounds__(256) void modeproj_kernel(const float* __restrict__ Hf,
                                                       const float* __restrict__ Wq,
                                                       const float* __restrict__ bq,
                                                       const float* __restrict__ cm,
                                                       float* __restrict__ Qf) {
    __shared__ float Hs[64][68];
    __shared__ float Ws[64][68];
    int b = blockIdx.x;
    int mh = blockIdx.y;
    int tid = threadIdx.x;
    for (int i = tid; i < 64 * 16; i += 256) {
        int d = i >> 4;
        int c4 = (i & 15) * 4;
        *reinterpret_cast<float4*>(&Hs[d][c4]) =
            *reinterpret_cast<const float4*>(Hf + ((size_t)(b * 64 + d)) * M2 + mh * 64 + c4);
    }
    for (int i = tid; i < 64 * 16; i += 256) {
        int he = i >> 4;
        int c4 = (i & 15) * 4;
        *reinterpret_cast<float4*>(&Ws[he][c4]) =
            *reinterpret_cast<const float4*>(Wq + he * 64 + c4);
    }
    __syncthreads();
    if (cm && mh == 0 && tid < 64) Hs[tid][0] -= cm[b * 64 + tid] * 1024.f;
    __syncthreads();
    int he = tid >> 2;
    int mg = tid & 3;
#pragma unroll
    for (int j = 0; j < 16; j++) {
        int ml = mg + 4 * j;
        float s = 0.f;
#pragma unroll
        for (int d = 0; d < 64; d++) s += Ws[he][d] * Hs[d][ml];
        int m2 = mh * 64 + ml;
        if (m2 == 0) s += bq[he] * 1024.f;
        Qf[((size_t)(b * 64 + he)) * M2 + m2] = s;
    }
}

// ------------------------------------------------------------------ fused modeproj + mode_mix (self-attn)
#define MPM_SMEM ((2*64*68 + 64*66) * 4)
__global__ __launch_bounds__(256) void modeproj_mix_kernel(const float* __restrict__ Hf,
                                                           const float* __restrict__ Wq,
                                                           const float* __restrict__ bq,
                                                           const float* __restrict__ wr,
                                                           const float* __restrict__ wi,
                                                           float* __restrict__ sel,
                                                           float scale) {
    extern __shared__ float sm[];
    float* Hs = sm;
    float* Ws = sm + 64 * 68;
    float* Qs = sm + 2 * 64 * 68;
    int b = blockIdx.x;
    int mh = blockIdx.y;
    int tid = threadIdx.x;
    for (int i = tid; i < 64 * 16; i += 256) {
        int d = i >> 4;
        int c4 = (i & 15) * 4;
        *reinterpret_cast<float4*>(&Hs[d * 68 + c4]) =
            *reinterpret_cast<const float4*>(Hf + ((size_t)(b * 64 + d)) * M2 + mh * 64 + c4);
    }
    for (int i = tid; i < 64 * 16; i += 256) {
        int he = i >> 4;
        int c4 = (i & 15) * 4;
        *reinterpret_cast<float4*>(&Ws[he * 68 + c4]) =
            *reinterpret_cast<const float4*>(Wq + he * 64 + c4);
    }
    __syncthreads();
    {
        int he = tid >> 2;
        int mg = tid & 3;
#pragma unroll
        for (int j = 0; j < 16; j++) {
            int ml = mg + 4 * j;
            float s = 0.f;
#pragma unroll
            for (int d = 0; d < 64; d++) s += Ws[he * 68 + d] * Hs[d * 68 + ml];
            if (mh == 0 && ml == 0) s += bq[he] * 1024.f;
            Qs[he * 66 + ml] = s;
        }
    }
    __syncthreads();
    {
        int lm = tid & 31;
        int hob = tid >> 5;
        int m = mh * 32 + lm;
#pragma unroll
        for (int j = 0; j < 8; j++) {
            int ho = hob * 8 + j;
            int h = ho >> 3, o = ho & 7;
            float ar = 0.f, ai = 0.f;
#pragma unroll
            for (int e = 0; e < 8; e++) {
                float xr = Qs[(h * 8 + e) * 66 + 2 * lm];
                float xi = Qs[(h * 8 + e) * 66 + 2 * lm + 1];
                int wix = ((h * 8 + e) * 8 + o) * MZ + m;
                float wrv = wr[wix], wiv = wi[wix];
                ar += xr * wrv - xi * wiv;
                ai += xr * wiv + xi * wrv;
            }
            size_t ro = ((size_t)(b * 64 + h * 8 + o)) * M2 + 2 * m;
            sel[ro] = ar * scale;
            sel[ro + 1] = ai * scale;
        }
    }
}

// ------------------------------------------------------------------ fused cross attention
__global__ __launch_bounds__(256) void qkattn_kernel(const float* __restrict__ Qf,
                                                     const float* __restrict__ Kf,
                                                     const float* __restrict__ wr,
                                                     const float* __restrict__ wi,
                                                     float* __restrict__ sel,
                                                     float scale) {
    __shared__ float Qs[8][128];
    __shared__ float Ks[8][128];
    __shared__ float qks[64][130];
    __shared__ float Vs[8][128];
    int bh = blockIdx.x;
    int h = bh & 7, b = bh >> 3;
    int tid = threadIdx.x;
    size_t tbase = (size_t)(b * 64 + h * 8) * M2;
#pragma unroll
    for (int i = 0; i < 4; i++) {
        int f = i * 256 + tid;
        int e = f >> 7, c = f & 127;
        Qs[e][c] = Qf[tbase + e * M2 + c];
        Ks[e][c] = Kf[tbase + e * M2 + c];
    }
    __syncthreads();
    {
        int x = tid >> 2;
        int ys = tid & 3;
#pragma unroll
        for (int j = 0; j < 16; j++) {
            int y = ys * 16 + j;
            float ar = 0.f, ai = 0.f;
#pragma unroll
            for (int e = 0; e < 8; e++) {
                float qr = Qs[e][2 * x], qi = Qs[e][2 * x + 1];
                float kr = Ks[e][2 * y], ki = Ks[e][2 * y + 1];
                ar += qr * kr - qi * ki;
                ai += qr * ki + qi * kr;
            }
            float a2 = 2.f * ar, b2 = 2.f * ai;
            float tr, ti;
            if (fabsf(a2) > 30.f) {
                tr = copysignf(1.f, ar);
                ti = 0.f;
            } else {
                float sn, cs;
                sincosf(b2, &sn, &cs);
                float ex = expf(a2);
                float exi = 1.f / ex;
                float den = 0.5f * (ex + exi) + cs;
                tr = 0.5f * (ex - exi) / den;
                ti = sn / den;
            }
            qks[x][2 * y] = tr;
            qks[x][2 * y + 1] = ti;
        }
    }
    __syncthreads();
    {
        int flat0 = tid * 2;
#pragma unroll
        for (int u = 0; u < 2; u++) {
            int flat = flat0 + u;
            int e = flat >> 6, x = flat & 63;
            float ar = 0.f, ai = 0.f;
#pragma unroll 16
            for (int y = 0; y < 64; y++) {
                float qr = qks[x][2 * y], qi = qks[x][2 * y + 1];
                float kr = Ks[e][2 * y], ki = Ks[e][2 * y + 1];
                ar += qr * kr - qi * ki;
                ai += qr * ki + qi * kr;
            }
            Vs[e][2 * x] = ar;
            Vs[e][2 * x + 1] = ai;
        }
    }
    __syncthreads();
    {
        int m = tid & 63;
        int og = tid >> 6;
#pragma unroll
        for (int j = 0; j < 2; j++) {
            int o = og * 2 + j;
            float ar = 0.f, ai = 0.f;
#pragma unroll
            for (int e = 0; e < 8; e++) {
                float xr = Vs[e][2 * m], xi = Vs[e][2 * m + 1];
                int wix = ((h * 8 + e) * 8 + o) * MZ + m;
                float wrv = wr[wix], wiv = wi[wix];
                ar += xr * wrv - xi * wiv;
                ai += xr * wiv + xi * wrv;
            }
            size_t ro = ((size_t)(b * 64 + h * 8 + o)) * M2 + 2 * m;
            sel[ro] = ar * scale;
            sel[ro + 1] = ai * scale;
        }
    }
}

// ------------------------------------------------------------------ layernorm family
__global__ void ln_row_kernel(const float* __restrict__ X, const float* __restrict__ g,
                              const float* __restrict__ be, float* __restrict__ out) {
    __shared__ float red[256];
    int tid = threadIdx.x;
    int sub = tid >> 6;
    int d = tid & 63;
    int row = blockIdx.x * 4 + sub;
    float v = X[(size_t)row * DZ + d];
    red[tid] = v;
    __syncthreads();
    for (int s = 32; s > 0; s >>= 1) {
        if (d < s) red[tid] += red[tid + s];
        __syncthreads();
    }
    float mu = red[sub * 64] * (1.f / 64.f);
    __syncthreads();
    float dv = v - mu;
    red[tid] = dv * dv;
    __syncthreads();
    for (int s = 32; s > 0; s >>= 1) {
        if (d < s) red[tid] += red[tid + s];
        __syncthreads();
    }
    float var = red[sub * 64] * (1.f / 64.f);
    out[(size_t)row * DZ + d] = dv * rsqrtf(var + 1e-5f) * g[d] + be[d];
}

__global__ void colmean_kernel(const float* __restrict__ X, float* __restrict__ cm) {
    __shared__ float r[256];
    int b = blockIdx.x / DZ, d = blockIdx.x % DZ;
    float s = 0.f;
    for (int t = threadIdx.x; t < LZ; t += 256) s += X[((size_t)(b * LZ + t)) * DZ + d];
    r[threadIdx.x] = s;
    __syncthreads();
    for (int o = 128; o > 0; o >>= 1) {
        if (threadIdx.x < o) r[threadIdx.x] += r[threadIdx.x + o];
        __syncthreads();
    }
    if (threadIdx.x == 0) cm[b * DZ + d] = r[0] * (1.f / LZ);
}

// ------------------------------------------------------------------ final epilogue
__global__ void final_kernel(const float* __restrict__ xln, const float* __restrict__ cm,
                             const float* __restrict__ tacc,
                             const float* __restrict__ tbase, const float* __restrict__ tw,
                             const float* __restrict__ pw, const float* __restrict__ pb,
                             float* __restrict__ out) {
    int idx = blockIdx.x * blockDim.x + threadIdx.x;
    if (idx >= BZ * 512) return;
    int t = idx & 511, b = idx >> 9;
    int tt = t + 512;
    float cv = 0.f;
#pragma unroll
    for (int j = 0; j < 3; j++) {
        int ts = (tt + j - 1) & (LZ - 1);
        const float* row = tacc + ((size_t)(b * LZ + ts)) * DZ;
#pragma unroll 4
        for (int d4 = 0; d4 < 16; d4++) {
            float4 rv = *reinterpret_cast<const float4*>(row + d4 * 4);
            cv += rv.x * tw[(d4 * 4 + 0) * 3 + j] + rv.y * tw[(d4 * 4 + 1) * 3 + j]
                + rv.z * tw[(d4 * 4 + 2) * 3 + j] + rv.w * tw[(d4 * 4 + 3) * 3 + j];
        }
    }
    float p = pb[0];
    const float* xr = xln + ((size_t)(b * LZ + tt)) * DZ;
    const float* cmr = cm + b * DZ;
#pragma unroll 4
    for (int d4 = 0; d4 < 16; d4++) {
        float4 xv = *reinterpret_cast<const float4*>(xr + d4 * 4);
        float4 cvv = *reinterpret_cast<const float4*>(cmr + d4 * 4);
        float4 pv = *reinterpret_cast<const float4*>(pw + d4 * 4);
        p += (xv.x - cvv.x) * pv.x + (xv.y - cvv.y) * pv.y
           + (xv.z - cvv.z) * pv.z + (xv.w - cvv.w) * pv.w;
    }
    out[idx] = p + cv + tbase[b * LZ + tt];
}

static float* symaddr_f(const void* sym) {
    void* p = nullptr;
    cudaGetSymbolAddress(&p, sym);
    return (float*)p;
}

extern "C" void kernel_launch(void* const* d_in, const int* in_sizes, int n_in,
                              void* d_out, int out_size) {
    const float* x_enc       = (const float*)d_in[0];
    const float* dp_w        = (const float*)d_in[1];
    const float* dp_b        = (const float*)d_in[2];
    const float* emb_enc_w   = (const float*)d_in[3];
    const float* emb_dec_w   = (const float*)d_in[4];
    const float* decomp_w    = (const float*)d_in[5];
    const float* decomp_b    = (const float*)d_in[6];
    const float* enc_attn_w  = (const float*)d_in[7];
    const float* enc_attn_b  = (const float*)d_in[8];
    const float* enc_four_wr = (const float*)d_in[9];
    const float* enc_four_wi = (const float*)d_in[10];
    const float* enc_c1      = (const float*)d_in[11];
    const float* enc_c2      = (const float*)d_in[12];
    const float* enc_ln_g    = (const float*)d_in[13];
    const float* enc_ln_b    = (const float*)d_in[14];
    const float* dec_self_w  = (const float*)d_in[15];
    const float* dec_self_b  = (const float*)d_in[16];
    const float* dec_four_wr = (const float*)d_in[17];
    const float* dec_four_wi = (const float*)d_in[18];
    const float* dec_cross_w = (const float*)d_in[19];
    const float* dec_cross_b = (const float*)d_in[20];
    const float* dec_cross_wr= (const float*)d_in[21];
    const float* dec_cross_wi= (const float*)d_in[22];
    const float* dec_c1      = (const float*)d_in[23];
    const float* dec_c2      = (const float*)d_in[24];
    const float* dec_trend_w = (const float*)d_in[25];
    const float* dec_ln_g    = (const float*)d_in[26];
    const float* dec_ln_b    = (const float*)d_in[27];
    const float* dec_proj_w  = (const float*)d_in[28];
    const float* dec_proj_b  = (const float*)d_in[29];
    float* out = (float*)d_out;

    float* px        = symaddr_f(g_x);
    float* pseas0    = symaddr_f(g_seas0);
    float* ptrend0   = symaddr_f(g_trend0);
    float* pseasinit = symaddr_f(g_seasinit);
    float* ph        = symaddr_f(g_h);
    float* py        = symaddr_f(g_y);
    float* pa        = symaddr_f(g_a);
    float* py2       = symaddr_f(g_y2);
    float* pa2       = symaddr_f(g_a2);
    float* pHf       = symaddr_f(g_Hf);
    float* pHf2      = pHf + (size_t)NHE * M2;
    float* pHq       = symaddr_f(g_Hq);
    float* pXf       = symaddr_f(g_Xf);
    float* pXk       = symaddr_f(g_Xk);
    float* psel      = symaddr_f(g_sel);
    float* psel2     = symaddr_f(g_sel2);
    float* pxd       = symaddr_f(g_xd);
    float* ptacc     = symaddr_f(g_tacc);
    float* pcm       = symaddr_f(g_cm);
    float* pcm2      = symaddr_f(g_cm2);
    float* pln       = symaddr_f(g_ln);
    float* pF        = symaddr_f(g_F);
    float* pFi       = symaddr_f(g_Fi);
    float* ptbase    = symaddr_f(g_trendbase);

    cudaFuncSetAttribute(gemm_tc<0>, cudaFuncAttributeMaxDynamicSharedMemorySize, GT_SMEM);
    cudaFuncSetAttribute(gemm_ffn, cudaFuncAttributeMaxDynamicSharedMemorySize, FFN_SMEM);
    cudaFuncSetAttribute(modeproj_mix_kernel, cudaFuncAttributeMaxDynamicSharedMemorySize, MPM_SMEM);

    static cudaStream_t s2 = nullptr;
    static cudaEvent_t evFork = nullptr, evJoin = nullptr;
    if (!s2) {
        cudaStreamCreateWithFlags(&s2, cudaStreamNonBlocking);
        cudaEventCreateWithFlags(&evFork, cudaEventDisableTiming);
        cudaEventCreateWithFlags(&evJoin, cudaEventDisableTiming);
    }

    dim3 dftg(BZ, 2, 4);
    dim3 mpg(BZ, 2);

    // ---- shared prep (stream 0) ----
    build_tables_kernel<<<512, 256>>>();
    transpose_in_kernel<<<1792, 256>>>(x_enc);
    colmean7_kernel<<<BZ * C7, 256>>>(x_enc);
    decomp7_kernel<<<BZ * C7, LZ>>>(px, decomp_w + 0, decomp_b + 0, pseas0, ptrend0);
    trendbase_kernel<<<256, 256>>>(dp_w, dp_b);
    seasinit_kernel<<<1792, 256>>>();
    cudaEventRecord(evFork, 0);

    // ---- decoder prefix + cross-Q path (stream s2) ----
    cudaStreamWaitEvent(s2, evFork, 0);
    embed_kernel<<<16384, 256, 0, s2>>>(pseasinit, emb_dec_w, pxd);
    cudaMemsetAsync(pHf2, 0, (size_t)NHE * M2 * sizeof(float), s2);
    gemm_dft<<<dftg, 128, 0, s2>>>(pxd, pF, pHf2);
    modeproj_mix_kernel<<<mpg, 256, MPM_SMEM, s2>>>(pHf2, dec_self_w + 0, dec_self_b + 0,
                                                    dec_four_wr, dec_four_wi, psel2, 1.0f);
    gemm_tc<0><<<dim3(32, 16), 128, GT_SMEM, s2>>>(psel2, pFi, nullptr, py2, NHE, 128, 1024);
    gemm_tc<0><<<dim3(512, 1), 128, GT_SMEM, s2>>>(py2, dec_self_w + 3 * 4096,
                                                   dec_self_b + 3 * 64, pa2, NROW, 64, 64);
    decomp64_kernel<<<1024, 256, 0, s2>>>(pxd, pa2, decomp_w + 5 * 4, decomp_b + 5 * 4,
                                          pxd, ptacc, 0);
    // cross-attention Q path (depends only on pxd)
    cudaMemsetAsync(pHq, 0, (size_t)NHE * M2 * sizeof(float), s2);
    gemm_dft<<<dftg, 128, 0, s2>>>(pxd, pF, pHq);
    modeproj_kernel<<<mpg, 256, 0, s2>>>(pHq, dec_cross_w + 0, dec_cross_b + 0, nullptr, pXf);
    cudaEventRecord(evJoin, s2);

    // ---- encoder (stream 0) ----
    embed_kernel<<<16384, 256>>>(px, emb_enc_w, ph);
    for (int l = 0; l < 2; l++) {
        const float* wq = enc_attn_w + (size_t)(l * 4 + 0) * 4096;
        const float* bq = enc_attn_b + (size_t)(l * 4 + 0) * 64;
        const float* wo = enc_attn_w + (size_t)(l * 4 + 3) * 4096;
        const float* bo = enc_attn_b + (size_t)(l * 4 + 3) * 64;
        cudaMemsetAsync(pHf, 0, (size_t)NHE * M2 * sizeof(float));
        gemm_dft<<<dftg, 128>>>(ph, pF, pHf);
        modeproj_mix_kernel<<<mpg, 256, MPM_SMEM>>>(pHf, wq, bq,
                                                    enc_four_wr + (size_t)l * 32768,
                                                    enc_four_wi + (size_t)l * 32768, psel, 1.0f);
        gemm_tc<0><<<dim3(32, 16), 128, GT_SMEM>>>(psel, pFi, nullptr, py, NHE, 128, 1024);
        gemm_tc<0><<<dim3(512, 1), 128, GT_SMEM>>>(py, wo, bo, pa, NROW, 64, 64);
        decomp64_kernel<<<1024, 256>>>(ph, pa, decomp_w + (1 + 2 * l) * 4,
                                       decomp_b + (1 + 2 * l) * 4, ph, nullptr, 0);
        gemm_ffn<<<512, 128, FFN_SMEM>>>(ph, enc_c1 + (size_t)l * 16384,
                                         enc_c2 + (size_t)l * 16384, py);
        decomp64_kernel<<<1024, 256>>>(ph, py, decomp_w + (2 + 2 * l) * 4,
                                       decomp_b + (2 + 2 * l) * 4, ph, nullptr, 0);
    }
    ln_row_kernel<<<16384, 256>>>(ph, enc_ln_g, enc_ln_b, ph);
    colmean_kernel<<<BZ * DZ, 256>>>(ph, pcm2);

    // ---- cross-attention K path (stream 0, encoder-only deps) ----
    cudaMemsetAsync(pHf, 0, (size_t)NHE * M2 * sizeof(float));
    gemm_dft<<<dftg, 128>>>(ph, pF, pHf);
    modeproj_kernel<<<mpg, 256>>>(pHf, dec_cross_w + 1 * 4096, dec_cross_b + 1 * 64, pcm2, pXk);

    // ---- join, then cross attention core ----
    cudaStreamWaitEvent(0, evJoin, 0);
    qkattn_kernel<<<512, 256>>>(pXf, pXk, dec_cross_wr, dec_cross_wi, psel, 1.0f / 4096.0f);
    gemm_tc<0><<<dim3(32, 16), 128, GT_SMEM>>>(psel, pFi, nullptr, py, NHE, 128, 1024);
    gemm_tc<0><<<dim3(512, 1), 128, GT_SMEM>>>(py, dec_cross_w + 3 * 4096, dec_cross_b + 3 * 64, pa,
                                               NROW, 64, 64);
    decomp64_kernel<<<1024, 256>>>(pxd, pa, decomp_w + 6 * 4, decomp_b + 6 * 4, pxd, ptacc, 1);

    gemm_ffn<<<512, 128, FFN_SMEM>>>(pxd, dec_c1, dec_c2, py);
    decomp64_kernel<<<1024, 256>>>(pxd, py, decomp_w + 7 * 4, decomp_b + 7 * 4, pxd, ptacc, 1);

    ln_row_kernel<<<16384, 256>>>(pxd, dec_ln_g, dec_ln_b, pln);
    colmean_kernel<<<BZ * DZ, 256>>>(pln, pcm);
    final_kernel<<<128, 256>>>(pln, pcm, ptacc, ptbase, dec_trend_w, dec_proj_w, dec_proj_b, out);
}

// round 16
// speedup vs baseline: 1.0507x; 1.0009x over previous
#include <cuda_runtime.h>
#include <cstdint>

#define BZ 64
#define LZ 1024
#define DZ 64
#define C7 7
#define HZ 8
#define EZ 8
#define MZ 64
#define M2 128
#define DFFD 256
#define NROW (BZ*LZ)
#define NHE  (BZ*DZ)

__device__ float g_x[BZ*LZ*C7];
__device__ float g_seas0[BZ*LZ*C7];
__device__ float g_trend0[BZ*LZ*C7];
__device__ float g_mean7[BZ*C7];
__device__ float g_trendbase[BZ*LZ];
__device__ float g_seasinit[BZ*LZ*C7];
__device__ float g_h[NROW*DZ];
__device__ float g_y[NROW*DZ];
__device__ float g_a[NROW*DZ];
__device__ float g_y2[NROW*DZ];
__device__ float g_a2[NROW*DZ];
__device__ float g_Hf[2*NHE*M2];
__device__ float g_Hq[NHE*M2];
__device__ float g_Xf[NHE*M2];
__device__ float g_Xk[NHE*M2];
__device__ float g_sel[NHE*M2];
__device__ float g_sel2[NHE*M2];
__device__ float g_xd[NROW*DZ];
__device__ float g_tacc[NROW*DZ];
__device__ float g_cm[BZ*DZ];
__device__ float g_cm2[BZ*DZ];
__device__ float g_ln[NROW*DZ];
__device__ float g_F[M2*LZ];
__device__ float g_Fi[LZ*M2];
__device__ float g_pe[LZ*DZ];

// ------------------------------------------------------------------ tables
__global__ void build_tables_kernel() {
    int idx = blockIdx.x * blockDim.x + threadIdx.x;
    if (idx < LZ * M2) {
        int t = idx >> 7;
        int m2 = idx & 127;
        int m = m2 >> 1;
        int r = (m * t) & (LZ - 1);
        float a = (float)r * (6.28318530717958647692f / (float)LZ);
        float s, c;
        sincosf(a, &s, &c);
        float v = (m2 & 1) ? -s : c;
        g_F[(size_t)m2 * LZ + t] = v;
        float cm = (m == 0) ? 1.f : 2.f;
        g_Fi[(size_t)t * M2 + m2] = v * (cm / (float)LZ);
    }
    if (idx < LZ * DZ) {
        int o = idx & 63;
        int t = idx >> 6;
        int i2 = o & ~1;
        float div = expf(-(float)i2 * 0.14391156831212793f);
        float arg = (float)t * div;
        g_pe[idx] = (o & 1) ? cosf(arg) : sinf(arg);
    }
}

// ------------------------------------------------------------------ input prep
__global__ void transpose_in_kernel(const float* __restrict__ xe) {
    int idx = blockIdx.x * blockDim.x + threadIdx.x;
    if (idx >= BZ * C7 * LZ) return;
    int t = idx & 1023;
    int c = (idx >> 10) % C7;
    int b = idx / (C7 * LZ);
    g_x[((size_t)(b * LZ + t)) * C7 + c] = xe[idx];
}

__global__ void colmean7_kernel(const float* __restrict__ xe) {
    __shared__ float r[256];
    int bc = blockIdx.x;
    float s = 0.f;
    for (int t = threadIdx.x; t < LZ; t += 256) s += xe[(size_t)bc * LZ + t];
    r[threadIdx.x] = s;
    __syncthreads();
    for (int o = 128; o > 0; o >>= 1) {
        if (threadIdx.x < o) r[threadIdx.x] += r[threadIdx.x + o];
        __syncthreads();
    }
    if (threadIdx.x == 0) g_mean7[bc] = r[0] * (1.f / LZ);
}

// ------------------------------------------------------------------ decomp7
__global__ void decomp7_kernel(const float* __restrict__ A,
                               const float* __restrict__ w4, const float* __restrict__ b4,
                               float* __restrict__ seas, float* __restrict__ trend) {
    __shared__ float ps[LZ];
    __shared__ float wsum[32];
    __shared__ float sx0, sxN;
    int c = blockIdx.x % C7, b = blockIdx.x / C7;
    int t = threadIdx.x, lane = t & 31, wid = t >> 5;
    size_t idx = ((size_t)(b * LZ + t)) * C7 + c;
    float x = A[idx];
    float s = x;
#pragma unroll
    for (int off = 1; off < 32; off <<= 1) {
        float v = __shfl_up_sync(0xffffffffu, s, off);
        if (lane >= off) s += v;
    }
    if (lane == 31) wsum[wid] = s;
    if (t == 0) sx0 = x;
    if (t == LZ - 1) sxN = x;
    __syncthreads();
    if (wid == 0) {
        float v = wsum[lane];
#pragma unroll
        for (int off = 1; off < 32; off <<= 1) {
            float u = __shfl_up_sync(0xffffffffu, v, off);
            if (lane >= off) v += u;
        }
        wsum[lane] = v;
    }
    __syncthreads();
    if (wid > 0) s += wsum[wid - 1];
    ps[t] = s;
    __syncthreads();
    float x0 = sx0, xN = sxN;
    const int ks[4] = {10, 50, 100, 500};
    float ma[4];
#pragma unroll
    for (int kk = 0; kk < 4; kk++) {
        int k = ks[kk], f = (k - 1) >> 1, e = k >> 1;
        int lo = t - f, hi = t + e;
        int cl = lo < 0 ? 0 : lo, ch = hi > LZ - 1 ? LZ - 1 : hi;
        float sw = ps[ch] - (cl > 0 ? ps[cl - 1] : 0.f)
                 + (float)(cl - lo) * x0 + (float)(hi - ch) * xN;
        ma[kk] = sw / (float)k;
    }
    float z[4], mx = -1e30f;
#pragma unroll
    for (int kk = 0; kk < 4; kk++) { z[kk] = x * w4[kk] + b4[kk]; mx = fmaxf(mx, z[kk]); }
    float se = 0.f, mean = 0.f;
#pragma unroll
    for (int kk = 0; kk < 4; kk++) { float e2 = __expf(z[kk] - mx); se += e2; mean += ma[kk] * e2; }
    mean /= se;
    seas[idx] = x - mean;
    trend[idx] = mean;
}

__device__ __forceinline__ float4 f4add(float4 a, float4 b) {
    return make_float4(a.x + b.x, a.y + b.y, a.z + b.z, a.w + b.w);
}

// ------------------------------------------------------------------ decomp64
__global__ __launch_bounds__(256) void decomp64_kernel(
    const float* __restrict__ A, const float* __restrict__ Bb,
    const float* __restrict__ w4, const float* __restrict__ b4,
    float* __restrict__ seas, float* __restrict__ trend, int accum) {
    __shared__ float4 ps[LZ];
    __shared__ float4 wsum[8];
    __shared__ float4 sedge[2];
    int c4 = blockIdx.x & 15, b = blockIdx.x >> 4;
    int tid = threadIdx.x, lane = tid & 31, wid = tid >> 5;
    int t4 = tid * 4;
    size_t base = ((size_t)(b * LZ + t4)) * DZ + c4 * 4;

    float4 x[4], p[4];
#pragma unroll
    for (int j = 0; j < 4; j++) {
        x[j] = *reinterpret_cast<const float4*>(A + base + (size_t)j * DZ);
        if (Bb) x[j] = f4add(x[j], *reinterpret_cast<const float4*>(Bb + base + (size_t)j * DZ));
    }
    p[0] = x[0];
#pragma unroll
    for (int j = 1; j < 4; j++) p[j] = f4add(p[j - 1], x[j]);

    float4 s = p[3];
#pragma unroll
    for (int off = 1; off < 32; off <<= 1) {
        float4 v;
        v.x = __shfl_up_sync(0xffffffffu, s.x, off);
        v.y = __shfl_up_sync(0xffffffffu, s.y, off);
        v.z = __shfl_up_sync(0xffffffffu, s.z, off);
        v.w = __shfl_up_sync(0xffffffffu, s.w, off);
        if (lane >= off) s = f4add(s, v);
    }
    if (lane == 31) wsum[wid] = s;
    if (tid == 0) sedge[0] = x[0];
    if (tid == 255) sedge[1] = x[3];
    __syncthreads();
    if (wid == 0 && lane < 8) {
        float4 v = wsum[lane];
#pragma unroll
        for (int off = 1; off < 8; off <<= 1) {
            float4 u;
            u.x = __shfl_up_sync(0xffu, v.x, off);
            u.y = __shfl_up_sync(0xffu, v.y, off);
            u.z = __shfl_up_sync(0xffu, v.z, off);
            u.w = __shfl_up_sync(0xffu, v.w, off);
            if (lane >= off) v = f4add(v, u);
        }
        wsum[lane] = v;
    }
    __syncthreads();
    float4 ex = make_float4(0.f, 0.f, 0.f, 0.f);
    if (wid > 0) ex = wsum[wid - 1];
    {
        float4 d;
        d.x = s.x - p[3].x; d.y = s.y - p[3].y; d.z = s.z - p[3].z; d.w = s.w - p[3].w;
        ex = f4add(ex, d);
    }
#pragma unroll
    for (int j = 0; j < 4; j++) ps[t4 + j] = f4add(ex, p[j]);
    __syncthreads();

    float4 x0 = sedge[0], xN = sedge[1];
    const int ks[4] = {10, 50, 100, 500};
#pragma unroll
    for (int j = 0; j < 4; j++) {
        int t = t4 + j;
        float ma[4][4];
#pragma unroll
        for (int kk = 0; kk < 4; kk++) {
            int k = ks[kk], f = (k - 1) >> 1, e = k >> 1;
            int lo = t - f, hi = t + e;
            int cl = lo < 0 ? 0 : lo, ch = hi > LZ - 1 ? LZ - 1 : hi;
            float4 pc = ps[ch];
            float4 pl = make_float4(0.f, 0.f, 0.f, 0.f);
            if (cl > 0) pl = ps[cl - 1];
            float fl = (float)(cl - lo), fr = (float)(hi - ch);
            float inv = 1.f / (float)k;
            ma[kk][0] = (pc.x - pl.x + fl * x0.x + fr * xN.x) * inv;
            ma[kk][1] = (pc.y - pl.y + fl * x0.y + fr * xN.y) * inv;
            ma[kk][2] = (pc.z - pl.z + fl * x0.z + fr * xN.z) * inv;
            ma[kk][3] = (pc.w - pl.w + fl * x0.w + fr * xN.w) * inv;
        }
        float xa[4] = {x[j].x, x[j].y, x[j].z, x[j].w};
        float so[4], tr[4];
#pragma unroll
        for (int cc = 0; cc < 4; cc++) {
            float z[4], mx = -1e30f;
#pragma unroll
            for (int kk = 0; kk < 4; kk++) { z[kk] = xa[cc] * w4[kk] + b4[kk]; mx = fmaxf(mx, z[kk]); }
            float se = 0.f, mean = 0.f;
#pragma unroll
            for (int kk = 0; kk < 4; kk++) { float e2 = __expf(z[kk] - mx); se += e2; mean += ma[kk][cc] * e2; }
            mean /= se;
            so[cc] = xa[cc] - mean;
            tr[cc] = mean;
        }
        *reinterpret_cast<float4*>(seas + base + (size_t)j * DZ) =
            make_float4(so[0], so[1], so[2], so[3]);
        if (trend) {
            float4 tv = make_float4(tr[0], tr[1], tr[2], tr[3]);
            if (accum) {
                float4 old = *reinterpret_cast<float4*>(trend + base + (size_t)j * DZ);
                tv = f4add(tv, old);
            }
            *reinterpret_cast<float4*>(trend + base + (size_t)j * DZ) = tv;
        }
    }
}

// ------------------------------------------------------------------ trend/seasonal init
__global__ void trendbase_kernel(const float* __restrict__ dpw, const float* __restrict__ dpb) {
    int idx = blockIdx.x * blockDim.x + threadIdx.x;
    if (idx >= BZ * LZ) return;
    int t = idx & 1023, b = idx >> 10;
    float s = dpb[0];
#pragma unroll
    for (int c = 0; c < C7; c++) {
        float v = (t < 512) ? g_trend0[((size_t)(b * LZ + 512 + t)) * C7 + c]
                            : g_mean7[b * C7 + c];
        s += v * dpw[c];
    }
    g_trendbase[idx] = s;
}

__global__ void seasinit_kernel() {
    int idx = blockIdx.x * blockDim.x + threadIdx.x;
    if (idx >= BZ * LZ * C7) return;
    int c = idx % C7;
    int t = (idx / C7) & 1023;
    int b = idx / (C7 * LZ);
    g_seasinit[idx] = (t < 512) ? g_seas0[((size_t)(b * LZ + 512 + t)) * C7 + c] : 0.f;
}

// ------------------------------------------------------------------ embedding
__global__ void embed_kernel(const float* __restrict__ in, const float* __restrict__ w,
                             float* __restrict__ out) {
    int idx = blockIdx.x * blockDim.x + threadIdx.x;
    if (idx >= BZ * LZ * DZ) return;
    int o = idx & 63;
    int t = (idx >> 6) & 1023;
    int b = idx >> 16;
    float s = 0.f;
#pragma unroll
    for (int j = 0; j < 3; j++) {
        int ts = (t + j - 1 + LZ) & (LZ - 1);
        const float* ip = in + ((size_t)(b * LZ + ts)) * C7;
#pragma unroll
        for (int c = 0; c < C7; c++) s += ip[c] * w[(o * C7 + c) * 3 + j];
    }
    out[idx] = s + g_pe[(t << 6) + o];
}

// ------------------------------------------------------------------ tf32 helpers
__device__ __forceinline__ uint32_t to_tf32(float x) {
    uint32_t r;
    asm("cvt.rna.tf32.f32 %0, %1;" : "=r"(r) : "f"(x));
    return r;
}
__device__ __forceinline__ void cpa16(uint32_t s, const float* g) {
    asm volatile("cp.async.ca.shared.global [%0], [%1], 16;" :: "r"(s), "l"(g));
}
__device__ __forceinline__ void cpa_commit() {
    asm volatile("cp.async.commit_group;");
}
__device__ __forceinline__ void cpa_wait1() {
    asm volatile("cp.async.wait_group 1;");
}
__device__ __forceinline__ void mma_tf32(float* acc, const uint32_t* a, const uint32_t* bf) {
    asm volatile(
        "mma.sync.aligned.m16n8k8.row.col.f32.tf32.tf32.f32 "
        "{%0,%1,%2,%3}, {%4,%5,%6,%7}, {%8,%9}, {%0,%1,%2,%3};"
        : "+f"(acc[0]), "+f"(acc[1]), "+f"(acc[2]), "+f"(acc[3])
        : "r"(a[0]), "r"(a[1]), "r"(a[2]), "r"(a[3]), "r"(bf[0]), "r"(bf[1]));
}

// ------------------------------------------------------------------ tf32 GEMM
#define GT_ASTRIDE (128*36)
#define GT_BSTRIDE (64*36)
#define GT_SMEM ((2*GT_ASTRIDE + 2*GT_BSTRIDE) * 4)

template <int ACT>
__global__ __launch_bounds__(128) void gemm_tc(const float* __restrict__ A,
                                               const float* __restrict__ W,
                                               const float* __restrict__ bias,
                                               float* __restrict__ C,
                                               int N, int K, int O) {
    extern __shared__ float dsm[];
    float* As = dsm;
    float* Bs = dsm + 2 * GT_ASTRIDE;
    const int rb = blockIdx.x * 128;
    const int cb = blockIdx.y * 64;
    const int tid = threadIdx.x;
    const int lane = tid & 31;
    const int w = tid >> 5;
    const int wm = w & 1, wn = w >> 1;
    const int m0 = wm * 64, n0 = wn * 32;
    const int g = lane >> 2, tg = lane & 3;
    const int lrow = tid >> 3;
    const int lcol = (tid & 7) * 4;

    uint32_t sA = (uint32_t)__cvta_generic_to_shared(As);
    uint32_t sB = (uint32_t)__cvta_generic_to_shared(Bs);

    float acc[4][4][4];
#pragma unroll
    for (int mi = 0; mi < 4; mi++)
#pragma unroll
        for (int ni = 0; ni < 4; ni++)
#pragma unroll
            for (int r = 0; r < 4; r++) acc[mi][ni][r] = 0.f;

#pragma unroll
    for (int r = 0; r < 8; r++) {
        int row = lrow + r * 16;
        cpa16(sA + (uint32_t)((row * 36 + lcol) * 4), A + (size_t)(rb + row) * K + lcol);
    }
#pragma unroll
    for (int r = 0; r < 4; r++) {
        int row = lrow + r * 16;
        cpa16(sB + (uint32_t)((row * 36 + lcol) * 4), W + (size_t)(cb + row) * K + lcol);
    }
    cpa_commit();

    int st = 0;
    for (int k0 = 0; k0 < K; k0 += 32, st ^= 1) {
        if (k0 + 32 < K) {
            int nx = st ^ 1;
#pragma unroll
            for (int r = 0; r < 8; r++) {
                int row = lrow + r * 16;
                cpa16(sA + (uint32_t)((nx * GT_ASTRIDE + row * 36 + lcol) * 4),
                      A + (size_t)(rb + row) * K + k0 + 32 + lcol);
            }
#pragma unroll
            for (int r = 0; r < 4; r++) {
                int row = lrow + r * 16;
                cpa16(sB + (uint32_t)((nx * GT_BSTRIDE + row * 36 + lcol) * 4),
                      W + (size_t)(cb + row) * K + k0 + 32 + lcol);
            }
        }
        cpa_commit();
        cpa_wait1();
        __syncthreads();
        const float* Ast = As + st * GT_ASTRIDE;
        const float* Bst = Bs + st * GT_BSTRIDE;
#pragma unroll
        for (int kk = 0; kk < 32; kk += 8) {
            uint32_t a[4][4], bfr[4][2];
#pragma unroll
            for (int mi = 0; mi < 4; mi++) {
                int r = m0 + mi * 16 + g;
                a[mi][0] = to_tf32(Ast[r * 36 + kk + tg]);
                a[mi][1] = to_tf32(Ast[(r + 8) * 36 + kk + tg]);
                a[mi][2] = to_tf32(Ast[r * 36 + kk + tg + 4]);
                a[mi][3] = to_tf32(Ast[(r + 8) * 36 + kk + tg + 4]);
            }
#pragma unroll
            for (int ni = 0; ni < 4; ni++) {
                int c = n0 + ni * 8 + g;
                bfr[ni][0] = to_tf32(Bst[c * 36 + kk + tg]);
                bfr[ni][1] = to_tf32(Bst[c * 36 + kk + tg + 4]);
            }
#pragma unroll
            for (int mi = 0; mi < 4; mi++)
#pragma unroll
                for (int ni = 0; ni < 4; ni++)
                    mma_tf32(acc[mi][ni], a[mi], bfr[ni]);
        }
        __syncthreads();
    }
#pragma unroll
    for (int mi = 0; mi < 4; mi++) {
        int row0 = rb + m0 + mi * 16 + g;
#pragma unroll
        for (int ni = 0; ni < 4; ni++) {
            int col = cb + n0 + ni * 8 + 2 * tg;
#pragma unroll
            for (int half = 0; half < 2; half++) {
                int row = row0 + half * 8;
                float v0 = acc[mi][ni][half * 2 + 0];
                float v1 = acc[mi][ni][half * 2 + 1];
                if (bias) { v0 += bias[col]; v1 += bias[col + 1]; }
                if (ACT == 1) {
                    v0 = 0.5f * v0 * (1.f + erff(v0 * 0.70710678118654752f));
                    v1 = 0.5f * v1 * (1.f + erff(v1 * 0.70710678118654752f));
                }
                C[(size_t)row * O + col] = v0;
                C[(size_t)row * O + col + 1] = v1;
            }
        }
    }
}

// ------------------------------------------------------------------ fused FFN
#define FFN_AS  (128*68)
#define FFN_WS  (64*68)
#define FFN_PS  (128*68)
#define FFN_SMEM ((FFN_AS + 2*FFN_WS + FFN_PS) * 4)

__global__ __launch_bounds__(128) void gemm_ffn(const float* __restrict__ A,
                                                const float* __restrict__ W1,
                                                const float* __restrict__ W2,
                                                float* __restrict__ C) {
    extern __shared__ float sm[];
    float* As  = sm;
    float* Ws1 = sm + FFN_AS;
    float* Ws2 = sm + FFN_AS + FFN_WS;
    float* Ps  = sm + FFN_AS + 2 * FFN_WS;
    const int rb = blockIdx.x * 128;
    const int tid = threadIdx.x;
    const int lane = tid & 31;
    const int w = tid >> 5;
    const int wm = w & 1, wn = w >> 1;
    const int m0 = wm * 64, n0 = wn * 32;
    const int g = lane >> 2, tg = lane & 3;

    for (int i = tid; i < 128 * 16; i += 128) {
        int row = i >> 4;
        int c4 = (i & 15) * 4;
        *reinterpret_cast<float4*>(&As[row * 68 + c4]) =
            *reinterpret_cast<const float4*>(A + (size_t)(rb + row) * 64 + c4);
    }

    float acc[4][4][4];
#pragma unroll
    for (int mi = 0; mi < 4; mi++)
#pragma unroll
        for (int ni = 0; ni < 4; ni++)
#pragma unroll
            for (int r = 0; r < 4; r++) acc[mi][ni][r] = 0.f;

    for (int ch = 0; ch < 4; ch++) {
        __syncthreads();
        for (int i = tid; i < 64 * 16; i += 128) {
            int row = i >> 4;
            int c4 = (i & 15) * 4;
            *reinterpret_cast<float4*>(&Ws1[row * 68 + c4]) =
                *reinterpret_cast<const float4*>(W1 + (size_t)(ch * 64 + row) * 64 + c4);
            *reinterpret_cast<float4*>(&Ws2[row * 68 + c4]) =
                *reinterpret_cast<const float4*>(W2 + (size_t)row * 256 + ch * 64 + c4);
        }
        __syncthreads();
        float p1[4][4][4];
#pragma unroll
        for (int mi = 0; mi < 4; mi++)
#pragma unroll
            for (int ni = 0; ni < 4; ni++)
#pragma unroll
                for (int r = 0; r < 4; r++) p1[mi][ni][r] = 0.f;
#pragma unroll
        for (int kk = 0; kk < 64; kk += 8) {
            uint32_t a[4][4], bfr[4][2];
#pragma unroll
            for (int mi = 0; mi < 4; mi++) {
                int r = m0 + mi * 16 + g;
                a[mi][0] = to_tf32(As[r * 68 + kk + tg]);
                a[mi][1] = to_tf32(As[(r + 8) * 68 + kk + tg]);
                a[mi][2] = to_tf32(As[r * 68 + kk + tg + 4]);
                a[mi][3] = to_tf32(As[(r + 8) * 68 + kk + tg + 4]);
            }
#pragma unroll
            for (int ni = 0; ni < 4; ni++) {
                int c = n0 + ni * 8 + g;
                bfr[ni][0] = to_tf32(Ws1[c * 68 + kk + tg]);
                bfr[ni][1] = to_tf32(Ws1[c * 68 + kk + tg + 4]);
            }
#pragma unroll
            for (int mi = 0; mi < 4; mi++)
#pragma unroll
                for (int ni = 0; ni < 4; ni++)
                    mma_tf32(p1[mi][ni], a[mi], bfr[ni]);
        }
#pragma unroll
        for (int mi = 0; mi < 4; mi++) {
            int row0 = m0 + mi * 16 + g;
#pragma unroll
            for (int ni = 0; ni < 4; ni++) {
                int col = n0 + ni * 8 + 2 * tg;
#pragma unroll
                for (int half = 0; half < 2; half++) {
                    int row = row0 + half * 8;
                    float v0 = p1[mi][ni][half * 2 + 0];
                    float v1 = p1[mi][ni][half * 2 + 1];
                    v0 = 0.5f * v0 * (1.f + erff(v0 * 0.70710678118654752f));
                    v1 = 0.5f * v1 * (1.f + erff(v1 * 0.70710678118654752f));
                    Ps[row * 68 + col] = v0;
                    Ps[row * 68 + col + 1] = v1;
                }
            }
        }
        __syncthreads();
#pragma unroll
        for (int kk = 0; kk < 64; kk += 8) {
            uint32_t a[4][4], bfr[4][2];
#pragma unroll
            for (int mi = 0; mi < 4; mi++) {
                int r = m0 + mi * 16 + g;
                a[mi][0] = to_tf32(Ps[r * 68 + kk + tg]);
                a[mi][1] = to_tf32(Ps[(r + 8) * 68 + kk + tg]);
                a[mi][2] = to_tf32(Ps[r * 68 + kk + tg + 4]);
                a[mi][3] = to_tf32(Ps[(r + 8) * 68 + kk + tg + 4]);
            }
#pragma unroll
            for (int ni = 0; ni < 4; ni++) {
                int c = n0 + ni * 8 + g;
                bfr[ni][0] = to_tf32(Ws2[c * 68 + kk + tg]);
                bfr[ni][1] = to_tf32(Ws2[c * 68 + kk + tg + 4]);
            }
#pragma unroll
            for (int mi = 0; mi < 4; mi++)
#pragma unroll
                for (int ni = 0; ni < 4; ni++)
                    mma_tf32(acc[mi][ni], a[mi], bfr[ni]);
        }
    }
#pragma unroll
    for (int mi = 0; mi < 4; mi++) {
        int row0 = rb + m0 + mi * 16 + g;
#pragma unroll
        for (int ni = 0; ni < 4; ni++) {
            int col = n0 + ni * 8 + 2 * tg;
#pragma unroll
            for (int half = 0; half < 2; half++) {
                int row = row0 + half * 8;
                C[(size_t)row * 64 + col] = acc[mi][ni][half * 2 + 0];
                C[(size_t)row * 64 + col + 1] = acc[mi][ni][half * 2 + 1];
            }
        }
    }
}

// ------------------------------------------------------------------ DFT GEMM with fused transpose (reg-prefetch)
__device__ __forceinline__ void dft_body(const float* __restrict__ Aq,
                                         const float* __restrict__ F,
                                         float* __restrict__ X,
                                         int b, int cb, int zz) {
    __shared__ float As[64][33];
    __shared__ float Bs[64][36];
    const int tbase = zz * 256;
    const int tid = threadIdx.x;
    const int lane = tid & 31;
    const int w = tid >> 5;
    const int wm = w & 1, wn = w >> 1;
    const int m0 = wm * 32, n0 = wn * 32;
    const int g = lane >> 2, tg = lane & 3;
    const int lrow = tid >> 3;
    const int lcol = (tid & 7) * 4;

    float acc[2][4][4];
#pragma unroll
    for (int mi = 0; mi < 2; mi++)
#pragma unroll
        for (int ni = 0; ni < 4; ni++)
#pragma unroll
            for (int r = 0; r < 4; r++) acc[mi][ni][r] = 0.f;

    float4 va[4], vb[4];
#pragma unroll
    for (int i = 0; i < 4; i++) {
        int f4 = i * 128 + tid;
        int tl = f4 >> 4;
        int he = (f4 & 15) * 4;
        va[i] = *reinterpret_cast<const float4*>(Aq + ((size_t)(b * LZ + tbase + tl)) * DZ + he);
    }
#pragma unroll
    for (int r = 0; r < 4; r++) {
        int row = lrow + r * 16;
        vb[r] = *reinterpret_cast<const float4*>(F + (size_t)(cb + row) * LZ + tbase + lcol);
    }

    for (int it = 0; it < 8; it++) {
        int t0 = tbase + it * 32;
#pragma unroll
        for (int i = 0; i < 4; i++) {
            int f4 = i * 128 + tid;
            int tl = f4 >> 4;
            int he = (f4 & 15) * 4;
            As[he + 0][tl] = va[i].x;
            As[he + 1][tl] = va[i].y;
            As[he + 2][tl] = va[i].z;
            As[he + 3][tl] = va[i].w;
        }
#pragma unroll
        for (int r = 0; r < 4; r++) {
            int row = lrow + r * 16;
            *reinterpret_cast<float4*>(&Bs[row][lcol]) = vb[r];
        }
        __syncthreads();
        float4 na[4], nb[4];
        if (it < 7) {
#pragma unroll
            for (int i = 0; i < 4; i++) {
                int f4 = i * 128 + tid;
                int tl = f4 >> 4;
                int he = (f4 & 15) * 4;
                na[i] = *reinterpret_cast<const float4*>(
                    Aq + ((size_t)(b * LZ + t0 + 32 + tl)) * DZ + he);
            }
#pragma unroll
            for (int r = 0; r < 4; r++) {
                int row = lrow + r * 16;
                nb[r] = *reinterpret_cast<const float4*>(
                    F + (size_t)(cb + row) * LZ + t0 + 32 + lcol);
            }
        }
#pragma unroll
        for (int kk = 0; kk < 32; kk += 8) {
            uint32_t a[2][4], bfr[4][2];
#pragma unroll
            for (int mi = 0; mi < 2; mi++) {
                int r = m0 + mi * 16 + g;
                a[mi][0] = to_tf32(As[r][kk + tg]);
                a[mi][1] = to_tf32(As[r + 8][kk + tg]);
                a[mi][2] = to_tf32(As[r][kk + tg + 4]);
                a[mi][3] = to_tf32(As[r + 8][kk + tg + 4]);
            }
#pragma unroll
            for (int ni = 0; ni < 4; ni++) {
                int c = n0 + ni * 8 + g;
                bfr[ni][0] = to_tf32(Bs[c][kk + tg]);
                bfr[ni][1] = to_tf32(Bs[c][kk + tg + 4]);
            }
#pragma unroll
            for (int mi = 0; mi < 2; mi++)
#pragma unroll
                for (int ni = 0; ni < 4; ni++)
                    mma_tf32(acc[mi][ni], a[mi], bfr[ni]);
        }
        __syncthreads();
        if (it < 7) {
#pragma unroll
            for (int i = 0; i < 4; i++) va[i] = na[i];
#pragma unroll
            for (int r = 0; r < 4; r++) vb[r] = nb[r];
        }
    }
#pragma unroll
    for (int mi = 0; mi < 2; mi++) {
        int r0 = m0 + mi * 16 + g;
#pragma unroll
        for (int ni = 0; ni < 4; ni++) {
            int col = cb + n0 + ni * 8 + 2 * tg;
#pragma unroll
            for (int half = 0; half < 2; half++) {
                int row = r0 + half * 8;
                atomicAdd(&X[(size_t)(b * 64 + row) * M2 + col], acc[mi][ni][half * 2 + 0]);
                atomicAdd(&X[(size_t)(b * 64 + row) * M2 + col + 1], acc[mi][ni][half * 2 + 1]);
            }
        }
    }
}

__global__ __launch_bounds__(128) void gemm_dft(const float* __restrict__ Aq,
                                                const float* __restrict__ F,
                                                float* __restrict__ X) {
    dft_body(Aq, F, X, blockIdx.x, blockIdx.y * 64, blockIdx.z);
}

// ------------------------------------------------------------------ mode-space projection (cross path)
__global__ __launch_bounds__(256) void modeproj_kernel(const float* __restrict__ Hf,
                                                       const float* __restrict__ Wq,
                                                       const float* __restrict__ bq,
                                                       const float* __restrict__ cm,
                                                       float* __restrict__ Qf) {
    __shared__ float Hs[64][68];
    __shared__ float Ws[64][68];
    int b = blockIdx.x;
    int mh = blockIdx.y;
    int tid = threadIdx.x;
    for (int i = tid; i < 64 * 16; i += 256) {
        int d = i >> 4;
        int c4 = (i & 15) * 4;
        *reinterpret_cast<float4*>(&Hs[d][c4]) =
            *reinterpret_cast<const float4*>(Hf + ((size_t)(b * 64 + d)) * M2 + mh * 64 + c4);
    }
    for (int i = tid; i < 64 * 16; i += 256) {
        int he = i >> 4;
        int c4 = (i & 15) * 4;
        *reinterpret_cast<float4*>(&Ws[he][c4]) =
            *reinterpret_cast<const float4*>(Wq + he * 64 + c4);
    }
    __syncthreads();
    if (cm && mh == 0 && tid < 64) Hs[tid][0] -= cm[b * 64 + tid] * 1024.f;
    __syncthreads();
    int he = tid >> 2;
    int mg = tid & 3;
#pragma unroll
    for (int j = 0; j < 16; j++) {
        int ml = mg + 4 * j;
        float s = 0.f;
#pragma unroll
        for (int d = 0; d < 64; d++) s += Ws[he][d] * Hs[d][ml];
        int m2 = mh * 64 + ml;
        if (m2 == 0) s += bq[he] * 1024.f;
        Qf[((size_t)(b * 64 + he)) * M2 + m2] = s;
    }
}

// ------------------------------------------------------------------ fused modeproj + mode_mix (self-attn)
#define MPM_SMEM ((2*64*68 + 64*66) * 4)
__global__ __launch_bounds__(256) void modeproj_mix_kernel(const float* __restrict__ Hf,
                                                           const float* __restrict__ Wq,
                                                           const float* __restrict__ bq,
                                                           const float* __restrict__ wr,
                                                           const float* __restrict__ wi,
                                                           float* __restrict__ sel,
                                                           float scale) {
    extern __shared__ float sm[];
    float* Hs = sm;
    float* Ws = sm + 64 * 68;
    float* Qs = sm + 2 * 64 * 68;
    int b = blockIdx.x;
    int mh = blockIdx.y;
    int tid = threadIdx.x;
    for (int i = tid; i < 64 * 16; i += 256) {
        int d = i >> 4;
        int c4 = (i & 15) * 4;
        *reinterpret_cast<float4*>(&Hs[d * 68 + c4]) =
            *reinterpret_cast<const float4*>(Hf + ((size_t)(b * 64 + d)) * M2 + mh * 64 + c4);
    }
    for (int i = tid; i < 64 * 16; i += 256) {
        int he = i >> 4;
        int c4 = (i & 15) * 4;
        *reinterpret_cast<float4*>(&Ws[he * 68 + c4]) =
            *reinterpret_cast<const float4*>(Wq + he * 64 + c4);
    }
    __syncthreads();
    {
        int he = tid >> 2;
        int mg = tid & 3;
#pragma unroll
        for (int j = 0; j < 16; j++) {
            int ml = mg + 4 * j;
            float s = 0.f;
#pragma unroll
            for (int d = 0; d < 64; d++) s += Ws[he * 68 + d] * Hs[d * 68 + ml];
            if (mh == 0 && ml == 0) s += bq[he] * 1024.f;
            Qs[he * 66 + ml] = s;
        }
    }
    __syncthreads();
    {
        int lm = tid & 31;
        int hob = tid >> 5;
        int m = mh * 32 + lm;
#pragma unroll
        for (int j = 0; j < 8; j++) {
            int ho = hob * 8 + j;
            int h = ho >> 3, o = ho & 7;
            float ar = 0.f, ai = 0.f;
#pragma unroll
            for (int e = 0; e < 8; e++) {
                float xr = Qs[(h * 8 + e) * 66 + 2 * lm];
                float xi = Qs[(h * 8 + e) * 66 + 2 * lm + 1];
                int wix = ((h * 8 + e) * 8 + o) * MZ + m;
                float wrv = wr[wix], wiv = wi[wix];
                ar += xr * wrv - xi * wiv;
                ai += xr * wiv + xi * wrv;
            }
            size_t ro = ((size_t)(b * 64 + h * 8 + o)) * M2 + 2 * m;
            sel[ro] = ar * scale;
            sel[ro + 1] = ai * scale;
        }
    }
}

// ------------------------------------------------------------------ fused cross attention
__global__ __launch_bounds__(256) void qkattn_kernel(const float* __restrict__ Qf,
                                                     const float* __restrict__ Kf,
                                                     const float* __restrict__ wr,
                                                     const float* __restrict__ wi,
                                                     float* __restrict__ sel,
                                                     float scale) {
    __shared__ float Qs[8][128];
    __shared__ float Ks[8][128];
    __shared__ float qks[64][130];
    __shared__ float Vs[8][128];
    int bh = blockIdx.x;
    int h = bh & 7, b = bh >> 3;
    int tid = threadIdx.x;
    size_t tbase = (size_t)(b * 64 + h * 8) * M2;
#pragma unroll
    for (int i = 0; i < 4; i++) {
        int f = i * 256 + tid;
        int e = f >> 7, c = f & 127;
        Qs[e][c] = Qf[tbase + e * M2 + c];
        Ks[e][c] = Kf[tbase + e * M2 + c];
    }
    __syncthreads();
    {
        int x = tid >> 2;
        int ys = tid & 3;
#pragma unroll
        for (int j = 0; j < 16; j++) {
            int y = ys * 16 + j;
            float ar = 0.f, ai = 0.f;
#pragma unroll
            for (int e = 0; e < 8; e++) {
                float qr = Qs[e][2 * x], qi = Qs[e][2 * x + 1];
                float kr = Ks[e][2 * y], ki = Ks[e][2 * y + 1];
                ar += qr * kr - qi * ki;
                ai += qr * ki + qi * kr;
            }
            float a2 = 2.f * ar, b2 = 2.f * ai;
            float tr, ti;
            if (fabsf(a2) > 30.f) {
                tr = copysignf(1.f, ar);
                ti = 0.f;
            } else {
                float sn, cs;
                sincosf(b2, &sn, &cs);
                float ex = __expf(a2);
                float exi = 1.f / ex;
                float den = 0.5f * (ex + exi) + cs;
                tr = 0.5f * (ex - exi) / den;
                ti = sn / den;
            }
            qks[x][2 * y] = tr;
            qks[x][2 * y + 1] = ti;
        }
    }
    __syncthreads();
    {
        int flat0 = tid * 2;
#pragma unroll
        for (int u = 0; u < 2; u++) {
            int flat = flat0 + u;
            int e = flat >> 6, x = flat & 63;
            float ar = 0.f, ai = 0.f;
#pragma unroll 16
            for (int y = 0; y < 64; y++) {
                float qr = qks[x][2 * y], qi = qks[x][2 * y + 1];
                float kr = Ks[e][2 * y], ki = Ks[e][2 * y + 1];
                ar += qr * kr - qi * ki;
                ai += qr * ki + qi * kr;
            }
            Vs[e][2 * x] = ar;
            Vs[e][2 * x + 1] = ai;
        }
    }
    __syncthreads();
    {
        int m = tid & 63;
        int og = tid >> 6;
#pragma unroll
        for (int j = 0; j < 2; j++) {
            int o = og * 2 + j;
            float ar = 0.f, ai = 0.f;
#pragma unroll
            for (int e = 0; e < 8; e++) {
                float xr = Vs[e][2 * m], xi = Vs[e][2 * m + 1];
                int wix = ((h * 8 + e) * 8 + o) * MZ + m;
                float wrv = wr[wix], wiv = wi[wix];
                ar += xr * wrv - xi * wiv;
                ai += xr * wiv + xi * wrv;
            }
            size_t ro = ((size_t)(b * 64 + h * 8 + o)) * M2 + 2 * m;
            sel[ro] = ar * scale;
            sel[ro + 1] = ai * scale;
        }
    }
}

// ------------------------------------------------------------------ layernorm family
__global__ void ln_row_kernel(const float* __restrict__ X, const float* __restrict__ g,
                              const float* __restrict__ be, float* __restrict__ out) {
    __shared__ float red[256];
    int tid = threadIdx.x;
    int sub = tid >> 6;
    int d = tid & 63;
    int row = blockIdx.x * 4 + sub;
    float v = X[(size_t)row * DZ + d];
    red[tid] = v;
    __syncthreads();
    for (int s = 32; s > 0; s >>= 1) {
        if (d < s) red[tid] += red[tid + s];
        __syncthreads();
    }
    float mu = red[sub * 64] * (1.f / 64.f);
    __syncthreads();
    float dv = v - mu;
    red[tid] = dv * dv;
    __syncthreads();
    for (int s = 32; s > 0; s >>= 1) {
        if (d < s) red[tid] += red[tid + s];
        __syncthreads();
    }
    float var = red[sub * 64] * (1.f / 64.f);
    out[(size_t)row * DZ + d] = dv * rsqrtf(var + 1e-5f) * g[d] + be[d];
}

__global__ void colmean_kernel(const float* __restrict__ X, float* __restrict__ cm) {
    __shared__ float r[256];
    int b = blockIdx.x / DZ, d = blockIdx.x % DZ;
    float s = 0.f;
    for (int t = threadIdx.x; t < LZ; t += 256) s += X[((size_t)(b * LZ + t)) * DZ + d];
    r[threadIdx.x] = s;
    __syncthreads();
    for (int o = 128; o > 0; o >>= 1) {
        if (threadIdx.x < o) r[threadIdx.x] += r[threadIdx.x + o];
        __syncthreads();
    }
    if (threadIdx.x == 0) cm[b * DZ + d] = r[0] * (1.f / LZ);
}

// ------------------------------------------------------------------ final epilogue
__global__ void final_kernel(const float* __restrict__ xln, const float* __restrict__ cm,
                             const float* __restrict__ tacc,
                             const float* __restrict__ tbase, const float* __restrict__ tw,
                             const float* __restrict__ pw, const float* __restrict__ pb,
                             float* __restrict__ out) {
    int idx = blockIdx.x * blockDim.x + threadIdx.x;
    if (idx >= BZ * 512) return;
    int t = idx & 511, b = idx >> 9;
    int tt = t + 512;
    float cv = 0.f;
#pragma unroll
    for (int j = 0; j < 3; j++) {
        int ts = (tt + j - 1) & (LZ - 1);
        const float* row = tacc + ((size_t)(b * LZ + ts)) * DZ;
#pragma unroll 4
        for (int d4 = 0; d4 < 16; d4++) {
            float4 rv = *reinterpret_cast<const float4*>(row + d4 * 4);
            cv += rv.x * tw[(d4 * 4 + 0) * 3 + j] + rv.y * tw[(d4 * 4 + 1) * 3 + j]
                + rv.z * tw[(d4 * 4 + 2) * 3 + j] + rv.w * tw[(d4 * 4 + 3) * 3 + j];
        }
    }
    float p = pb[0];
    const float* xr = xln + ((size_t)(b * LZ + tt)) * DZ;
    const float* cmr = cm + b * DZ;
#pragma unroll 4
    for (int d4 = 0; d4 < 16; d4++) {
        float4 xv = *reinterpret_cast<const float4*>(xr + d4 * 4);
        float4 cvv = *reinterpret_cast<const float4*>(cmr + d4 * 4);
        float4 pv = *reinterpret_cast<const float4*>(pw + d4 * 4);
        p += (xv.x - cvv.x) * pv.x + (xv.y - cvv.y) * pv.y
           + (xv.z - cvv.z) * pv.z + (xv.w - cvv.w) * pv.w;
    }
    out[idx] = p + cv + tbase[b * LZ + tt];
}

static float* symaddr_f(const void* sym) {
    void* p = nullptr;
    cudaGetSymbolAddress(&p, sym);
    return (float*)p;
}

extern "C" void kernel_launch(void* const* d_in, const int* in_sizes, int n_in,
                              void* d_out, int out_size) {
    const float* x_enc       = (const float*)d_in[0];
    const float* dp_w        = (const float*)d_in[1];
    const float* dp_b        = (const float*)d_in[2];
    const float* emb_enc_w   = (const float*)d_in[3];
    const float* emb_dec_w   = (const float*)d_in[4];
    const float* decomp_w    = (const float*)d_in[5];
    const float* decomp_b    = (const float*)d_in[6];
    const float* enc_attn_w  = (const float*)d_in[7];
    const float* enc_attn_b  = (const float*)d_in[8];
    const float* enc_four_wr = (const float*)d_in[9];
    const float* enc_four_wi = (const float*)d_in[10];
    const float* enc_c1      = (const float*)d_in[11];
    const float* enc_c2      = (const float*)d_in[12];
    const float* enc_ln_g    = (const float*)d_in[13];
    const float* enc_ln_b    = (const float*)d_in[14];
    const float* dec_self_w  = (const float*)d_in[15];
    const float* dec_self_b  = (const float*)d_in[16];
    const float* dec_four_wr = (const float*)d_in[17];
    const float* dec_four_wi = (const float*)d_in[18];
    const float* dec_cross_w = (const float*)d_in[19];
    const float* dec_cross_b = (const float*)d_in[20];
    const float* dec_cross_wr= (const float*)d_in[21];
    const float* dec_cross_wi= (const float*)d_in[22];
    const float* dec_c1      = (const float*)d_in[23];
    const float* dec_c2      = (const float*)d_in[24];
    const float* dec_trend_w = (const float*)d_in[25];
    const float* dec_ln_g    = (const float*)d_in[26];
    const float* dec_ln_b    = (const float*)d_in[27];
    const float* dec_proj_w  = (const float*)d_in[28];
    const float* dec_proj_b  = (const float*)d_in[29];
    float* out = (float*)d_out;

    float* px        = symaddr_f(g_x);
    float* pseas0    = symaddr_f(g_seas0);
    float* ptrend0   = symaddr_f(g_trend0);
    float* pseasinit = symaddr_f(g_seasinit);
    float* ph        = symaddr_f(g_h);
    float* py        = symaddr_f(g_y);
    float* pa        = symaddr_f(g_a);
    float* py2       = symaddr_f(g_y2);
    float* pa2       = symaddr_f(g_a2);
    float* pHf       = symaddr_f(g_Hf);
    float* pHf2      = pHf + (size_t)NHE * M2;
    float* pHq       = symaddr_f(g_Hq);
    float* pXf       = symaddr_f(g_Xf);
    float* pXk       = symaddr_f(g_Xk);
    float* psel      = symaddr_f(g_sel);
    float* psel2     = symaddr_f(g_sel2);
    float* pxd       = symaddr_f(g_xd);
    float* ptacc     = symaddr_f(g_tacc);
    float* pcm       = symaddr_f(g_cm);
    float* pcm2      = symaddr_f(g_cm2);
    float* pln       = symaddr_f(g_ln);
    float* pF        = symaddr_f(g_F);
    float* pFi       = symaddr_f(g_Fi);
    float* ptbase    = symaddr_f(g_trendbase);

    cudaFuncSetAttribute(gemm_tc<0>, cudaFuncAttributeMaxDynamicSharedMemorySize, GT_SMEM);
    cudaFuncSetAttribute(gemm_ffn, cudaFuncAttributeMaxDynamicSharedMemorySize, FFN_SMEM);
    cudaFuncSetAttribute(modeproj_mix_kernel, cudaFuncAttributeMaxDynamicSharedMemorySize, MPM_SMEM);

    static cudaStream_t s2 = nullptr;
    static cudaEvent_t evFork = nullptr, evJoin = nullptr;
    if (!s2) {
        cudaStreamCreateWithFlags(&s2, cudaStreamNonBlocking);
        cudaEventCreateWithFlags(&evFork, cudaEventDisableTiming);
        cudaEventCreateWithFlags(&evJoin, cudaEventDisableTiming);
    }

    dim3 dftg(BZ, 2, 4);
    dim3 mpg(BZ, 2);

    // ---- shared prep (stream 0) ----
    build_tables_kernel<<<512, 256>>>();
    transpose_in_kernel<<<1792, 256>>>(x_enc);
    colmean7_kernel<<<BZ * C7, 256>>>(x_enc);
    decomp7_kernel<<<BZ * C7, LZ>>>(px, decomp_w + 0, decomp_b + 0, pseas0, ptrend0);
    trendbase_kernel<<<256, 256>>>(dp_w, dp_b);
    seasinit_kernel<<<1792, 256>>>();
    cudaEventRecord(evFork, 0);

    // ---- decoder prefix + cross-Q path (stream s2) ----
    cudaStreamWaitEvent(s2, evFork, 0);
    embed_kernel<<<16384, 256, 0, s2>>>(pseasinit, emb_dec_w, pxd);
    cudaMemsetAsync(pHf2, 0, (size_t)NHE * M2 * sizeof(float), s2);
    gemm_dft<<<dftg, 128, 0, s2>>>(pxd, pF, pHf2);
    modeproj_mix_kernel<<<mpg, 256, MPM_SMEM, s2>>>(pHf2, dec_self_w + 0, dec_self_b + 0,
                                                    dec_four_wr, dec_four_wi, psel2, 1.0f);
    gemm_tc<0><<<dim3(32, 16), 128, GT_SMEM, s2>>>(psel2, pFi, nullptr, py2, NHE, 128, 1024);
    gemm_tc<0><<<dim3(512, 1), 128, GT_SMEM, s2>>>(py2, dec_self_w + 3 * 4096,
                                                   dec_self_b + 3 * 64, pa2, NROW, 64, 64);
    decomp64_kernel<<<1024, 256, 0, s2>>>(pxd, pa2, decomp_w + 5 * 4, decomp_b + 5 * 4,
                                          pxd, ptacc, 0);
    cudaMemsetAsync(pHq, 0, (size_t)NHE * M2 * sizeof(float), s2);
    gemm_dft<<<dftg, 128, 0, s2>>>(pxd, pF, pHq);
    modeproj_kernel<<<mpg, 256, 0, s2>>>(pHq, dec_cross_w + 0, dec_cross_b + 0, nullptr, pXf);
    cudaEventRecord(evJoin, s2);

    // ---- encoder (stream 0) ----
    embed_kernel<<<16384, 256>>>(px, emb_enc_w, ph);
    for (int l = 0; l < 2; l++) {
        const float* wq = enc_attn_w + (size_t)(l * 4 + 0) * 4096;
        const float* bq = enc_attn_b + (size_t)(l * 4 + 0) * 64;
        const float* wo = enc_attn_w + (size_t)(l * 4 + 3) * 4096;
        const float* bo = enc_attn_b + (size_t)(l * 4 + 3) * 64;
        cudaMemsetAsync(pHf, 0, (size_t)NHE * M2 * sizeof(float));
        gemm_dft<<<dftg, 128>>>(ph, pF, pHf);
        modeproj_mix_kernel<<<mpg, 256, MPM_SMEM>>>(pHf, wq, bq,
                                                    enc_four_wr + (size_t)l * 32768,
                                                    enc_four_wi + (size_t)l * 32768, psel, 1.0f);
        gemm_tc<0><<<dim3(32, 16), 128, GT_SMEM>>>(psel, pFi, nullptr, py, NHE, 128, 1024);
        gemm_tc<0><<<dim3(512, 1), 128, GT_SMEM>>>(py, wo, bo, pa, NROW, 64, 64);
        decomp64_kernel<<<1024, 256>>>(ph, pa, decomp_w + (1 + 2 * l) * 4,
                                       decomp_b + (1 + 2 * l) * 4, ph, nullptr, 0);
        gemm_ffn<<<512, 128, FFN_SMEM>>>(ph, enc_c1 + (size_t)l * 16384,
                                         enc_c2 + (size_t)l * 16384, py);
        decomp64_kernel<<<1024, 256>>>(ph, py, decomp_w + (2 + 2 * l) * 4,
                                       decomp_b + (2 + 2 * l) * 4, ph, nullptr, 0);
    }
    ln_row_kernel<<<16384, 256>>>(ph, enc_ln_g, enc_ln_b, ph);
    colmean_kernel<<<BZ * DZ, 256>>>(ph, pcm2);

    // ---- cross-attention K path (stream 0, encoder-only deps) ----
    cudaMemsetAsync(pHf, 0, (size_t)NHE * M2 * sizeof(float));
    gemm_dft<<<dftg, 128>>>(ph, pF, pHf);
    modeproj_kernel<<<mpg, 256>>>(pHf, dec_cross_w + 1 * 4096, dec_cross_b + 1 * 64, pcm2, pXk);

    // ---- join, then cross attention core ----
    cudaStreamWaitEvent(0, evJoin, 0);
    qkattn_kernel<<<512, 256>>>(pXf, pXk, dec_cross_wr, dec_cross_wi, psel, 1.0f / 4096.0f);
    gemm_tc<0><<<dim3(32, 16), 128, GT_SMEM>>>(psel, pFi, nullptr, py, NHE, 128, 1024);
    gemm_tc<0><<<dim3(512, 1), 128, GT_SMEM>>>(py, dec_cross_w + 3 * 4096, dec_cross_b + 3 * 64, pa,
                                               NROW, 64, 64);
    decomp64_kernel<<<1024, 256>>>(pxd, pa, decomp_w + 6 * 4, decomp_b + 6 * 4, pxd, ptacc, 1);

    gemm_ffn<<<512, 128, FFN_SMEM>>>(pxd, dec_c1, dec_c2, py);
    decomp64_kernel<<<1024, 256>>>(pxd, py, decomp_w + 7 * 4, decomp_b + 7 * 4, pxd, ptacc, 1);

    ln_row_kernel<<<16384, 256>>>(pxd, dec_ln_g, dec_ln_b, pln);
    colmean_kernel<<<BZ * DZ, 256>>>(pln, pcm);
    final_kernel<<<128, 256>>>(pln, pcm, ptacc, ptbase, dec_trend_w, dec_proj_w, dec_proj_b, out);
}

// round 17
// speedup vs baseline: 1.0860x; 1.0337x over previous
#include <cuda_runtime.h>
#include <cstdint>

#define BZ 64
#define LZ 1024
#define DZ 64
#define C7 7
#define HZ 8
#define EZ 8
#define MZ 64
#define M2 128
#define DFFD 256
#define NROW (BZ*LZ)
#define NHE  (BZ*DZ)

__device__ float g_x[BZ*LZ*C7];
__device__ float g_seas0[BZ*LZ*C7];
__device__ float g_trend0[BZ*LZ*C7];
__device__ float g_mean7[BZ*C7];
__device__ float g_trendbase[BZ*LZ];
__device__ float g_seasinit[BZ*LZ*C7];
__device__ float g_h[NROW*DZ];
__device__ float g_y[NROW*DZ];
__device__ float g_a[NROW*DZ];
__device__ float g_y2[NROW*DZ];
__device__ float g_a2[NROW*DZ];
__device__ float g_Hf[2*NHE*M2];
__device__ float g_Hq[NHE*M2];
__device__ float g_Xf[NHE*M2];
__device__ float g_Xk[NHE*M2];
__device__ float g_sel[NHE*M2];
__device__ float g_sel2[NHE*M2];
__device__ float g_xd[NROW*DZ];
__device__ float g_tacc[NROW*DZ];
__device__ float g_cm[BZ*DZ];
__device__ float g_cm2[BZ*DZ];
__device__ float g_ln[NROW*DZ];
__device__ float g_F[M2*LZ];
__device__ float g_Fi[LZ*M2];
__device__ float g_pe[LZ*DZ];

// ------------------------------------------------------------------ tables
__global__ void build_tables_kernel() {
    int idx = blockIdx.x * blockDim.x + threadIdx.x;
    if (idx < LZ * M2) {
        int t = idx >> 7;
        int m2 = idx & 127;
        int m = m2 >> 1;
        int r = (m * t) & (LZ - 1);
        float a = (float)r * (6.28318530717958647692f / (float)LZ);
        float s, c;
        sincosf(a, &s, &c);
        float v = (m2 & 1) ? -s : c;
        g_F[(size_t)m2 * LZ + t] = v;
        float cm = (m == 0) ? 1.f : 2.f;
        g_Fi[(size_t)t * M2 + m2] = v * (cm / (float)LZ);
    }
    if (idx < LZ * DZ) {
        int o = idx & 63;
        int t = idx >> 6;
        int i2 = o & ~1;
        float div = expf(-(float)i2 * 0.14391156831212793f);
        float arg = (float)t * div;
        g_pe[idx] = (o & 1) ? cosf(arg) : sinf(arg);
    }
}

// ------------------------------------------------------------------ input prep
__global__ void transpose_in_kernel(const float* __restrict__ xe) {
    int idx = blockIdx.x * blockDim.x + threadIdx.x;
    if (idx >= BZ * C7 * LZ) return;
    int t = idx & 1023;
    int c = (idx >> 10) % C7;
    int b = idx / (C7 * LZ);
    g_x[((size_t)(b * LZ + t)) * C7 + c] = xe[idx];
}

__global__ void colmean7_kernel(const float* __restrict__ xe) {
    __shared__ float r[256];
    int bc = blockIdx.x;
    float s = 0.f;
    for (int t = threadIdx.x; t < LZ; t += 256) s += xe[(size_t)bc * LZ + t];
    r[threadIdx.x] = s;
    __syncthreads();
    for (int o = 128; o > 0; o >>= 1) {
        if (threadIdx.x < o) r[threadIdx.x] += r[threadIdx.x + o];
        __syncthreads();
    }
    if (threadIdx.x == 0) g_mean7[bc] = r[0] * (1.f / LZ);
}

// ------------------------------------------------------------------ decomp7
__global__ void decomp7_kernel(const float* __restrict__ A,
                               const float* __restrict__ w4, const float* __restrict__ b4,
                               float* __restrict__ seas, float* __restrict__ trend) {
    __shared__ float ps[LZ];
    __shared__ float wsum[32];
    __shared__ float sx0, sxN;
    int c = blockIdx.x % C7, b = blockIdx.x / C7;
    int t = threadIdx.x, lane = t & 31, wid = t >> 5;
    size_t idx = ((size_t)(b * LZ + t)) * C7 + c;
    float x = A[idx];
    float s = x;
#pragma unroll
    for (int off = 1; off < 32; off <<= 1) {
        float v = __shfl_up_sync(0xffffffffu, s, off);
        if (lane >= off) s += v;
    }
    if (lane == 31) wsum[wid] = s;
    if (t == 0) sx0 = x;
    if (t == LZ - 1) sxN = x;
    __syncthreads();
    if (wid == 0) {
        float v = wsum[lane];
#pragma unroll
        for (int off = 1; off < 32; off <<= 1) {
            float u = __shfl_up_sync(0xffffffffu, v, off);
            if (lane >= off) v += u;
        }
        wsum[lane] = v;
    }
    __syncthreads();
    if (wid > 0) s += wsum[wid - 1];
    ps[t] = s;
    __syncthreads();
    float x0 = sx0, xN = sxN;
    const int ks[4] = {10, 50, 100, 500};
    float ma[4];
#pragma unroll
    for (int kk = 0; kk < 4; kk++) {
        int k = ks[kk], f = (k - 1) >> 1, e = k >> 1;
        int lo = t - f, hi = t + e;
        int cl = lo < 0 ? 0 : lo, ch = hi > LZ - 1 ? LZ - 1 : hi;
        float sw = ps[ch] - (cl > 0 ? ps[cl - 1] : 0.f)
                 + (float)(cl - lo) * x0 + (float)(hi - ch) * xN;
        ma[kk] = sw / (float)k;
    }
    float z[4], mx = -1e30f;
#pragma unroll
    for (int kk = 0; kk < 4; kk++) { z[kk] = x * w4[kk] + b4[kk]; mx = fmaxf(mx, z[kk]); }
    float se = 0.f, mean = 0.f;
#pragma unroll
    for (int kk = 0; kk < 4; kk++) { float e2 = __expf(z[kk] - mx); se += e2; mean += ma[kk] * e2; }
    mean /= se;
    seas[idx] = x - mean;
    trend[idx] = mean;
}

__device__ __forceinline__ float4 f4add(float4 a, float4 b) {
    return make_float4(a.x + b.x, a.y + b.y, a.z + b.z, a.w + b.w);
}

// ------------------------------------------------------------------ decomp64
__global__ __launch_bounds__(256) void decomp64_kernel(
    const float* __restrict__ A, const float* __restrict__ Bb,
    const float* __restrict__ w4, const float* __restrict__ b4,
    float* __restrict__ seas, float* __restrict__ trend, int accum) {
    __shared__ float4 ps[LZ];
    __shared__ float4 wsum[8];
    __shared__ float4 sedge[2];
    int c4 = blockIdx.x & 15, b = blockIdx.x >> 4;
    int tid = threadIdx.x, lane = tid & 31, wid = tid >> 5;
    int t4 = tid * 4;
    size_t base = ((size_t)(b * LZ + t4)) * DZ + c4 * 4;

    float4 x[4], p[4];
#pragma unroll
    for (int j = 0; j < 4; j++) {
        x[j] = *reinterpret_cast<const float4*>(A + base + (size_t)j * DZ);
        if (Bb) x[j] = f4add(x[j], *reinterpret_cast<const float4*>(Bb + base + (size_t)j * DZ));
    }
    p[0] = x[0];
#pragma unroll
    for (int j = 1; j < 4; j++) p[j] = f4add(p[j - 1], x[j]);

    float4 s = p[3];
#pragma unroll
    for (int off = 1; off < 32; off <<= 1) {
        float4 v;
        v.x = __shfl_up_sync(0xffffffffu, s.x, off);
        v.y = __shfl_up_sync(0xffffffffu, s.y, off);
        v.z = __shfl_up_sync(0xffffffffu, s.z, off);
        v.w = __shfl_up_sync(0xffffffffu, s.w, off);
        if (lane >= off) s = f4add(s, v);
    }
    if (lane == 31) wsum[wid] = s;
    if (tid == 0) sedge[0] = x[0];
    if (tid == 255) sedge[1] = x[3];
    __syncthreads();
    if (wid == 0 && lane < 8) {
        float4 v = wsum[lane];
#pragma unroll
        for (int off = 1; off < 8; off <<= 1) {
            float4 u;
            u.x = __shfl_up_sync(0xffu, v.x, off);
            u.y = __shfl_up_sync(0xffu, v.y, off);
            u.z = __shfl_up_sync(0xffu, v.z, off);
            u.w = __shfl_up_sync(0xffu, v.w, off);
            if (lane >= off) v = f4add(v, u);
        }
        wsum[lane] = v;
    }
    __syncthreads();
    float4 ex = make_float4(0.f, 0.f, 0.f, 0.f);
    if (wid > 0) ex = wsum[wid - 1];
    {
        float4 d;
        d.x = s.x - p[3].x; d.y = s.y - p[3].y; d.z = s.z - p[3].z; d.w = s.w - p[3].w;
        ex = f4add(ex, d);
    }
#pragma unroll
    for (int j = 0; j < 4; j++) ps[t4 + j] = f4add(ex, p[j]);
    __syncthreads();

    float4 x0 = sedge[0], xN = sedge[1];
    const int ks[4] = {10, 50, 100, 500};
#pragma unroll
    for (int j = 0; j < 4; j++) {
        int t = t4 + j;
        float ma[4][4];
#pragma unroll
        for (int kk = 0; kk < 4; kk++) {
            int k = ks[kk], f = (k - 1) >> 1, e = k >> 1;
            int lo = t - f, hi = t + e;
            int cl = lo < 0 ? 0 : lo, ch = hi > LZ - 1 ? LZ - 1 : hi;
            float4 pc = ps[ch];
            float4 pl = make_float4(0.f, 0.f, 0.f, 0.f);
            if (cl > 0) pl = ps[cl - 1];
            float fl = (float)(cl - lo), fr = (float)(hi - ch);
            float inv = 1.f / (float)k;
            ma[kk][0] = (pc.x - pl.x + fl * x0.x + fr * xN.x) * inv;
            ma[kk][1] = (pc.y - pl.y + fl * x0.y + fr * xN.y) * inv;
            ma[kk][2] = (pc.z - pl.z + fl * x0.z + fr * xN.z) * inv;
            ma[kk][3] = (pc.w - pl.w + fl * x0.w + fr * xN.w) * inv;
        }
        float xa[4] = {x[j].x, x[j].y, x[j].z, x[j].w};
        float so[4], tr[4];
#pragma unroll
        for (int cc = 0; cc < 4; cc++) {
            float z[4], mx = -1e30f;
#pragma unroll
            for (int kk = 0; kk < 4; kk++) { z[kk] = xa[cc] * w4[kk] + b4[kk]; mx = fmaxf(mx, z[kk]); }
            float se = 0.f, mean = 0.f;
#pragma unroll
            for (int kk = 0; kk < 4; kk++) { float e2 = __expf(z[kk] - mx); se += e2; mean += ma[kk][cc] * e2; }
            mean /= se;
            so[cc] = xa[cc] - mean;
            tr[cc] = mean;
        }
        *reinterpret_cast<float4*>(seas + base + (size_t)j * DZ) =
            make_float4(so[0], so[1], so[2], so[3]);
        if (trend) {
            float4 tv = make_float4(tr[0], tr[1], tr[2], tr[3]);
            if (accum) {
                float4 old = *reinterpret_cast<float4*>(trend + base + (size_t)j * DZ);
                tv = f4add(tv, old);
            }
            *reinterpret_cast<float4*>(trend + base + (size_t)j * DZ) = tv;
        }
    }
}

// ------------------------------------------------------------------ trend + seasonal init (merged)
__global__ void initdec_kernel(const float* __restrict__ dpw, const float* __restrict__ dpb) {
    int idx = blockIdx.x * blockDim.x + threadIdx.x;
    if (idx >= BZ * LZ * C7) return;
    int c = idx % C7;
    int t = (idx / C7) & 1023;
    int b = idx / (C7 * LZ);
    g_seasinit[idx] = (t < 512) ? g_seas0[((size_t)(b * LZ + 512 + t)) * C7 + c] : 0.f;
    if (c == 0) {
        float s = dpb[0];
#pragma unroll
        for (int cc = 0; cc < C7; cc++) {
            float v = (t < 512) ? g_trend0[((size_t)(b * LZ + 512 + t)) * C7 + cc]
                                : g_mean7[b * C7 + cc];
            s += v * dpw[cc];
        }
        g_trendbase[b * LZ + t] = s;
    }
}

// ------------------------------------------------------------------ embedding
__global__ void embed_kernel(const float* __restrict__ in, const float* __restrict__ w,
                             float* __restrict__ out) {
    int idx = blockIdx.x * blockDim.x + threadIdx.x;
    if (idx >= BZ * LZ * DZ) return;
    int o = idx & 63;
    int t = (idx >> 6) & 1023;
    int b = idx >> 16;
    float s = 0.f;
#pragma unroll
    for (int j = 0; j < 3; j++) {
        int ts = (t + j - 1 + LZ) & (LZ - 1);
        const float* ip = in + ((size_t)(b * LZ + ts)) * C7;
#pragma unroll
        for (int c = 0; c < C7; c++) s += ip[c] * w[(o * C7 + c) * 3 + j];
    }
    out[idx] = s + g_pe[(t << 6) + o];
}

// ------------------------------------------------------------------ tf32 helpers
__device__ __forceinline__ uint32_t to_tf32(float x) {
    uint32_t r;
    asm("cvt.rna.tf32.f32 %0, %1;" : "=r"(r) : "f"(x));
    return r;
}
__device__ __forceinline__ void cpa16(uint32_t s, const float* g) {
    asm volatile("cp.async.ca.shared.global [%0], [%1], 16;" :: "r"(s), "l"(g));
}
__device__ __forceinline__ void cpa_commit() {
    asm volatile("cp.async.commit_group;");
}
__device__ __forceinline__ void cpa_wait1() {
    asm volatile("cp.async.wait_group 1;");
}
__device__ __forceinline__ void mma_tf32(float* acc, const uint32_t* a, const uint32_t* bf) {
    asm volatile(
        "mma.sync.aligned.m16n8k8.row.col.f32.tf32.tf32.f32 "
        "{%0,%1,%2,%3}, {%4,%5,%6,%7}, {%8,%9}, {%0,%1,%2,%3};"
        : "+f"(acc[0]), "+f"(acc[1]), "+f"(acc[2]), "+f"(acc[3])
        : "r"(a[0]), "r"(a[1]), "r"(a[2]), "r"(a[3]), "r"(bf[0]), "r"(bf[1]));
}

// ------------------------------------------------------------------ tf32 GEMM
#define GT_ASTRIDE (128*36)
#define GT_BSTRIDE (64*36)
#define GT_SMEM ((2*GT_ASTRIDE + 2*GT_BSTRIDE) * 4)

template <int ACT>
__global__ __launch_bounds__(128) void gemm_tc(const float* __restrict__ A,
                                               const float* __restrict__ W,
                                               const float* __restrict__ bias,
                                               float* __restrict__ C,
                                               int N, int K, int O) {
    extern __shared__ float dsm[];
    float* As = dsm;
    float* Bs = dsm + 2 * GT_ASTRIDE;
    const int rb = blockIdx.x * 128;
    const int cb = blockIdx.y * 64;
    const int tid = threadIdx.x;
    const int lane = tid & 31;
    const int w = tid >> 5;
    const int wm = w & 1, wn = w >> 1;
    const int m0 = wm * 64, n0 = wn * 32;
    const int g = lane >> 2, tg = lane & 3;
    const int lrow = tid >> 3;
    const int lcol = (tid & 7) * 4;

    uint32_t sA = (uint32_t)__cvta_generic_to_shared(As);
    uint32_t sB = (uint32_t)__cvta_generic_to_shared(Bs);

    float acc[4][4][4];
#pragma unroll
    for (int mi = 0; mi < 4; mi++)
#pragma unroll
        for (int ni = 0; ni < 4; ni++)
#pragma unroll
            for (int r = 0; r < 4; r++) acc[mi][ni][r] = 0.f;

#pragma unroll
    for (int r = 0; r < 8; r++) {
        int row = lrow + r * 16;
        cpa16(sA + (uint32_t)((row * 36 + lcol) * 4), A + (size_t)(rb + row) * K + lcol);
    }
#pragma unroll
    for (int r = 0; r < 4; r++) {
        int row = lrow + r * 16;
        cpa16(sB + (uint32_t)((row * 36 + lcol) * 4), W + (size_t)(cb + row) * K + lcol);
    }
    cpa_commit();

    int st = 0;
    for (int k0 = 0; k0 < K; k0 += 32, st ^= 1) {
        if (k0 + 32 < K) {
            int nx = st ^ 1;
#pragma unroll
            for (int r = 0; r < 8; r++) {
                int row = lrow + r * 16;
                cpa16(sA + (uint32_t)((nx * GT_ASTRIDE + row * 36 + lcol) * 4),
                      A + (size_t)(rb + row) * K + k0 + 32 + lcol);
            }
#pragma unroll
            for (int r = 0; r < 4; r++) {
                int row = lrow + r * 16;
                cpa16(sB + (uint32_t)((nx * GT_BSTRIDE + row * 36 + lcol) * 4),
                      W + (size_t)(cb + row) * K + k0 + 32 + lcol);
            }
        }
        cpa_commit();
        cpa_wait1();
        __syncthreads();
        const float* Ast = As + st * GT_ASTRIDE;
        const float* Bst = Bs + st * GT_BSTRIDE;
#pragma unroll
        for (int kk = 0; kk < 32; kk += 8) {
            uint32_t a[4][4], bfr[4][2];
#pragma unroll
            for (int mi = 0; mi < 4; mi++) {
                int r = m0 + mi * 16 + g;
                a[mi][0] = to_tf32(Ast[r * 36 + kk + tg]);
                a[mi][1] = to_tf32(Ast[(r + 8) * 36 + kk + tg]);
                a[mi][2] = to_tf32(Ast[r * 36 + kk + tg + 4]);
                a[mi][3] = to_tf32(Ast[(r + 8) * 36 + kk + tg + 4]);
            }
#pragma unroll
            for (int ni = 0; ni < 4; ni++) {
                int c = n0 + ni * 8 + g;
                bfr[ni][0] = to_tf32(Bst[c * 36 + kk + tg]);
                bfr[ni][1] = to_tf32(Bst[c * 36 + kk + tg + 4]);
            }
#pragma unroll
            for (int mi = 0; mi < 4; mi++)
#pragma unroll
                for (int ni = 0; ni < 4; ni++)
                    mma_tf32(acc[mi][ni], a[mi], bfr[ni]);
        }
        __syncthreads();
    }
#pragma unroll
    for (int mi = 0; mi < 4; mi++) {
        int row0 = rb + m0 + mi * 16 + g;
#pragma unroll
        for (int ni = 0; ni < 4; ni++) {
            int col = cb + n0 + ni * 8 + 2 * tg;
#pragma unroll
            for (int half = 0; half < 2; half++) {
                int row = row0 + half * 8;
                float v0 = acc[mi][ni][half * 2 + 0];
                float v1 = acc[mi][ni][half * 2 + 1];
                if (bias) { v0 += bias[col]; v1 += bias[col + 1]; }
                if (ACT == 1) {
                    v0 = 0.5f * v0 * (1.f + erff(v0 * 0.70710678118654752f));
                    v1 = 0.5f * v1 * (1.f + erff(v1 * 0.70710678118654752f));
                }
                C[(size_t)row * O + col] = v0;
                C[(size_t)row * O + col + 1] = v1;
            }
        }
    }
}

// ------------------------------------------------------------------ fused FFN
#define FFN_AS  (128*68)
#define FFN_WS  (64*68)
#define FFN_PS  (128*68)
#define FFN_SMEM ((FFN_AS + 2*FFN_WS + FFN_PS) * 4)

__global__ __launch_bounds__(128) void gemm_ffn(const float* __restrict__ A,
                                                const float* __restrict__ W1,
                                                const float* __restrict__ W2,
                                                float* __restrict__ C) {
    extern __shared__ float sm[];
    float* As  = sm;
    float* Ws1 = sm + FFN_AS;
    float* Ws2 = sm + FFN_AS + FFN_WS;
    float* Ps  = sm + FFN_AS + 2 * FFN_WS;
    const int rb = blockIdx.x * 128;
    const int tid = threadIdx.x;
    const int lane = tid & 31;
    const int w = tid >> 5;
    const int wm = w & 1, wn = w >> 1;
    const int m0 = wm * 64, n0 = wn * 32;
    const int g = lane >> 2, tg = lane & 3;

    for (int i = tid; i < 128 * 16; i += 128) {
        int row = i >> 4;
        int c4 = (i & 15) * 4;
        *reinterpret_cast<float4*>(&As[row * 68 + c4]) =
            *reinterpret_cast<const float4*>(A + (size_t)(rb + row) * 64 + c4);
    }

    float acc[4][4][4];
#pragma unroll
    for (int mi = 0; mi < 4; mi++)
#pragma unroll
        for (int ni = 0; ni < 4; ni++)
#pragma unroll
            for (int r = 0; r < 4; r++) acc[mi][ni][r] = 0.f;

    for (int ch = 0; ch < 4; ch++) {
        __syncthreads();
        for (int i = tid; i < 64 * 16; i += 128) {
            int row = i >> 4;
            int c4 = (i & 15) * 4;
            *reinterpret_cast<float4*>(&Ws1[row * 68 + c4]) =
                *reinterpret_cast<const float4*>(W1 + (size_t)(ch * 64 + row) * 64 + c4);
            *reinterpret_cast<float4*>(&Ws2[row * 68 + c4]) =
                *reinterpret_cast<const float4*>(W2 + (size_t)row * 256 + ch * 64 + c4);
        }
        __syncthreads();
        float p1[4][4][4];
#pragma unroll
        for (int mi = 0; mi < 4; mi++)
#pragma unroll
            for (int ni = 0; ni < 4; ni++)
#pragma unroll
                for (int r = 0; r < 4; r++) p1[mi][ni][r] = 0.f;
#pragma unroll
        for (int kk = 0; kk < 64; kk += 8) {
            uint32_t a[4][4], bfr[4][2];
#pragma unroll
            for (int mi = 0; mi < 4; mi++) {
                int r = m0 + mi * 16 + g;
                a[mi][0] = to_tf32(As[r * 68 + kk + tg]);
                a[mi][1] = to_tf32(As[(r + 8) * 68 + kk + tg]);
                a[mi][2] = to_tf32(As[r * 68 + kk + tg + 4]);
                a[mi][3] = to_tf32(As[(r + 8) * 68 + kk + tg + 4]);
            }
#pragma unroll
            for (int ni = 0; ni < 4; ni++) {
                int c = n0 + ni * 8 + g;
                bfr[ni][0] = to_tf32(Ws1[c * 68 + kk + tg]);
                bfr[ni][1] = to_tf32(Ws1[c * 68 + kk + tg + 4]);
            }
#pragma unroll
            for (int mi = 0; mi < 4; mi++)
#pragma unroll
                for (int ni = 0; ni < 4; ni++)
                    mma_tf32(p1[mi][ni], a[mi], bfr[ni]);
        }
#pragma unroll
        for (int mi = 0; mi < 4; mi++) {
            int row0 = m0 + mi * 16 + g;
#pragma unroll
            for (int ni = 0; ni < 4; ni++) {
                int col = n0 + ni * 8 + 2 * tg;
#pragma unroll
                for (int half = 0; half < 2; half++) {
                    int row = row0 + half * 8;
                    float v0 = p1[mi][ni][half * 2 + 0];
                    float v1 = p1[mi][ni][half * 2 + 1];
                    v0 = 0.5f * v0 * (1.f + erff(v0 * 0.70710678118654752f));
                    v1 = 0.5f * v1 * (1.f + erff(v1 * 0.70710678118654752f));
                    Ps[row * 68 + col] = v0;
                    Ps[row * 68 + col + 1] = v1;
                }
            }
        }
        __syncthreads();
#pragma unroll
        for (int kk = 0; kk < 64; kk += 8) {
            uint32_t a[4][4], bfr[4][2];
#pragma unroll
            for (int mi = 0; mi < 4; mi++) {
                int r = m0 + mi * 16 + g;
                a[mi][0] = to_tf32(Ps[r * 68 + kk + tg]);
                a[mi][1] = to_tf32(Ps[(r + 8) * 68 + kk + tg]);
                a[mi][2] = to_tf32(Ps[r * 68 + kk + tg + 4]);
                a[mi][3] = to_tf32(Ps[(r + 8) * 68 + kk + tg + 4]);
            }
#pragma unroll
            for (int ni = 0; ni < 4; ni++) {
                int c = n0 + ni * 8 + g;
                bfr[ni][0] = to_tf32(Ws2[c * 68 + kk + tg]);
                bfr[ni][1] = to_tf32(Ws2[c * 68 + kk + tg + 4]);
            }
#pragma unroll
            for (int mi = 0; mi < 4; mi++)
#pragma unroll
                for (int ni = 0; ni < 4; ni++)
                    mma_tf32(acc[mi][ni], a[mi], bfr[ni]);
        }
    }
#pragma unroll
    for (int mi = 0; mi < 4; mi++) {
        int row0 = rb + m0 + mi * 16 + g;
#pragma unroll
        for (int ni = 0; ni < 4; ni++) {
            int col = n0 + ni * 8 + 2 * tg;
#pragma unroll
            for (int half = 0; half < 2; half++) {
                int row = row0 + half * 8;
                C[(size_t)row * 64 + col] = acc[mi][ni][half * 2 + 0];
                C[(size_t)row * 64 + col + 1] = acc[mi][ni][half * 2 + 1];
            }
        }
    }
}

// ------------------------------------------------------------------ DFT GEMM with fused transpose (reg-prefetch)
__device__ __forceinline__ void dft_body(const float* __restrict__ Aq,
                                         const float* __restrict__ F,
                                         float* __restrict__ X,
                                         int b, int cb, int zz) {
    __shared__ float As[64][33];
    __shared__ float Bs[64][36];
    const int tbase = zz * 256;
    const int tid = threadIdx.x;
    const int lane = tid & 31;
    const int w = tid >> 5;
    const int wm = w & 1, wn = w >> 1;
    const int m0 = wm * 32, n0 = wn * 32;
    const int g = lane >> 2, tg = lane & 3;
    const int lrow = tid >> 3;
    const int lcol = (tid & 7) * 4;

    float acc[2][4][4];
#pragma unroll
    for (int mi = 0; mi < 2; mi++)
#pragma unroll
        for (int ni = 0; ni < 4; ni++)
#pragma unroll
            for (int r = 0; r < 4; r++) acc[mi][ni][r] = 0.f;

    float4 va[4], vb[4];
#pragma unroll
    for (int i = 0; i < 4; i++) {
        int f4 = i * 128 + tid;
        int tl = f4 >> 4;
        int he = (f4 & 15) * 4;
        va[i] = *reinterpret_cast<const float4*>(Aq + ((size_t)(b * LZ + tbase + tl)) * DZ + he);
    }
#pragma unroll
    for (int r = 0; r < 4; r++) {
        int row = lrow + r * 16;
        vb[r] = *reinterpret_cast<const float4*>(F + (size_t)(cb + row) * LZ + tbase + lcol);
    }

    for (int it = 0; it < 8; it++) {
        int t0 = tbase + it * 32;
#pragma unroll
        for (int i = 0; i < 4; i++) {
            int f4 = i * 128 + tid;
            int tl = f4 >> 4;
            int he = (f4 & 15) * 4;
            As[he + 0][tl] = va[i].x;
            As[he + 1][tl] = va[i].y;
            As[he + 2][tl] = va[i].z;
            As[he + 3][tl] = va[i].w;
        }
#pragma unroll
        for (int r = 0; r < 4; r++) {
            int row = lrow + r * 16;
            *reinterpret_cast<float4*>(&Bs[row][lcol]) = vb[r];
        }
        __syncthreads();
        float4 na[4], nb[4];
        if (it < 7) {
#pragma unroll
            for (int i = 0; i < 4; i++) {
                int f4 = i * 128 + tid;
                int tl = f4 >> 4;
                int he = (f4 & 15) * 4;
                na[i] = *reinterpret_cast<const float4*>(
                    Aq + ((size_t)(b * LZ + t0 + 32 + tl)) * DZ + he);
            }
#pragma unroll
            for (int r = 0; r < 4; r++) {
                int row = lrow + r * 16;
                nb[r] = *reinterpret_cast<const float4*>(
                    F + (size_t)(cb + row) * LZ + t0 + 32 + lcol);
            }
        }
#pragma unroll
        for (int kk = 0; kk < 32; kk += 8) {
            uint32_t a[2][4], bfr[4][2];
#pragma unroll
            for (int mi = 0; mi < 2; mi++) {
                int r = m0 + mi * 16 + g;
                a[mi][0] = to_tf32(As[r][kk + tg]);
                a[mi][1] = to_tf32(As[r + 8][kk + tg]);
                a[mi][2] = to_tf32(As[r][kk + tg + 4]);
                a[mi][3] = to_tf32(As[r + 8][kk + tg + 4]);
            }
#pragma unroll
            for (int ni = 0; ni < 4; ni++) {
                int c = n0 + ni * 8 + g;
                bfr[ni][0] = to_tf32(Bs[c][kk + tg]);
                bfr[ni][1] = to_tf32(Bs[c][kk + tg + 4]);
            }
#pragma unroll
            for (int mi = 0; mi < 2; mi++)
#pragma unroll
                for (int ni = 0; ni < 4; ni++)
                    mma_tf32(acc[mi][ni], a[mi], bfr[ni]);
        }
        __syncthreads();
        if (it < 7) {
#pragma unroll
            for (int i = 0; i < 4; i++) va[i] = na[i];
#pragma unroll
            for (int r = 0; r < 4; r++) vb[r] = nb[r];
        }
    }
#pragma unroll
    for (int mi = 0; mi < 2; mi++) {
        int r0 = m0 + mi * 16 + g;
#pragma unroll
        for (int ni = 0; ni < 4; ni++) {
            int col = cb + n0 + ni * 8 + 2 * tg;
#pragma unroll
            for (int half = 0; half < 2; half++) {
                int row = r0 + half * 8;
                atomicAdd(&X[(size_t)(b * 64 + row) * M2 + col], acc[mi][ni][half * 2 + 0]);
                atomicAdd(&X[(size_t)(b * 64 + row) * M2 + col + 1], acc[mi][ni][half * 2 + 1]);
            }
        }
    }
}

__global__ __launch_bounds__(128) void gemm_dft(const float* __restrict__ Aq,
                                                const float* __restrict__ F,
                                                float* __restrict__ X) {
    dft_body(Aq, F, X, blockIdx.x, blockIdx.y * 64, blockIdx.z);
}

// ------------------------------------------------------------------ mode-space projection (cross path)
__global__ __launch_bounds__(256) void modeproj_kernel(const float* __restrict__ Hf,
                                                       const float* __restrict__ Wq,
                                                       const float* __restrict__ bq,
                                                       const float* __restrict__ cm,
                                                       float* __restrict__ Qf) {
    __shared__ float Hs[64][68];
    __shared__ float Ws[64][68];
    int b = blockIdx.x;
    int mh = blockIdx.y;
    int tid = threadIdx.x;
    for (int i = tid; i < 64 * 16; i += 256) {
        int d = i >> 4;
        int c4 = (i & 15) * 4;
        *reinterpret_cast<float4*>(&Hs[d][c4]) =
            *reinterpret_cast<const float4*>(Hf + ((size_t)(b * 64 + d)) * M2 + mh * 64 + c4);
    }
    for (int i = tid; i < 64 * 16; i += 256) {
        int he = i >> 4;
        int c4 = (i & 15) * 4;
        *reinterpret_cast<float4*>(&Ws[he][c4]) =
            *reinterpret_cast<const float4*>(Wq + he * 64 + c4);
    }
    __syncthreads();
    if (cm && mh == 0 && tid < 64) Hs[tid][0] -= cm[b * 64 + tid] * 1024.f;
    __syncthreads();
    int he = tid >> 2;
    int mg = tid & 3;
#pragma unroll
    for (int j = 0; j < 16; j++) {
        int ml = mg + 4 * j;
        float s = 0.f;
#pragma unroll
        for (int d = 0; d < 64; d++) s += Ws[he][d] * Hs[d][ml];
        int m2 = mh * 64 + ml;
        if (m2 == 0) s += bq[he] * 1024.f;
        Qf[((size_t)(b * 64 + he)) * M2 + m2] = s;
    }
}

// ------------------------------------------------------------------ fused modeproj + mode_mix (self-attn)
#define MPM_SMEM ((2*64*68 + 64*66) * 4)
__global__ __launch_bounds__(256) void modeproj_mix_kernel(const float* __restrict__ Hf,
                                                           const float* __restrict__ Wq,
                                                           const float* __restrict__ bq,
                                                           const float* __restrict__ wr,
                                                           const float* __restrict__ wi,
                                                           float* __restrict__ sel,
                                                           float scale) {
    extern __shared__ float sm[];
    float* Hs = sm;
    float* Ws = sm + 64 * 68;
    float* Qs = sm + 2 * 64 * 68;
    int b = blockIdx.x;
    int mh = blockIdx.y;
    int tid = threadIdx.x;
    for (int i = tid; i < 64 * 16; i += 256) {
        int d = i >> 4;
        int c4 = (i & 15) * 4;
        *reinterpret_cast<float4*>(&Hs[d * 68 + c4]) =
            *reinterpret_cast<const float4*>(Hf + ((size_t)(b * 64 + d)) * M2 + mh * 64 + c4);
    }
    for (int i = tid; i < 64 * 16; i += 256) {
        int he = i >> 4;
        int c4 = (i & 15) * 4;
        *reinterpret_cast<float4*>(&Ws[he * 68 + c4]) =
            *reinterpret_cast<const float4*>(Wq + he * 64 + c4);
    }
    __syncthreads();
    {
        int he = tid >> 2;
        int mg = tid & 3;
#pragma unroll
        for (int j = 0; j < 16; j++) {
            int ml = mg + 4 * j;
            float s = 0.f;
#pragma unroll
            for (int d = 0; d < 64; d++) s += Ws[he * 68 + d] * Hs[d * 68 + ml];
            if (mh == 0 && ml == 0) s += bq[he] * 1024.f;
            Qs[he * 66 + ml] = s;
        }
    }
    __syncthreads();
    {
        int lm = tid & 31;
        int hob = tid >> 5;
        int m = mh * 32 + lm;
#pragma unroll
        for (int j = 0; j < 8; j++) {
            int ho = hob * 8 + j;
            int h = ho >> 3, o = ho & 7;
            float ar = 0.f, ai = 0.f;
#pragma unroll
            for (int e = 0; e < 8; e++) {
                float xr = Qs[(h * 8 + e) * 66 + 2 * lm];
                float xi = Qs[(h * 8 + e) * 66 + 2 * lm + 1];
                int wix = ((h * 8 + e) * 8 + o) * MZ + m;
                float wrv = wr[wix], wiv = wi[wix];
                ar += xr * wrv - xi * wiv;
                ai += xr * wiv + xi * wrv;
            }
            size_t ro = ((size_t)(b * 64 + h * 8 + o)) * M2 + 2 * m;
            sel[ro] = ar * scale;
            sel[ro + 1] = ai * scale;
        }
    }
}

// ------------------------------------------------------------------ fused cross attention
__global__ __launch_bounds__(256) void qkattn_kernel(const float* __restrict__ Qf,
                                                     const float* __restrict__ Kf,
                                                     const float* __restrict__ wr,
                                                     const float* __restrict__ wi,
                                                     float* __restrict__ sel,
                                                     float scale) {
    __shared__ float Qs[8][128];
    __shared__ float Ks[8][128];
    __shared__ float qks[64][130];
    __shared__ float Vs[8][128];
    int bh = blockIdx.x;
    int h = bh & 7, b = bh >> 3;
    int tid = threadIdx.x;
    size_t tbase = (size_t)(b * 64 + h * 8) * M2;
#pragma unroll
    for (int i = 0; i < 4; i++) {
        int f = i * 256 + tid;
        int e = f >> 7, c = f & 127;
        Qs[e][c] = Qf[tbase + e * M2 + c];
        Ks[e][c] = Kf[tbase + e * M2 + c];
    }
    __syncthreads();
    {
        int x = tid >> 2;
        int ys = tid & 3;
#pragma unroll
        for (int j = 0; j < 16; j++) {
            int y = ys * 16 + j;
            float ar = 0.f, ai = 0.f;
#pragma unroll
            for (int e = 0; e < 8; e++) {
                float qr = Qs[e][2 * x], qi = Qs[e][2 * x + 1];
                float kr = Ks[e][2 * y], ki = Ks[e][2 * y + 1];
                ar += qr * kr - qi * ki;
                ai += qr * ki + qi * kr;
            }
            float a2 = 2.f * ar, b2 = 2.f * ai;
            float tr, ti;
            if (fabsf(a2) > 30.f) {
                tr = copysignf(1.f, ar);
                ti = 0.f;
            } else {
                float sn, cs;
                sincosf(b2, &sn, &cs);
                float ex = __expf(a2);
                float exi = 1.f / ex;
                float den = 0.5f * (ex + exi) + cs;
                tr = 0.5f * (ex - exi) / den;
                ti = sn / den;
            }
            qks[x][2 * y] = tr;
            qks[x][2 * y + 1] = ti;
        }
    }
    __syncthreads();
    {
        int flat0 = tid * 2;
#pragma unroll
        for (int u = 0; u < 2; u++) {
            int flat = flat0 + u;
            int e = flat >> 6, x = flat & 63;
            float ar = 0.f, ai = 0.f;
#pragma unroll 16
            for (int y = 0; y < 64; y++) {
                float qr = qks[x][2 * y], qi = qks[x][2 * y + 1];
                float kr = Ks[e][2 * y], ki = Ks[e][2 * y + 1];
                ar += qr * kr - qi * ki;
                ai += qr * ki + qi * kr;
            }
            Vs[e][2 * x] = ar;
            Vs[e][2 * x + 1] = ai;
        }
    }
    __syncthreads();
    {
        int m = tid & 63;
        int og = tid >> 6;
#pragma unroll
        for (int j = 0; j < 2; j++) {
            int o = og * 2 + j;
            float ar = 0.f, ai = 0.f;
#pragma unroll
            for (int e = 0; e < 8; e++) {
                float xr = Vs[e][2 * m], xi = Vs[e][2 * m + 1];
                int wix = ((h * 8 + e) * 8 + o) * MZ + m;
                float wrv = wr[wix], wiv = wi[wix];
                ar += xr * wrv - xi * wiv;
                ai += xr * wiv + xi * wrv;
            }
            size_t ro = ((size_t)(b * 64 + h * 8 + o)) * M2 + 2 * m;
            sel[ro] = ar * scale;
            sel[ro + 1] = ai * scale;
        }
    }
}

// ------------------------------------------------------------------ layernorm + fused column-mean accumulation
__global__ void ln_row_kernel(const float* __restrict__ X, const float* __restrict__ g,
                              const float* __restrict__ be, float* __restrict__ out,
                              float* __restrict__ cm) {
    __shared__ float red[256];
    int tid = threadIdx.x;
    int sub = tid >> 6;
    int d = tid & 63;
    int row = blockIdx.x * 4 + sub;
    float v = X[(size_t)row * DZ + d];
    red[tid] = v;
    __syncthreads();
    for (int s = 32; s > 0; s >>= 1) {
        if (d < s) red[tid] += red[tid + s];
        __syncthreads();
    }
    float mu = red[sub * 64] * (1.f / 64.f);
    __syncthreads();
    float dv = v - mu;
    red[tid] = dv * dv;
    __syncthreads();
    for (int s = 32; s > 0; s >>= 1) {
        if (d < s) red[tid] += red[tid + s];
        __syncthreads();
    }
    float var = red[sub * 64] * (1.f / 64.f);
    float vout = dv * rsqrtf(var + 1e-5f) * g[d] + be[d];
    out[(size_t)row * DZ + d] = vout;
    __syncthreads();
    red[tid] = vout;
    __syncthreads();
    if (sub == 0) {
        float s = red[d] + red[64 + d] + red[128 + d] + red[192 + d];
        int b = row >> 10;
        atomicAdd(&cm[b * DZ + d], s * (1.f / LZ));
    }
}

// ------------------------------------------------------------------ final epilogue
__global__ void final_kernel(const float* __restrict__ xln, const float* __restrict__ cm,
                             const float* __restrict__ tacc,
                             const float* __restrict__ tbase, const float* __restrict__ tw,
                             const float* __restrict__ pw, const float* __restrict__ pb,
                             float* __restrict__ out) {
    int idx = blockIdx.x * blockDim.x + threadIdx.x;
    if (idx >= BZ * 512) return;
    int t = idx & 511, b = idx >> 9;
    int tt = t + 512;
    float cv = 0.f;
#pragma unroll
    for (int j = 0; j < 3; j++) {
        int ts = (tt + j - 1) & (LZ - 1);
        const float* row = tacc + ((size_t)(b * LZ + ts)) * DZ;
#pragma unroll 4
        for (int d4 = 0; d4 < 16; d4++) {
            float4 rv = *reinterpret_cast<const float4*>(row + d4 * 4);
            cv += rv.x * tw[(d4 * 4 + 0) * 3 + j] + rv.y * tw[(d4 * 4 + 1) * 3 + j]
                + rv.z * tw[(d4 * 4 + 2) * 3 + j] + rv.w * tw[(d4 * 4 + 3) * 3 + j];
        }
    }
    float p = pb[0];
    const float* xr = xln + ((size_t)(b * LZ + tt)) * DZ;
    const float* cmr = cm + b * DZ;
#pragma unroll 4
    for (int d4 = 0; d4 < 16; d4++) {
        float4 xv = *reinterpret_cast<const float4*>(xr + d4 * 4);
        float4 cvv = *reinterpret_cast<const float4*>(cmr + d4 * 4);
        float4 pv = *reinterpret_cast<const float4*>(pw + d4 * 4);
        p += (xv.x - cvv.x) * pv.x + (xv.y - cvv.y) * pv.y
           + (xv.z - cvv.z) * pv.z + (xv.w - cvv.w) * pv.w;
    }
    out[idx] = p + cv + tbase[b * LZ + tt];
}

static float* symaddr_f(const void* sym) {
    void* p = nullptr;
    cudaGetSymbolAddress(&p, sym);
    return (float*)p;
}

extern "C" void kernel_launch(void* const* d_in, const int* in_sizes, int n_in,
                              void* d_out, int out_size) {
    const float* x_enc       = (const float*)d_in[0];
    const float* dp_w        = (const float*)d_in[1];
    const float* dp_b        = (const float*)d_in[2];
    const float* emb_enc_w   = (const float*)d_in[3];
    const float* emb_dec_w   = (const float*)d_in[4];
    const float* decomp_w    = (const float*)d_in[5];
    const float* decomp_b    = (const float*)d_in[6];
    const float* enc_attn_w  = (const float*)d_in[7];
    const float* enc_attn_b  = (const float*)d_in[8];
    const float* enc_four_wr = (const float*)d_in[9];
    const float* enc_four_wi = (const float*)d_in[10];
    const float* enc_c1      = (const float*)d_in[11];
    const float* enc_c2      = (const float*)d_in[12];
    const float* enc_ln_g    = (const float*)d_in[13];
    const float* enc_ln_b    = (const float*)d_in[14];
    const float* dec_self_w  = (const float*)d_in[15];
    const float* dec_self_b  = (const float*)d_in[16];
    const float* dec_four_wr = (const float*)d_in[17];
    const float* dec_four_wi = (const float*)d_in[18];
    const float* dec_cross_w = (const float*)d_in[19];
    const float* dec_cross_b = (const float*)d_in[20];
    const float* dec_cross_wr= (const float*)d_in[21];
    const float* dec_cross_wi= (const float*)d_in[22];
    const float* dec_c1      = (const float*)d_in[23];
    const float* dec_c2      = (const float*)d_in[24];
    const float* dec_trend_w = (const float*)d_in[25];
    const float* dec_ln_g    = (const float*)d_in[26];
    const float* dec_ln_b    = (const float*)d_in[27];
    const float* dec_proj_w  = (const float*)d_in[28];
    const float* dec_proj_b  = (const float*)d_in[29];
    float* out = (float*)d_out;

    float* px        = symaddr_f(g_x);
    float* pseas0    = symaddr_f(g_seas0);
    float* ptrend0   = symaddr_f(g_trend0);
    float* pseasinit = symaddr_f(g_seasinit);
    float* ph        = symaddr_f(g_h);
    float* py        = symaddr_f(g_y);
    float* pa        = symaddr_f(g_a);
    float* py2       = symaddr_f(g_y2);
    float* pa2       = symaddr_f(g_a2);
    float* pHf       = symaddr_f(g_Hf);
    float* pHf2      = pHf + (size_t)NHE * M2;
    float* pHq       = symaddr_f(g_Hq);
    float* pXf       = symaddr_f(g_Xf);
    float* pXk       = symaddr_f(g_Xk);
    float* psel      = symaddr_f(g_sel);
    float* psel2     = symaddr_f(g_sel2);
    float* pxd       = symaddr_f(g_xd);
    float* ptacc     = symaddr_f(g_tacc);
    float* pcm       = symaddr_f(g_cm);
    float* pcm2      = symaddr_f(g_cm2);
    float* pln       = symaddr_f(g_ln);
    float* pF        = symaddr_f(g_F);
    float* pFi       = symaddr_f(g_Fi);
    float* ptbase    = symaddr_f(g_trendbase);

    cudaFuncSetAttribute(gemm_tc<0>, cudaFuncAttributeMaxDynamicSharedMemorySize, GT_SMEM);
    cudaFuncSetAttribute(gemm_ffn, cudaFuncAttributeMaxDynamicSharedMemorySize, FFN_SMEM);
    cudaFuncSetAttribute(modeproj_mix_kernel, cudaFuncAttributeMaxDynamicSharedMemorySize, MPM_SMEM);

    static cudaStream_t s2 = nullptr;
    static cudaEvent_t evFork = nullptr, evJoin = nullptr;
    if (!s2) {
        cudaStreamCreateWithFlags(&s2, cudaStreamNonBlocking);
        cudaEventCreateWithFlags(&evFork, cudaEventDisableTiming);
        cudaEventCreateWithFlags(&evJoin, cudaEventDisableTiming);
    }

    dim3 dftg(BZ, 2, 4);
    dim3 mpg(BZ, 2);

    // ---- shared prep (stream 0) ----
    cudaMemsetAsync(pcm, 0, BZ * DZ * sizeof(float));
    cudaMemsetAsync(pcm2, 0, BZ * DZ * sizeof(float));
    build_tables_kernel<<<512, 256>>>();
    transpose_in_kernel<<<1792, 256>>>(x_enc);
    colmean7_kernel<<<BZ * C7, 256>>>(x_enc);
    decomp7_kernel<<<BZ * C7, LZ>>>(px, decomp_w + 0, decomp_b + 0, pseas0, ptrend0);
    initdec_kernel<<<1792, 256>>>(dp_w, dp_b);
    cudaEventRecord(evFork, 0);

    // ---- decoder prefix + cross-Q path (stream s2) ----
    cudaStreamWaitEvent(s2, evFork, 0);
    embed_kernel<<<16384, 256, 0, s2>>>(pseasinit, emb_dec_w, pxd);
    cudaMemsetAsync(pHf2, 0, (size_t)NHE * M2 * sizeof(float), s2);
    gemm_dft<<<dftg, 128, 0, s2>>>(pxd, pF, pHf2);
    modeproj_mix_kernel<<<mpg, 256, MPM_SMEM, s2>>>(pHf2, dec_self_w + 0, dec_self_b + 0,
                                                    dec_four_wr, dec_four_wi, psel2, 1.0f);
    gemm_tc<0><<<dim3(32, 16), 128, GT_SMEM, s2>>>(psel2, pFi, nullptr, py2, NHE, 128, 1024);
    gemm_tc<0><<<dim3(512, 1), 128, GT_SMEM, s2>>>(py2, dec_self_w + 3 * 4096,
                                                   dec_self_b + 3 * 64, pa2, NROW, 64, 64);
    decomp64_kernel<<<1024, 256, 0, s2>>>(pxd, pa2, decomp_w + 5 * 4, decomp_b + 5 * 4,
                                          pxd, ptacc, 0);
    cudaMemsetAsync(pHq, 0, (size_t)NHE * M2 * sizeof(float), s2);
    gemm_dft<<<dftg, 128, 0, s2>>>(pxd, pF, pHq);
    modeproj_kernel<<<mpg, 256, 0, s2>>>(pHq, dec_cross_w + 0, dec_cross_b + 0, nullptr, pXf);
    cudaEventRecord(evJoin, s2);

    // ---- encoder (stream 0) ----
    embed_kernel<<<16384, 256>>>(px, emb_enc_w, ph);
    for (int l = 0; l < 2; l++) {
        const float* wq = enc_attn_w + (size_t)(l * 4 + 0) * 4096;
        const float* bq = enc_attn_b + (size_t)(l * 4 + 0) * 64;
        const float* wo = enc_attn_w + (size_t)(l * 4 + 3) * 4096;
        const float* bo = enc_attn_b + (size_t)(l * 4 + 3) * 64;
        cudaMemsetAsync(pHf, 0, (size_t)NHE * M2 * sizeof(float));
        gemm_dft<<<dftg, 128>>>(ph, pF, pHf);
        modeproj_mix_kernel<<<mpg, 256, MPM_SMEM>>>(pHf, wq, bq,
                                                    enc_four_wr + (size_t)l * 32768,
                                                    enc_four_wi + (size_t)l * 32768, psel, 1.0f);
        gemm_tc<0><<<dim3(32, 16), 128, GT_SMEM>>>(psel, pFi, nullptr, py, NHE, 128, 1024);
        gemm_tc<0><<<dim3(512, 1), 128, GT_SMEM>>>(py, wo, bo, pa, NROW, 64, 64);
        decomp64_kernel<<<1024, 256>>>(ph, pa, decomp_w + (1 + 2 * l) * 4,
                                       decomp_b + (1 + 2 * l) * 4, ph, nullptr, 0);
        gemm_ffn<<<512, 128, FFN_SMEM>>>(ph, enc_c1 + (size_t)l * 16384,
                                         enc_c2 + (size_t)l * 16384, py);
        decomp64_kernel<<<1024, 256>>>(ph, py, decomp_w + (2 + 2 * l) * 4,
                                       decomp_b + (2 + 2 * l) * 4, ph, nullptr, 0);
    }
    ln_row_kernel<<<16384, 256>>>(ph, enc_ln_g, enc_ln_b, ph, pcm2);

    // ---- cross-attention K path (stream 0, encoder-only deps) ----
    cudaMemsetAsync(pHf, 0, (size_t)NHE * M2 * sizeof(float));
    gemm_dft<<<dftg, 128>>>(ph, pF, pHf);
    modeproj_kernel<<<mpg, 256>>>(pHf, dec_cross_w + 1 * 4096, dec_cross_b + 1 * 64, pcm2, pXk);

    // ---- join, then cross attention core ----
    cudaStreamWaitEvent(0, evJoin, 0);
    qkattn_kernel<<<512, 256>>>(pXf, pXk, dec_cross_wr, dec_cross_wi, psel, 1.0f / 4096.0f);
    gemm_tc<0><<<dim3(32, 16), 128, GT_SMEM>>>(psel, pFi, nullptr, py, NHE, 128, 1024);
    gemm_tc<0><<<dim3(512, 1), 128, GT_SMEM>>>(py, dec_cross_w + 3 * 4096, dec_cross_b + 3 * 64, pa,
                                               NROW, 64, 64);
    decomp64_kernel<<<1024, 256>>>(pxd, pa, decomp_w + 6 * 4, decomp_b + 6 * 4, pxd, ptacc, 1);

    gemm_ffn<<<512, 128, FFN_SMEM>>>(pxd, dec_c1, dec_c2, py);
    decomp64_kernel<<<1024, 256>>>(pxd, py, decomp_w + 7 * 4, decomp_b + 7 * 4, pxd, ptacc, 1);

    ln_row_kernel<<<16384, 256>>>(pxd, dec_ln_g, dec_ln_b, pln, pcm);
    final_kernel<<<128, 256>>>(pln, pcm, ptacc, ptbase, dec_trend_w, dec_proj_w, dec_proj_b, out);
}